// round 12
// baseline (speedup 1.0000x reference)
#include <cuda_runtime.h>
#include <cuda_fp16.h>
#include <cstdint>
#include <math.h>

// Problem constants
#define BB 4
#define NN 2048
#define CC 512
#define HH 8
#define DH 64
#define GROUPS 8

// ===========================================================================
// Scratch (__device__ globals; alloc-free rule)
// ===========================================================================
__device__ float g_P1[BB * NN * CC];
__device__ float g_P2[BB * NN * CC];
__device__ float g_PE[(size_t)BB * NN * NN];   // holds 0.125 * sigmoid(...)
__device__ float g_gnstat1[BB * GROUPS * 2];   // (sum, sumsq) per (b,g)
__device__ float g_gnstat2[BB * GROUPS * 2];

// fp16 split operands, tiled SW128 layout (tile = 128 rows x 64 f16 = 16KB)
#define TILE_BYTES 16384
__device__ char g_xs_hi[8192 * 1024];
__device__ char g_pes_hi[8192 * 1024], g_pes_lo[8192 * 1024];
__device__ char g_p1s_hi[8192 * 1024];
__device__ char g_p2s_hi[8192 * 1024], g_p2s_lo[8192 * 1024];
__device__ char g_os_hi[8192 * 1024];
__device__ char g_wqkv_hi[1536 * 1024];
__device__ char g_wc1_hi[512 * 1024],  g_wc1_lo[512 * 1024];
__device__ char g_wc2_hi[512 * 1024],  g_wc2_lo[512 * 1024];
__device__ char g_wpj_hi[512 * 1024];
// QKV in split-tile form: 64 row-tiles x 24 col-tiles x 16KB
__device__ char g_qkvs_hi[64 * 24 * TILE_BYTES];
__device__ char g_qkvs_lo[64 * 24 * TILE_BYTES];   // only V-lo tiles used

// ===========================================================================
// Helpers
// ===========================================================================
__device__ __forceinline__ uint32_t smem_to_u32(const void* p) {
    uint32_t a;
    asm("{ .reg .u64 t; cvta.to.shared.u64 t, %1; cvt.u32.u64 %0, t; }"
        : "=r"(a) : "l"(p));
    return a;
}

__device__ __forceinline__ void cpa16(uint32_t s, const void* g) {
    asm volatile("cp.async.cg.shared.global [%0], [%1], 16;" :: "r"(s), "l"(g));
}

__device__ __forceinline__ void ldm_x4(uint32_t* r, uint32_t addr) {
    asm volatile("ldmatrix.sync.aligned.m8n8.x4.shared.b16 {%0,%1,%2,%3}, [%4];"
        : "=r"(r[0]), "=r"(r[1]), "=r"(r[2]), "=r"(r[3]) : "r"(addr));
}

__device__ __forceinline__ void ldm_x4_t(uint32_t* r, uint32_t addr) {
    asm volatile("ldmatrix.sync.aligned.m8n8.x4.trans.shared.b16 {%0,%1,%2,%3}, [%4];"
        : "=r"(r[0]), "=r"(r[1]), "=r"(r[2]), "=r"(r[3]) : "r"(addr));
}

__device__ __forceinline__ void mma_f16(float* d, const uint32_t* a,
                                        const uint32_t* b) {
    asm volatile(
        "mma.sync.aligned.m16n8k16.row.col.f32.f16.f16.f32 "
        "{%0,%1,%2,%3}, {%4,%5,%6,%7}, {%8,%9}, {%0,%1,%2,%3};"
        : "+f"(d[0]), "+f"(d[1]), "+f"(d[2]), "+f"(d[3])
        : "r"(a[0]), "r"(a[1]), "r"(a[2]), "r"(a[3]), "r"(b[0]), "r"(b[1]));
}

// pack (lo, hi) floats -> f16x2 reg (lo in low 16 bits)
__device__ __forceinline__ uint32_t packh(float lo, float hi) {
    uint32_t d;
    asm("cvt.rn.f16x2.f32 %0, %1, %2;" : "=r"(d) : "f"(hi), "f"(lo));
    return d;
}

// ===========================================================================
// Split fp32 -> (f16 hi, f16 lo) into tiled SW128-swizzled layout.
// ===========================================================================
template <bool WLO>
__global__ void __launch_bounds__(256) split_f16_kernel(
    const float* __restrict__ X, char* __restrict__ Hi, char* __restrict__ Lo,
    int K, int total8)
{
    int idx = blockIdx.x * 256 + threadIdx.x;
    if (idx >= total8) return;
    int perRow = K >> 3;
    int r = idx / perRow;
    int c = (idx % perRow) << 3;

    float4 v0 = *(const float4*)(X + (size_t)r * K + c);
    float4 v1 = *(const float4*)(X + (size_t)r * K + c + 4);
    float vin[8] = {v0.x, v0.y, v0.z, v0.w, v1.x, v1.y, v1.z, v1.w};

    uint32_t hw[4], lw[4];
#pragma unroll
    for (int i = 0; i < 4; i++) {
        __half h0 = __float2half(vin[2 * i]);
        __half h1 = __float2half(vin[2 * i + 1]);
        __half2 hp = {h0, h1};
        hw[i] = *reinterpret_cast<uint32_t*>(&hp);
        if (WLO) {
            float l0 = vin[2 * i] - __half2float(h0);
            float l1 = vin[2 * i + 1] - __half2float(h1);
            lw[i] = packh(l0, l1);
        }
    }

    int rt = r >> 7, rr = r & 127;
    int kt = c >> 6, cc = c & 63;
    int tile = rt * (K >> 6) + kt;
    uint32_t inTile = rr * 128 + cc * 2;
    uint32_t sw = inTile ^ ((inTile >> 3) & 0x70);
    size_t off = (size_t)tile * TILE_BYTES + sw;
    *(uint4*)(Hi + off) = make_uint4(hw[0], hw[1], hw[2], hw[3]);
    if (WLO) *(uint4*)(Lo + off) = make_uint4(lw[0], lw[1], lw[2], lw[3]);
}

// ===========================================================================
// Zero GN stat accumulators
// ===========================================================================
__global__ void gn_zero_kernel()
{
    if (threadIdx.x < BB * GROUPS * 2) {
        g_gnstat1[threadIdx.x] = 0.f;
        g_gnstat2[threadIdx.x] = 0.f;
    }
}

// ===========================================================================
// fp16 split GEMM-NT via mma.sync.
// TERMS=1: ah*bh. TERMS=2: + ah*bl. TERMS=3: + al*bh.
// CTA tile 128x128, 8 warps (2m x 4n), K chunk 64, double-buffered cp.async.
// GNSTAT: epilogue accumulates (sum, sumsq) per (b, group) via atomics.
// ===========================================================================
template <int TERMS, bool SIG, bool BIAS, bool SPLIT, bool GNSTAT>
__global__ void __launch_bounds__(256) gemm_mma(
    const char* __restrict__ Ahi, const char* __restrict__ Alo,
    const char* __restrict__ Bhi, const char* __restrict__ Blo,
    const float* __restrict__ bias, float* __restrict__ C,
    char* __restrict__ Chi, char* __restrict__ Clo,
    float* __restrict__ stats,
    int numKt, int aBatchTiles, int bBatchTiles, long long cBatchStride, int ldc)
{
    constexpr int NTILES = TERMS + 1;      // 1->2, 2->3, 3->4
    constexpr uint32_t STB = NTILES * TILE_BYTES;

    extern __shared__ __align__(128) char smem[];
    uint32_t smem_base = smem_to_u32(smem);
    const int tid = threadIdx.x;
    const int wid = tid >> 5;
    const int lane = tid & 31;
    const int wm = wid & 1;
    const int wn = wid >> 1;

    const long long aTileBase = (long long)blockIdx.z * aBatchTiles + (long long)blockIdx.y * numKt;
    const long long bTileBase = (long long)blockIdx.z * bBatchTiles + (long long)blockIdx.x * numKt;

    auto issue_loads = [&](int kt, int stage) {
        const char* srcs[4];
        srcs[0] = Ahi + (aTileBase + kt) * TILE_BYTES;
        srcs[1] = Bhi + (bTileBase + kt) * TILE_BYTES;
        if (TERMS >= 2) srcs[2] = Blo + (bTileBase + kt) * TILE_BYTES;
        if (TERMS == 3) srcs[3] = Alo + (aTileBase + kt) * TILE_BYTES;
        uint32_t sb = smem_base + stage * STB;
#pragma unroll
        for (int t = 0; t < NTILES; t++)
#pragma unroll
            for (int i = 0; i < 4; i++) {
                uint32_t o = t * TILE_BYTES + i * 4096 + tid * 16;
                cpa16(sb + o, srcs[t] + i * 4096 + tid * 16);
            }
        asm volatile("cp.async.commit_group;" ::: "memory");
    };

    const int aRowBase = wm * 64 + (lane & 15);
    const uint32_t aKadd = (lane >> 4) * 16;
    const int bRowBase = wn * 32 + ((lane >> 4) << 3) + (lane & 7);
    const uint32_t bKadd = ((lane >> 3) & 1) * 16;

    float acc[4][4][4];
#pragma unroll
    for (int mt = 0; mt < 4; mt++)
#pragma unroll
        for (int nt = 0; nt < 4; nt++)
#pragma unroll
            for (int f = 0; f < 4; f++) acc[mt][nt][f] = 0.f;

    issue_loads(0, 0);

    for (int c = 0; c < numKt; c++) {
        const int buf = c & 1;
        if (c + 1 < numKt) {
            issue_loads(c + 1, buf ^ 1);
            asm volatile("cp.async.wait_group 1;" ::: "memory");
        } else {
            asm volatile("cp.async.wait_group 0;" ::: "memory");
        }
        __syncthreads();

        const uint32_t sb = smem_base + buf * STB;
        const uint32_t aHiB = sb;
        const uint32_t bHiB = sb + TILE_BYTES;
        const uint32_t bLoB = sb + 2 * TILE_BYTES;  // valid if TERMS>=2
        const uint32_t aLoB = sb + 3 * TILE_BYTES;  // valid if TERMS==3

#pragma unroll
        for (int ks = 0; ks < 4; ks++) {
            uint32_t ah[4][4], al[4][4];
#pragma unroll
            for (int mt = 0; mt < 4; mt++) {
                int row = aRowBase + mt * 16;
                uint32_t koff = (ks * 32 + aKadd) ^ ((row & 7) << 4);
                uint32_t off = (uint32_t)row * 128 + koff;
                ldm_x4(ah[mt], aHiB + off);
                if (TERMS == 3) ldm_x4(al[mt], aLoB + off);
            }
            uint32_t bh[2][4], bl[2][4];
#pragma unroll
            for (int np = 0; np < 2; np++) {
                int row = bRowBase + np * 16;
                uint32_t koff = (ks * 32 + bKadd) ^ ((row & 7) << 4);
                uint32_t off = (uint32_t)row * 128 + koff;
                ldm_x4(bh[np], bHiB + off);
                if (TERMS >= 2) ldm_x4(bl[np], bLoB + off);
            }
#pragma unroll
            for (int mt = 0; mt < 4; mt++)
#pragma unroll
                for (int nt = 0; nt < 4; nt++) {
                    const uint32_t* bhp = &bh[nt >> 1][(nt & 1) * 2];
                    mma_f16(acc[mt][nt], ah[mt], bhp);
                    if (TERMS >= 2) {
                        const uint32_t* blp = &bl[nt >> 1][(nt & 1) * 2];
                        mma_f16(acc[mt][nt], ah[mt], blp);
                    }
                    if (TERMS == 3) mma_f16(acc[mt][nt], al[mt], bhp);
                }
        }
        __syncthreads();
    }

    // Epilogue
    const int g = lane >> 2, tg = lane & 3;
    float ls = 0.f, lsq = 0.f;
    if (SPLIT) {
        const int tilesPerRow = ldc >> 6;
#pragma unroll
        for (int mt = 0; mt < 4; mt++) {
            const int row0 = blockIdx.y * 128 + wm * 64 + mt * 16 + g;
#pragma unroll
            for (int nt = 0; nt < 4; nt++) {
                const int col = blockIdx.x * 128 + wn * 32 + nt * 8 + tg * 2;
                const int tile = (row0 >> 7) * tilesPerRow + (col >> 6);
#pragma unroll
                for (int half = 0; half < 2; half++) {
                    const int rowIn = (row0 & 127) + half * 8;
                    float v0 = acc[mt][nt][half * 2 + 0];
                    float v1 = acc[mt][nt][half * 2 + 1];
                    __half h0 = __float2half(v0);
                    __half h1 = __float2half(v1);
                    float l0 = v0 - __half2float(h0);
                    float l1 = v1 - __half2float(h1);
                    __half2 hp = {h0, h1};
                    uint32_t inoff = rowIn * 128 + (col & 63) * 2;
                    uint32_t sw = inoff ^ ((inoff >> 3) & 0x70);
                    *(uint32_t*)(Chi + (size_t)tile * TILE_BYTES + sw) =
                        *reinterpret_cast<uint32_t*>(&hp);
                    *(uint32_t*)(Clo + (size_t)tile * TILE_BYTES + sw) = packh(l0, l1);
                }
            }
        }
    } else {
        float* Cbase = C + (long long)blockIdx.z * cBatchStride;
#pragma unroll
        for (int mt = 0; mt < 4; mt++) {
            const int row0 = blockIdx.y * 128 + wm * 64 + mt * 16 + g;
#pragma unroll
            for (int nt = 0; nt < 4; nt++) {
                const int col = blockIdx.x * 128 + wn * 32 + nt * 8 + tg * 2;
                float b0 = 0.f, b1 = 0.f;
                if (BIAS) { b0 = bias[col]; b1 = bias[col + 1]; }
#pragma unroll
                for (int half = 0; half < 2; half++) {
                    float v0 = acc[mt][nt][half * 2 + 0] + b0;
                    float v1 = acc[mt][nt][half * 2 + 1] + b1;
                    if (SIG) {
                        // fold attention scale (1/8) into the stored gate
                        v0 = 0.125f / (1.f + __expf(-v0));
                        v1 = 0.125f / (1.f + __expf(-v1));
                    }
                    if (GNSTAT) {
                        ls += v0 + v1;
                        lsq += v0 * v0 + v1 * v1;
                    }
                    *(float2*)(Cbase + (long long)(row0 + half * 8) * ldc + col) =
                        make_float2(v0, v1);
                }
            }
        }
        if (GNSTAT) {
#pragma unroll
            for (int off = 16; off > 0; off >>= 1) {
                ls  += __shfl_xor_sync(0xffffffffu, ls, off);
                lsq += __shfl_xor_sync(0xffffffffu, lsq, off);
            }
            if (lane == 0) {
                const int b = blockIdx.y >> 4;
                const int grp = blockIdx.x * 2 + (wn >> 1);
                atomicAdd(&stats[(b * GROUPS + grp) * 2 + 0], ls);
                atomicAdd(&stats[(b * GROUPS + grp) * 2 + 1], lsq);
            }
        }
    }
}

// ===========================================================================
// GN apply: normalize P (fp32) using precomputed stats and write f16 hi(/lo)
// SW128 split tiles (p1: hi only — A operand; p2: hi+lo).
// ===========================================================================
__global__ void __launch_bounds__(256) gn_apply_kernel(
    const float* __restrict__ g1, const float* __restrict__ b1,
    const float* __restrict__ g2, const float* __restrict__ b2,
    char* __restrict__ p1Hi,
    char* __restrict__ p2Hi, char* __restrict__ p2Lo)
{
    const int which = blockIdx.y;
    const float* P = which == 0 ? g_P1 : g_P2;
    const float* st = which == 0 ? g_gnstat1 : g_gnstat2;
    const float* gamma = which == 0 ? g1 : g2;
    const float* beta  = which == 0 ? b1 : b2;
    char* Hi = which == 0 ? p1Hi : p2Hi;
    char* Lo = p2Lo;
    const bool wlo = (which == 1);

    const int idx = blockIdx.x * 256 + threadIdx.x;
    const int r = idx >> 6;
    const int c = (idx & 63) << 3;
    const int b = r >> 11;
    const int grp = c >> 6;
    const float CNT = (float)((CC / GROUPS) * NN);

    const float s = st[(b * GROUPS + grp) * 2 + 0];
    const float sq = st[(b * GROUPS + grp) * 2 + 1];
    const float mean = s / CNT;
    const float var = sq / CNT - mean * mean;
    const float rstd = rsqrtf(var + 1e-5f);

    float4 v0 = *(const float4*)(P + (size_t)r * CC + c);
    float4 v1 = *(const float4*)(P + (size_t)r * CC + c + 4);
    float vin[8] = {v0.x, v0.y, v0.z, v0.w, v1.x, v1.y, v1.z, v1.w};
    float4 gm0 = *(const float4*)(gamma + c);
    float4 gm1 = *(const float4*)(gamma + c + 4);
    float4 bt0 = *(const float4*)(beta + c);
    float4 bt1 = *(const float4*)(beta + c + 4);
    float gm[8] = {gm0.x, gm0.y, gm0.z, gm0.w, gm1.x, gm1.y, gm1.z, gm1.w};
    float bt[8] = {bt0.x, bt0.y, bt0.z, bt0.w, bt1.x, bt1.y, bt1.z, bt1.w};

    uint32_t hw[4], lw[4];
#pragma unroll
    for (int i = 0; i < 4; i++) {
        float a0 = (vin[2 * i] - mean) * rstd * gm[2 * i] + bt[2 * i];
        float a1 = (vin[2 * i + 1] - mean) * rstd * gm[2 * i + 1] + bt[2 * i + 1];
        __half h0 = __float2half(a0);
        __half h1 = __float2half(a1);
        __half2 hp = {h0, h1};
        hw[i] = *reinterpret_cast<uint32_t*>(&hp);
        lw[i] = packh(a0 - __half2float(h0), a1 - __half2float(h1));
    }

    const int tile = (r >> 7) * 8 + grp;
    uint32_t inTile = (uint32_t)(r & 127) * 128 + (c & 63) * 2;
    uint32_t sw = inTile ^ ((inTile >> 3) & 0x70);
    size_t off = (size_t)tile * TILE_BYTES + sw;
    *(uint4*)(Hi + off) = make_uint4(hw[0], hw[1], hw[2], hw[3]);
    if (wlo) *(uint4*)(Lo + off) = make_uint4(lw[0], lw[1], lw[2], lw[3]);
}

// ===========================================================================
// Tensor-core flash attention with PE gate.
// S = Qh*Kh (1-term), O += Ph*(Vh+Vl) (2-term). Grid (N/128, H, B); 8 warps.
// KV stage: Kh 8KB + Vh 8KB + Vl 8KB = 24KB.
// ===========================================================================
#define ATT_STAGE 24576
#define ATT_SMEM (16384 + 2 * ATT_STAGE)   // Q hi + 2 KV stages = 64KB

__global__ void __launch_bounds__(256) attn_mma()
{
    extern __shared__ __align__(128) char smem[];
    const uint32_t sb = smem_to_u32(smem);
    const uint32_t qh_base = sb;
    const uint32_t stage0 = sb + 16384;

    const int tid = threadIdx.x, wid = tid >> 5, lane = tid & 31;
    const int q0 = blockIdx.x * 128, h = blockIdx.y, b = blockIdx.z;
    const int g = lane >> 2, tg = lane & 3;

    const int rtQ = (b * NN + q0) >> 7;
    {
        const char* qsh = g_qkvs_hi + (size_t)(rtQ * 24 + h) * TILE_BYTES;
#pragma unroll
        for (int i = 0; i < 4; i++)
            cpa16(qh_base + i * 4096 + tid * 16, qsh + i * 4096 + tid * 16);
        asm volatile("cp.async.commit_group;" ::: "memory");
    }

    auto issue_kv = [&](int t, int stg) {
        const int kRow = t * 64;
        const int rt = (b * NN + kRow) >> 7;
        const int halfOff = (kRow & 64) ? 8192 : 0;
        const char* kh = g_qkvs_hi + (size_t)(rt * 24 + 8 + h) * TILE_BYTES + halfOff;
        const char* vh = g_qkvs_hi + (size_t)(rt * 24 + 16 + h) * TILE_BYTES + halfOff;
        const char* vl = g_qkvs_lo + (size_t)(rt * 24 + 16 + h) * TILE_BYTES + halfOff;
        uint32_t s = stage0 + stg * ATT_STAGE;
#pragma unroll
        for (int i = 0; i < 2; i++) {
            uint32_t o = i * 4096 + tid * 16;
            cpa16(s + o,         kh + o);
            cpa16(s + 8192 + o,  vh + o);
            cpa16(s + 16384 + o, vl + o);
        }
        asm volatile("cp.async.commit_group;" ::: "memory");
    };

    issue_kv(0, 0);
    asm volatile("cp.async.wait_group 1;" ::: "memory");  // Q arrived
    __syncthreads();

    // Q fragments (hi only, resident)
    uint32_t qfh[4][4];
    {
        const int row = wid * 16 + (lane & 15);
        const uint32_t roff = (uint32_t)row * 128;
#pragma unroll
        for (int ks = 0; ks < 4; ks++) {
            uint32_t colb = (lane >> 4) * 16 + ks * 32;
            uint32_t a = roff + (colb ^ ((row & 7) << 4));
            ldm_x4(qfh[ks], qh_base + a);
        }
    }

    float Oa[8][4];
#pragma unroll
    for (int nt = 0; nt < 8; nt++)
#pragma unroll
        for (int f = 0; f < 4; f++) Oa[nt][f] = 0.f;
    float mrow[2] = {-1e30f, -1e30f}, lrow[2] = {0.f, 0.f};

    const size_t peBase = (size_t)b * NN * NN;
    const int qRow0 = q0 + wid * 16 + g;
    const int bRow0 = ((lane >> 4) << 3) + (lane & 7);
    const uint32_t bKadd = ((lane >> 3) & 1) * 16;

    for (int t = 0; t < NN / 64; t++) {
        const int buf = t & 1;
        if (t + 1 < NN / 64) {
            issue_kv(t + 1, buf ^ 1);
            asm volatile("cp.async.wait_group 1;" ::: "memory");
        } else {
            asm volatile("cp.async.wait_group 0;" ::: "memory");
        }
        __syncthreads();

        const uint32_t kb = stage0 + buf * ATT_STAGE;
        const uint32_t kh_b = kb;
        const uint32_t vh_b = kb + 8192, vl_b = kb + 16384;

        // S = Q K^T (fp16 1-term)
        float S[8][4];
#pragma unroll
        for (int nt = 0; nt < 8; nt++)
#pragma unroll
            for (int f = 0; f < 4; f++) S[nt][f] = 0.f;

#pragma unroll
        for (int ks = 0; ks < 4; ks++) {
#pragma unroll
            for (int np = 0; np < 4; np++) {
                const int row = bRow0 + np * 16;
                const uint32_t a = (uint32_t)row * 128 +
                                   ((ks * 32 + bKadd) ^ ((row & 7) << 4));
                uint32_t KH[4];
                ldm_x4(KH, kh_b + a);
#pragma unroll
                for (int hn = 0; hn < 2; hn++)
                    mma_f16(S[np * 2 + hn], qfh[ks], &KH[hn * 2]);
            }
        }

        // gate with PE (0.125 pre-folded into gate)
        const int k0 = t * 64;
#pragma unroll
        for (int nt = 0; nt < 8; nt++) {
#pragma unroll
            for (int r = 0; r < 2; r++) {
                const float2 pe = *(const float2*)&g_PE[
                    peBase + (size_t)(qRow0 + r * 8) * NN + k0 + nt * 8 + tg * 2];
                S[nt][r * 2 + 0] *= pe.x;
                S[nt][r * 2 + 1] *= pe.y;
            }
        }

        // online softmax
        float corr[2];
#pragma unroll
        for (int r = 0; r < 2; r++) {
            float vm = -1e30f;
#pragma unroll
            for (int nt = 0; nt < 8; nt++)
                vm = fmaxf(vm, fmaxf(S[nt][r * 2], S[nt][r * 2 + 1]));
            vm = fmaxf(vm, __shfl_xor_sync(0xffffffffu, vm, 1));
            vm = fmaxf(vm, __shfl_xor_sync(0xffffffffu, vm, 2));
            const float mn = fmaxf(mrow[r], vm);
            corr[r] = __expf(mrow[r] - mn);
            mrow[r] = mn;
            float rsum = 0.f;
#pragma unroll
            for (int nt = 0; nt < 8; nt++) {
                float p0 = __expf(S[nt][r * 2] - mn);
                float p1 = __expf(S[nt][r * 2 + 1] - mn);
                S[nt][r * 2] = p0;
                S[nt][r * 2 + 1] = p1;
                rsum += p0 + p1;
            }
            rsum += __shfl_xor_sync(0xffffffffu, rsum, 1);
            rsum += __shfl_xor_sync(0xffffffffu, rsum, 2);
            lrow[r] = lrow[r] * corr[r] + rsum;
        }
#pragma unroll
        for (int nt = 0; nt < 8; nt++) {
            Oa[nt][0] *= corr[0]; Oa[nt][1] *= corr[0];
            Oa[nt][2] *= corr[1]; Oa[nt][3] *= corr[1];
        }

        // O += P V (fp16 2-term); P hi fragments from S accumulators
#pragma unroll
        for (int ks = 0; ks < 4; ks++) {
            uint32_t ah[4];
#pragma unroll
            for (int q = 0; q < 2; q++) {
                const float* sv = S[2 * ks + q];
                ah[q * 2 + 0] = packh(sv[0], sv[1]);
                ah[q * 2 + 1] = packh(sv[2], sv[3]);
            }
#pragma unroll
            for (int dp = 0; dp < 4; dp++) {
                const int row = ks * 16 + (lane & 15);
                const uint32_t a = (uint32_t)row * 128 +
                    ((dp * 32 + (lane >> 4) * 16) ^ ((row & 7) << 4));
                uint32_t VH[4], VL[4];
                ldm_x4_t(VH, vh_b + a);
                ldm_x4_t(VL, vl_b + a);
#pragma unroll
                for (int hn = 0; hn < 2; hn++) {
                    const int nt = dp * 2 + hn;
                    mma_f16(Oa[nt], ah, &VH[hn * 2]);
                    mma_f16(Oa[nt], ah, &VL[hn * 2]);
                }
            }
        }
        __syncthreads();
    }

    // Epilogue: normalize and write hi tiles for proj GEMM (O is A operand)
    const float inv[2] = {1.f / lrow[0], 1.f / lrow[1]};
    char* osh = g_os_hi + (size_t)(rtQ * 8 + h) * TILE_BYTES;
#pragma unroll
    for (int nt = 0; nt < 8; nt++) {
#pragma unroll
        for (int r = 0; r < 2; r++) {
            const float v0 = Oa[nt][r * 2 + 0] * inv[r];
            const float v1 = Oa[nt][r * 2 + 1] * inv[r];
            const int rowIn = wid * 16 + g + r * 8;
            const uint32_t inoff = (uint32_t)rowIn * 128 + nt * 16 + tg * 4;
            const uint32_t sw = inoff ^ ((inoff >> 3) & 0x70);
            *(uint32_t*)(osh + sw) = packh(v0, v1);
        }
    }
}

// ===========================================================================

static void split(const void* X, void* Hi, void* Lo, int K, int rows, bool wlo)
{
    int total8 = rows * K / 8;
    if (wlo)
        split_f16_kernel<true><<<(total8 + 255) / 256, 256>>>(
            (const float*)X, (char*)Hi, (char*)Lo, K, total8);
    else
        split_f16_kernel<false><<<(total8 + 255) / 256, 256>>>(
            (const float*)X, (char*)Hi, nullptr, K, total8);
}

#define GEMM_SMEM1 (2 * 2 * TILE_BYTES)   // 64KB
#define GEMM_SMEM2 (2 * 3 * TILE_BYTES)   // 96KB
#define GEMM_SMEM3 (2 * 4 * TILE_BYTES)   // 128KB

extern "C" void kernel_launch(void* const* d_in, const int* in_sizes, int n_in,
                              void* d_out, int out_size)
{
    const float* x       = (const float*)d_in[0];
    const float* pe      = (const float*)d_in[1];
    const float* qkv_w   = (const float*)d_in[2];
    const float* proj_w  = (const float*)d_in[3];
    const float* proj_b  = (const float*)d_in[4];
    const float* conv1_w = (const float*)d_in[5];
    const float* conv1_b = (const float*)d_in[6];
    const float* gn1_g   = (const float*)d_in[7];
    const float* gn1_b   = (const float*)d_in[8];
    const float* conv2_w = (const float*)d_in[9];
    const float* conv2_b = (const float*)d_in[10];
    const float* gn2_g   = (const float*)d_in[11];
    const float* gn2_b   = (const float*)d_in[12];
    float* out = (float*)d_out;

    float *p1, *p2, *pem, *st1, *st2;
    cudaGetSymbolAddress((void**)&p1, g_P1);
    cudaGetSymbolAddress((void**)&p2, g_P2);
    cudaGetSymbolAddress((void**)&pem, g_PE);
    cudaGetSymbolAddress((void**)&st1, g_gnstat1);
    cudaGetSymbolAddress((void**)&st2, g_gnstat2);

    char *xsh, *pesh, *pesl, *p1h, *p2h, *p2l, *osh;
    char *wqh, *w1h, *w1l, *w2h, *w2l, *wph, *qsh, *qsl;
    cudaGetSymbolAddress((void**)&xsh, g_xs_hi);
    cudaGetSymbolAddress((void**)&pesh, g_pes_hi); cudaGetSymbolAddress((void**)&pesl, g_pes_lo);
    cudaGetSymbolAddress((void**)&p1h, g_p1s_hi);
    cudaGetSymbolAddress((void**)&p2h, g_p2s_hi);  cudaGetSymbolAddress((void**)&p2l, g_p2s_lo);
    cudaGetSymbolAddress((void**)&osh, g_os_hi);
    cudaGetSymbolAddress((void**)&wqh, g_wqkv_hi);
    cudaGetSymbolAddress((void**)&w1h, g_wc1_hi);  cudaGetSymbolAddress((void**)&w1l, g_wc1_lo);
    cudaGetSymbolAddress((void**)&w2h, g_wc2_hi);  cudaGetSymbolAddress((void**)&w2l, g_wc2_lo);
    cudaGetSymbolAddress((void**)&wph, g_wpj_hi);
    cudaGetSymbolAddress((void**)&qsh, g_qkvs_hi); cudaGetSymbolAddress((void**)&qsl, g_qkvs_lo);

    static bool attrSet = false;
    if (!attrSet) {
        cudaFuncSetAttribute(gemm_mma<3, false, true, false, true>,   cudaFuncAttributeMaxDynamicSharedMemorySize, GEMM_SMEM3);
        cudaFuncSetAttribute(gemm_mma<2, true, false, false, false>,  cudaFuncAttributeMaxDynamicSharedMemorySize, GEMM_SMEM2);
        cudaFuncSetAttribute(gemm_mma<1, false, false, true, false>,  cudaFuncAttributeMaxDynamicSharedMemorySize, GEMM_SMEM1);
        cudaFuncSetAttribute(gemm_mma<1, false, true, false, false>,  cudaFuncAttributeMaxDynamicSharedMemorySize, GEMM_SMEM1);
        cudaFuncSetAttribute(attn_mma, cudaFuncAttributeMaxDynamicSharedMemorySize, ATT_SMEM);
        attrSet = true;
    }

    const int M = BB * NN;       // 8192
    const int NKT = CC / 64;     // 8

    // 0) zero GN stats + split conversions
    gn_zero_kernel<<<1, 128>>>();
    split(pe, pesh, pesl, CC, M, true);        // A of conv (3-term)
    split(x, xsh, nullptr, CC, M, false);      // A of QKV (1-term)
    split(qkv_w, wqh, nullptr, CC, 3 * CC, false);  // B of QKV (1-term)
    split(conv1_w, w1h, w1l, CC, CC, true);    // B of conv (3-term)
    split(conv2_w, w2h, w2l, CC, CC, true);
    split(proj_w, wph, nullptr, CC, CC, false); // B of proj (1-term)

    // 1) conv1 / conv2 -> P1, P2 (fp32) + GN stats (fp16 3-term)
    gemm_mma<3, false, true, false, true><<<dim3(CC / 128, M / 128, 1), 256, GEMM_SMEM3>>>(
        pesh, pesl, w1h, w1l, conv1_b, p1, nullptr, nullptr, st1, NKT, 0, 0, 0, CC);
    gemm_mma<3, false, true, false, true><<<dim3(CC / 128, M / 128, 1), 256, GEMM_SMEM3>>>(
        pesh, pesl, w2h, w2l, conv2_b, p2, nullptr, nullptr, st2, NKT, 0, 0, 0, CC);

    // 2) GN apply -> writes P1 (hi) / P2 (hi+lo) split tiles
    gn_apply_kernel<<<dim3(2048, 2), 256>>>(
        gn1_g, gn1_b, gn2_g, gn2_b, p1h, p2h, p2l);

    // 3) PE gate: 0.125 * sigmoid(P1 @ P2^T)   (fp16 2-term)
    gemm_mma<2, true, false, false, false><<<dim3(NN / 128, NN / 128, BB), 256, GEMM_SMEM2>>>(
        p1h, nullptr, p2h, p2l, nullptr, pem, nullptr, nullptr, nullptr, NKT,
        (NN / 128) * NKT, (NN / 128) * NKT, (long long)NN * NN, NN);

    // 4) QKV projection -> split tiles (fp16 1-term; epilogue writes hi+lo)
    gemm_mma<1, false, false, true, false><<<dim3(3 * CC / 128, M / 128, 1), 256, GEMM_SMEM1>>>(
        xsh, nullptr, wqh, nullptr, nullptr, nullptr, qsh, qsl, nullptr, NKT, 0, 0, 0, 3 * CC);

    // 5) attention: QK 1-term, PV 2-term -> O hi tiles
    attn_mma<<<dim3(NN / 128, HH, BB), 256, ATT_SMEM>>>();

    // 6) output projection (fp16 1-term)
    gemm_mma<1, false, true, false, false><<<dim3(CC / 128, M / 128, 1), 256, GEMM_SMEM1>>>(
        osh, nullptr, wph, nullptr, proj_b, out, nullptr, nullptr, nullptr, NKT, 0, 0, 0, CC);
}

// round 13
// speedup vs baseline: 1.2403x; 1.2403x over previous
#include <cuda_runtime.h>
#include <cuda_fp16.h>
#include <cstdint>
#include <math.h>

// Problem constants
#define BB 4
#define NN 2048
#define CC 512
#define HH 8
#define DH 64
#define GROUPS 8

// ===========================================================================
// Scratch (__device__ globals; alloc-free rule)
// ===========================================================================
__device__ float g_P1[BB * NN * CC];
__device__ float g_P2[BB * NN * CC];
__device__ __half g_PEh[(size_t)BB * NN * NN];  // 0.125 * sigmoid(...), fp16
__device__ float g_gnstat1[BB * GROUPS * 2];    // (sum, sumsq) per (b,g)
__device__ float g_gnstat2[BB * GROUPS * 2];

// fp16 split operands, tiled SW128 layout (tile = 128 rows x 64 f16 = 16KB)
#define TILE_BYTES 16384
__device__ char g_xs_hi[8192 * 1024];
__device__ char g_pes_hi[8192 * 1024], g_pes_lo[8192 * 1024];
__device__ char g_p1s_hi[8192 * 1024];
__device__ char g_p2s_hi[8192 * 1024], g_p2s_lo[8192 * 1024];
__device__ char g_os_hi[8192 * 1024];
__device__ char g_wqkv_hi[1536 * 1024];
__device__ char g_wc1_hi[512 * 1024],  g_wc1_lo[512 * 1024];
__device__ char g_wc2_hi[512 * 1024],  g_wc2_lo[512 * 1024];
__device__ char g_wpj_hi[512 * 1024],  g_wpj_lo[512 * 1024];
// QKV in split-tile form: 64 row-tiles x 24 col-tiles x 16KB
__device__ char g_qkvs_hi[64 * 24 * TILE_BYTES];
__device__ char g_qkvs_lo[64 * 24 * TILE_BYTES];   // only V-lo tiles used

// ===========================================================================
// Helpers
// ===========================================================================
__device__ __forceinline__ uint32_t smem_to_u32(const void* p) {
    uint32_t a;
    asm("{ .reg .u64 t; cvta.to.shared.u64 t, %1; cvt.u32.u64 %0, t; }"
        : "=r"(a) : "l"(p));
    return a;
}

__device__ __forceinline__ void cpa16(uint32_t s, const void* g) {
    asm volatile("cp.async.cg.shared.global [%0], [%1], 16;" :: "r"(s), "l"(g));
}

__device__ __forceinline__ void ldm_x4(uint32_t* r, uint32_t addr) {
    asm volatile("ldmatrix.sync.aligned.m8n8.x4.shared.b16 {%0,%1,%2,%3}, [%4];"
        : "=r"(r[0]), "=r"(r[1]), "=r"(r[2]), "=r"(r[3]) : "r"(addr));
}

__device__ __forceinline__ void ldm_x4_t(uint32_t* r, uint32_t addr) {
    asm volatile("ldmatrix.sync.aligned.m8n8.x4.trans.shared.b16 {%0,%1,%2,%3}, [%4];"
        : "=r"(r[0]), "=r"(r[1]), "=r"(r[2]), "=r"(r[3]) : "r"(addr));
}

__device__ __forceinline__ void mma_f16(float* d, const uint32_t* a,
                                        const uint32_t* b) {
    asm volatile(
        "mma.sync.aligned.m16n8k16.row.col.f32.f16.f16.f32 "
        "{%0,%1,%2,%3}, {%4,%5,%6,%7}, {%8,%9}, {%0,%1,%2,%3};"
        : "+f"(d[0]), "+f"(d[1]), "+f"(d[2]), "+f"(d[3])
        : "r"(a[0]), "r"(a[1]), "r"(a[2]), "r"(a[3]), "r"(b[0]), "r"(b[1]));
}

// pack (lo, hi) floats -> f16x2 reg (lo in low 16 bits)
__device__ __forceinline__ uint32_t packh(float lo, float hi) {
    uint32_t d;
    asm("cvt.rn.f16x2.f32 %0, %1, %2;" : "=r"(d) : "f"(hi), "f"(lo));
    return d;
}

// ===========================================================================
// Split fp32 -> (f16 hi, f16 lo) into tiled SW128-swizzled layout.
// ===========================================================================
template <bool WLO>
__global__ void __launch_bounds__(256) split_f16_kernel(
    const float* __restrict__ X, char* __restrict__ Hi, char* __restrict__ Lo,
    int K, int total8)
{
    int idx = blockIdx.x * 256 + threadIdx.x;
    if (idx >= total8) return;
    int perRow = K >> 3;
    int r = idx / perRow;
    int c = (idx % perRow) << 3;

    float4 v0 = *(const float4*)(X + (size_t)r * K + c);
    float4 v1 = *(const float4*)(X + (size_t)r * K + c + 4);
    float vin[8] = {v0.x, v0.y, v0.z, v0.w, v1.x, v1.y, v1.z, v1.w};

    uint32_t hw[4], lw[4];
#pragma unroll
    for (int i = 0; i < 4; i++) {
        __half h0 = __float2half(vin[2 * i]);
        __half h1 = __float2half(vin[2 * i + 1]);
        __half2 hp = {h0, h1};
        hw[i] = *reinterpret_cast<uint32_t*>(&hp);
        if (WLO) {
            float l0 = vin[2 * i] - __half2float(h0);
            float l1 = vin[2 * i + 1] - __half2float(h1);
            lw[i] = packh(l0, l1);
        }
    }

    int rt = r >> 7, rr = r & 127;
    int kt = c >> 6, cc = c & 63;
    int tile = rt * (K >> 6) + kt;
    uint32_t inTile = rr * 128 + cc * 2;
    uint32_t sw = inTile ^ ((inTile >> 3) & 0x70);
    size_t off = (size_t)tile * TILE_BYTES + sw;
    *(uint4*)(Hi + off) = make_uint4(hw[0], hw[1], hw[2], hw[3]);
    if (WLO) *(uint4*)(Lo + off) = make_uint4(lw[0], lw[1], lw[2], lw[3]);
}

// ===========================================================================
// Zero GN stat accumulators
// ===========================================================================
__global__ void gn_zero_kernel()
{
    if (threadIdx.x < BB * GROUPS * 2) {
        g_gnstat1[threadIdx.x] = 0.f;
        g_gnstat2[threadIdx.x] = 0.f;
    }
}

// ===========================================================================
// fp16 split GEMM-NT via mma.sync.
// TERMS=1: ah*bh. TERMS=2: + ah*bl. TERMS=3: + al*bh.
// SIG: writes fp16 gate (0.125*sigmoid) into C interpreted as __half*.
// GNSTAT: epilogue accumulates (sum, sumsq) per (b, group) via atomics.
// ===========================================================================
template <int TERMS, bool SIG, bool BIAS, bool SPLIT, bool GNSTAT>
__global__ void __launch_bounds__(256) gemm_mma(
    const char* __restrict__ Ahi, const char* __restrict__ Alo,
    const char* __restrict__ Bhi, const char* __restrict__ Blo,
    const float* __restrict__ bias, void* __restrict__ C,
    char* __restrict__ Chi, char* __restrict__ Clo,
    float* __restrict__ stats,
    int numKt, int aBatchTiles, int bBatchTiles, long long cBatchStride, int ldc)
{
    constexpr int NTILES = TERMS + 1;
    constexpr uint32_t STB = NTILES * TILE_BYTES;

    extern __shared__ __align__(128) char smem[];
    uint32_t smem_base = smem_to_u32(smem);
    const int tid = threadIdx.x;
    const int wid = tid >> 5;
    const int lane = tid & 31;
    const int wm = wid & 1;
    const int wn = wid >> 1;

    const long long aTileBase = (long long)blockIdx.z * aBatchTiles + (long long)blockIdx.y * numKt;
    const long long bTileBase = (long long)blockIdx.z * bBatchTiles + (long long)blockIdx.x * numKt;

    auto issue_loads = [&](int kt, int stage) {
        const char* srcs[4];
        srcs[0] = Ahi + (aTileBase + kt) * TILE_BYTES;
        srcs[1] = Bhi + (bTileBase + kt) * TILE_BYTES;
        if (TERMS >= 2) srcs[2] = Blo + (bTileBase + kt) * TILE_BYTES;
        if (TERMS == 3) srcs[3] = Alo + (aTileBase + kt) * TILE_BYTES;
        uint32_t sb = smem_base + stage * STB;
#pragma unroll
        for (int t = 0; t < NTILES; t++)
#pragma unroll
            for (int i = 0; i < 4; i++) {
                uint32_t o = t * TILE_BYTES + i * 4096 + tid * 16;
                cpa16(sb + o, srcs[t] + i * 4096 + tid * 16);
            }
        asm volatile("cp.async.commit_group;" ::: "memory");
    };

    const int aRowBase = wm * 64 + (lane & 15);
    const uint32_t aKadd = (lane >> 4) * 16;
    const int bRowBase = wn * 32 + ((lane >> 4) << 3) + (lane & 7);
    const uint32_t bKadd = ((lane >> 3) & 1) * 16;

    float acc[4][4][4];
#pragma unroll
    for (int mt = 0; mt < 4; mt++)
#pragma unroll
        for (int nt = 0; nt < 4; nt++)
#pragma unroll
            for (int f = 0; f < 4; f++) acc[mt][nt][f] = 0.f;

    issue_loads(0, 0);

    for (int c = 0; c < numKt; c++) {
        const int buf = c & 1;
        if (c + 1 < numKt) {
            issue_loads(c + 1, buf ^ 1);
            asm volatile("cp.async.wait_group 1;" ::: "memory");
        } else {
            asm volatile("cp.async.wait_group 0;" ::: "memory");
        }
        __syncthreads();

        const uint32_t sb = smem_base + buf * STB;
        const uint32_t aHiB = sb;
        const uint32_t bHiB = sb + TILE_BYTES;
        const uint32_t bLoB = sb + 2 * TILE_BYTES;
        const uint32_t aLoB = sb + 3 * TILE_BYTES;

#pragma unroll
        for (int ks = 0; ks < 4; ks++) {
            uint32_t ah[4][4], al[4][4];
#pragma unroll
            for (int mt = 0; mt < 4; mt++) {
                int row = aRowBase + mt * 16;
                uint32_t koff = (ks * 32 + aKadd) ^ ((row & 7) << 4);
                uint32_t off = (uint32_t)row * 128 + koff;
                ldm_x4(ah[mt], aHiB + off);
                if (TERMS == 3) ldm_x4(al[mt], aLoB + off);
            }
            uint32_t bh[2][4], bl[2][4];
#pragma unroll
            for (int np = 0; np < 2; np++) {
                int row = bRowBase + np * 16;
                uint32_t koff = (ks * 32 + bKadd) ^ ((row & 7) << 4);
                uint32_t off = (uint32_t)row * 128 + koff;
                ldm_x4(bh[np], bHiB + off);
                if (TERMS >= 2) ldm_x4(bl[np], bLoB + off);
            }
#pragma unroll
            for (int mt = 0; mt < 4; mt++)
#pragma unroll
                for (int nt = 0; nt < 4; nt++) {
                    const uint32_t* bhp = &bh[nt >> 1][(nt & 1) * 2];
                    mma_f16(acc[mt][nt], ah[mt], bhp);
                    if (TERMS >= 2) {
                        const uint32_t* blp = &bl[nt >> 1][(nt & 1) * 2];
                        mma_f16(acc[mt][nt], ah[mt], blp);
                    }
                    if (TERMS == 3) mma_f16(acc[mt][nt], al[mt], bhp);
                }
        }
        __syncthreads();
    }

    // Epilogue
    const int g = lane >> 2, tg = lane & 3;
    float ls = 0.f, lsq = 0.f;
    if (SPLIT) {
        const int tilesPerRow = ldc >> 6;
#pragma unroll
        for (int mt = 0; mt < 4; mt++) {
            const int row0 = blockIdx.y * 128 + wm * 64 + mt * 16 + g;
#pragma unroll
            for (int nt = 0; nt < 4; nt++) {
                const int col = blockIdx.x * 128 + wn * 32 + nt * 8 + tg * 2;
                const int tile = (row0 >> 7) * tilesPerRow + (col >> 6);
#pragma unroll
                for (int half = 0; half < 2; half++) {
                    const int rowIn = (row0 & 127) + half * 8;
                    float v0 = acc[mt][nt][half * 2 + 0];
                    float v1 = acc[mt][nt][half * 2 + 1];
                    __half h0 = __float2half(v0);
                    __half h1 = __float2half(v1);
                    float l0 = v0 - __half2float(h0);
                    float l1 = v1 - __half2float(h1);
                    __half2 hp = {h0, h1};
                    uint32_t inoff = rowIn * 128 + (col & 63) * 2;
                    uint32_t sw = inoff ^ ((inoff >> 3) & 0x70);
                    *(uint32_t*)(Chi + (size_t)tile * TILE_BYTES + sw) =
                        *reinterpret_cast<uint32_t*>(&hp);
                    *(uint32_t*)(Clo + (size_t)tile * TILE_BYTES + sw) = packh(l0, l1);
                }
            }
        }
    } else if (SIG) {
        __half* Gbase = (__half*)C + (long long)blockIdx.z * cBatchStride;
#pragma unroll
        for (int mt = 0; mt < 4; mt++) {
            const int row0 = blockIdx.y * 128 + wm * 64 + mt * 16 + g;
#pragma unroll
            for (int nt = 0; nt < 4; nt++) {
                const int col = blockIdx.x * 128 + wn * 32 + nt * 8 + tg * 2;
#pragma unroll
                for (int half = 0; half < 2; half++) {
                    float v0 = 0.125f / (1.f + __expf(-acc[mt][nt][half * 2 + 0]));
                    float v1 = 0.125f / (1.f + __expf(-acc[mt][nt][half * 2 + 1]));
                    *(uint32_t*)(Gbase + (long long)(row0 + half * 8) * ldc + col) =
                        packh(v0, v1);
                }
            }
        }
    } else {
        float* Cbase = (float*)C + (long long)blockIdx.z * cBatchStride;
#pragma unroll
        for (int mt = 0; mt < 4; mt++) {
            const int row0 = blockIdx.y * 128 + wm * 64 + mt * 16 + g;
#pragma unroll
            for (int nt = 0; nt < 4; nt++) {
                const int col = blockIdx.x * 128 + wn * 32 + nt * 8 + tg * 2;
                float b0 = 0.f, b1 = 0.f;
                if (BIAS) { b0 = bias[col]; b1 = bias[col + 1]; }
#pragma unroll
                for (int half = 0; half < 2; half++) {
                    float v0 = acc[mt][nt][half * 2 + 0] + b0;
                    float v1 = acc[mt][nt][half * 2 + 1] + b1;
                    if (GNSTAT) {
                        ls += v0 + v1;
                        lsq += v0 * v0 + v1 * v1;
                    }
                    *(float2*)(Cbase + (long long)(row0 + half * 8) * ldc + col) =
                        make_float2(v0, v1);
                }
            }
        }
        if (GNSTAT) {
#pragma unroll
            for (int off = 16; off > 0; off >>= 1) {
                ls  += __shfl_xor_sync(0xffffffffu, ls, off);
                lsq += __shfl_xor_sync(0xffffffffu, lsq, off);
            }
            if (lane == 0) {
                const int b = blockIdx.y >> 4;
                const int grp = blockIdx.x * 2 + (wn >> 1);
                atomicAdd(&stats[(b * GROUPS + grp) * 2 + 0], ls);
                atomicAdd(&stats[(b * GROUPS + grp) * 2 + 1], lsq);
            }
        }
    }
}

// ===========================================================================
// GN apply: normalize P (fp32) using precomputed stats and write f16 hi(/lo)
// SW128 split tiles (p1: hi only — A operand; p2: hi+lo).
// ===========================================================================
__global__ void __launch_bounds__(256) gn_apply_kernel(
    const float* __restrict__ g1, const float* __restrict__ b1,
    const float* __restrict__ g2, const float* __restrict__ b2,
    char* __restrict__ p1Hi,
    char* __restrict__ p2Hi, char* __restrict__ p2Lo)
{
    const int which = blockIdx.y;
    const float* P = which == 0 ? g_P1 : g_P2;
    const float* st = which == 0 ? g_gnstat1 : g_gnstat2;
    const float* gamma = which == 0 ? g1 : g2;
    const float* beta  = which == 0 ? b1 : b2;
    char* Hi = which == 0 ? p1Hi : p2Hi;
    char* Lo = p2Lo;
    const bool wlo = (which == 1);

    const int idx = blockIdx.x * 256 + threadIdx.x;
    const int r = idx >> 6;
    const int c = (idx & 63) << 3;
    const int b = r >> 11;
    const int grp = c >> 6;
    const float CNT = (float)((CC / GROUPS) * NN);

    const float s = st[(b * GROUPS + grp) * 2 + 0];
    const float sq = st[(b * GROUPS + grp) * 2 + 1];
    const float mean = s / CNT;
    const float var = sq / CNT - mean * mean;
    const float rstd = rsqrtf(var + 1e-5f);

    float4 v0 = *(const float4*)(P + (size_t)r * CC + c);
    float4 v1 = *(const float4*)(P + (size_t)r * CC + c + 4);
    float vin[8] = {v0.x, v0.y, v0.z, v0.w, v1.x, v1.y, v1.z, v1.w};
    float4 gm0 = *(const float4*)(gamma + c);
    float4 gm1 = *(const float4*)(gamma + c + 4);
    float4 bt0 = *(const float4*)(beta + c);
    float4 bt1 = *(const float4*)(beta + c + 4);
    float gm[8] = {gm0.x, gm0.y, gm0.z, gm0.w, gm1.x, gm1.y, gm1.z, gm1.w};
    float bt[8] = {bt0.x, bt0.y, bt0.z, bt0.w, bt1.x, bt1.y, bt1.z, bt1.w};

    uint32_t hw[4], lw[4];
#pragma unroll
    for (int i = 0; i < 4; i++) {
        float a0 = (vin[2 * i] - mean) * rstd * gm[2 * i] + bt[2 * i];
        float a1 = (vin[2 * i + 1] - mean) * rstd * gm[2 * i + 1] + bt[2 * i + 1];
        __half h0 = __float2half(a0);
        __half h1 = __float2half(a1);
        __half2 hp = {h0, h1};
        hw[i] = *reinterpret_cast<uint32_t*>(&hp);
        lw[i] = packh(a0 - __half2float(h0), a1 - __half2float(h1));
    }

    const int tile = (r >> 7) * 8 + grp;
    uint32_t inTile = (uint32_t)(r & 127) * 128 + (c & 63) * 2;
    uint32_t sw = inTile ^ ((inTile >> 3) & 0x70);
    size_t off = (size_t)tile * TILE_BYTES + sw;
    *(uint4*)(Hi + off) = make_uint4(hw[0], hw[1], hw[2], hw[3]);
    if (wlo) *(uint4*)(Lo + off) = make_uint4(lw[0], lw[1], lw[2], lw[3]);
}

// ===========================================================================
// Tensor-core flash attention with fp16 PE gate, register-prefetched.
// S = Qh*Kh (1-term), O += Ph*(Vh+Vl) (2-term). Grid (N/128, H, B); 8 warps.
// ===========================================================================
#define ATT_STAGE 24576
#define ATT_SMEM (16384 + 2 * ATT_STAGE)   // Q hi + 2 KV stages = 64KB

__global__ void __launch_bounds__(256) attn_mma()
{
    extern __shared__ __align__(128) char smem[];
    const uint32_t sb = smem_to_u32(smem);
    const uint32_t qh_base = sb;
    const uint32_t stage0 = sb + 16384;

    const int tid = threadIdx.x, wid = tid >> 5, lane = tid & 31;
    const int q0 = blockIdx.x * 128, h = blockIdx.y, b = blockIdx.z;
    const int g = lane >> 2, tg = lane & 3;

    const int rtQ = (b * NN + q0) >> 7;
    {
        const char* qsh = g_qkvs_hi + (size_t)(rtQ * 24 + h) * TILE_BYTES;
#pragma unroll
        for (int i = 0; i < 4; i++)
            cpa16(qh_base + i * 4096 + tid * 16, qsh + i * 4096 + tid * 16);
        asm volatile("cp.async.commit_group;" ::: "memory");
    }

    auto issue_kv = [&](int t, int stg) {
        const int kRow = t * 64;
        const int rt = (b * NN + kRow) >> 7;
        const int halfOff = (kRow & 64) ? 8192 : 0;
        const char* kh = g_qkvs_hi + (size_t)(rt * 24 + 8 + h) * TILE_BYTES + halfOff;
        const char* vh = g_qkvs_hi + (size_t)(rt * 24 + 16 + h) * TILE_BYTES + halfOff;
        const char* vl = g_qkvs_lo + (size_t)(rt * 24 + 16 + h) * TILE_BYTES + halfOff;
        uint32_t s = stage0 + stg * ATT_STAGE;
#pragma unroll
        for (int i = 0; i < 2; i++) {
            uint32_t o = i * 4096 + tid * 16;
            cpa16(s + o,         kh + o);
            cpa16(s + 8192 + o,  vh + o);
            cpa16(s + 16384 + o, vl + o);
        }
        asm volatile("cp.async.commit_group;" ::: "memory");
    };

    issue_kv(0, 0);
    asm volatile("cp.async.wait_group 1;" ::: "memory");  // Q arrived
    __syncthreads();

    // Q fragments (hi only, resident)
    uint32_t qfh[4][4];
    {
        const int row = wid * 16 + (lane & 15);
        const uint32_t roff = (uint32_t)row * 128;
#pragma unroll
        for (int ks = 0; ks < 4; ks++) {
            uint32_t colb = (lane >> 4) * 16 + ks * 32;
            uint32_t a = roff + (colb ^ ((row & 7) << 4));
            ldm_x4(qfh[ks], qh_base + a);
        }
    }

    float Oa[8][4];
#pragma unroll
    for (int nt = 0; nt < 8; nt++)
#pragma unroll
        for (int f = 0; f < 4; f++) Oa[nt][f] = 0.f;
    float mrow[2] = {-1e30f, -1e30f}, lrow[2] = {0.f, 0.f};

    const size_t peBase = (size_t)b * NN * NN;
    const int qRow0 = q0 + wid * 16 + g;
    const int bRow0 = ((lane >> 4) << 3) + (lane & 7);
    const uint32_t bKadd = ((lane >> 3) & 1) * 16;

    for (int t = 0; t < NN / 64; t++) {
        const int buf = t & 1;
        const int k0 = t * 64;

        // Prefetch fp16 PE gate words for this tile BEFORE the QK MMAs so
        // the global-load latency overlaps tensor work.
        uint32_t peReg[16];
#pragma unroll
        for (int nt = 0; nt < 8; nt++)
#pragma unroll
            for (int r = 0; r < 2; r++)
                peReg[nt * 2 + r] = *(const uint32_t*)&g_PEh[
                    peBase + (size_t)(qRow0 + r * 8) * NN + k0 + nt * 8 + tg * 2];

        if (t + 1 < NN / 64) {
            issue_kv(t + 1, buf ^ 1);
            asm volatile("cp.async.wait_group 1;" ::: "memory");
        } else {
            asm volatile("cp.async.wait_group 0;" ::: "memory");
        }
        __syncthreads();

        const uint32_t kb = stage0 + buf * ATT_STAGE;
        const uint32_t kh_b = kb;
        const uint32_t vh_b = kb + 8192, vl_b = kb + 16384;

        // S = Q K^T (fp16 1-term)
        float S[8][4];
#pragma unroll
        for (int nt = 0; nt < 8; nt++)
#pragma unroll
            for (int f = 0; f < 4; f++) S[nt][f] = 0.f;

#pragma unroll
        for (int ks = 0; ks < 4; ks++) {
#pragma unroll
            for (int np = 0; np < 4; np++) {
                const int row = bRow0 + np * 16;
                const uint32_t a = (uint32_t)row * 128 +
                                   ((ks * 32 + bKadd) ^ ((row & 7) << 4));
                uint32_t KH[4];
                ldm_x4(KH, kh_b + a);
#pragma unroll
                for (int hn = 0; hn < 2; hn++)
                    mma_f16(S[np * 2 + hn], qfh[ks], &KH[hn * 2]);
            }
        }

        // gate with prefetched fp16 PE (0.125 pre-folded)
#pragma unroll
        for (int nt = 0; nt < 8; nt++) {
#pragma unroll
            for (int r = 0; r < 2; r++) {
                const float2 pe = __half22float2(
                    *reinterpret_cast<const __half2*>(&peReg[nt * 2 + r]));
                S[nt][r * 2 + 0] *= pe.x;
                S[nt][r * 2 + 1] *= pe.y;
            }
        }

        // online softmax
        float corr[2];
#pragma unroll
        for (int r = 0; r < 2; r++) {
            float vm = -1e30f;
#pragma unroll
            for (int nt = 0; nt < 8; nt++)
                vm = fmaxf(vm, fmaxf(S[nt][r * 2], S[nt][r * 2 + 1]));
            vm = fmaxf(vm, __shfl_xor_sync(0xffffffffu, vm, 1));
            vm = fmaxf(vm, __shfl_xor_sync(0xffffffffu, vm, 2));
            const float mn = fmaxf(mrow[r], vm);
            corr[r] = __expf(mrow[r] - mn);
            mrow[r] = mn;
            float rsum = 0.f;
#pragma unroll
            for (int nt = 0; nt < 8; nt++) {
                float p0 = __expf(S[nt][r * 2] - mn);
                float p1 = __expf(S[nt][r * 2 + 1] - mn);
                S[nt][r * 2] = p0;
                S[nt][r * 2 + 1] = p1;
                rsum += p0 + p1;
            }
            rsum += __shfl_xor_sync(0xffffffffu, rsum, 1);
            rsum += __shfl_xor_sync(0xffffffffu, rsum, 2);
            lrow[r] = lrow[r] * corr[r] + rsum;
        }
#pragma unroll
        for (int nt = 0; nt < 8; nt++) {
            Oa[nt][0] *= corr[0]; Oa[nt][1] *= corr[0];
            Oa[nt][2] *= corr[1]; Oa[nt][3] *= corr[1];
        }

        // O += P V (fp16 2-term); P hi fragments from S accumulators
#pragma unroll
        for (int ks = 0; ks < 4; ks++) {
            uint32_t ah[4];
#pragma unroll
            for (int q = 0; q < 2; q++) {
                const float* sv = S[2 * ks + q];
                ah[q * 2 + 0] = packh(sv[0], sv[1]);
                ah[q * 2 + 1] = packh(sv[2], sv[3]);
            }
#pragma unroll
            for (int dp = 0; dp < 4; dp++) {
                const int row = ks * 16 + (lane & 15);
                const uint32_t a = (uint32_t)row * 128 +
                    ((dp * 32 + (lane >> 4) * 16) ^ ((row & 7) << 4));
                uint32_t VH[4], VL[4];
                ldm_x4_t(VH, vh_b + a);
                ldm_x4_t(VL, vl_b + a);
#pragma unroll
                for (int hn = 0; hn < 2; hn++) {
                    const int nt = dp * 2 + hn;
                    mma_f16(Oa[nt], ah, &VH[hn * 2]);
                    mma_f16(Oa[nt], ah, &VL[hn * 2]);
                }
            }
        }
        __syncthreads();
    }

    // Epilogue: normalize and write hi tiles for proj GEMM (O is A operand)
    const float inv[2] = {1.f / lrow[0], 1.f / lrow[1]};
    char* osh = g_os_hi + (size_t)(rtQ * 8 + h) * TILE_BYTES;
#pragma unroll
    for (int nt = 0; nt < 8; nt++) {
#pragma unroll
        for (int r = 0; r < 2; r++) {
            const float v0 = Oa[nt][r * 2 + 0] * inv[r];
            const float v1 = Oa[nt][r * 2 + 1] * inv[r];
            const int rowIn = wid * 16 + g + r * 8;
            const uint32_t inoff = (uint32_t)rowIn * 128 + nt * 16 + tg * 4;
            const uint32_t sw = inoff ^ ((inoff >> 3) & 0x70);
            *(uint32_t*)(osh + sw) = packh(v0, v1);
        }
    }
}

// ===========================================================================

static void split(const void* X, void* Hi, void* Lo, int K, int rows, bool wlo)
{
    int total8 = rows * K / 8;
    if (wlo)
        split_f16_kernel<true><<<(total8 + 255) / 256, 256>>>(
            (const float*)X, (char*)Hi, (char*)Lo, K, total8);
    else
        split_f16_kernel<false><<<(total8 + 255) / 256, 256>>>(
            (const float*)X, (char*)Hi, nullptr, K, total8);
}

#define GEMM_SMEM1 (2 * 2 * TILE_BYTES)   // 64KB
#define GEMM_SMEM2 (2 * 3 * TILE_BYTES)   // 96KB
#define GEMM_SMEM3 (2 * 4 * TILE_BYTES)   // 128KB

extern "C" void kernel_launch(void* const* d_in, const int* in_sizes, int n_in,
                              void* d_out, int out_size)
{
    const float* x       = (const float*)d_in[0];
    const float* pe      = (const float*)d_in[1];
    const float* qkv_w   = (const float*)d_in[2];
    const float* proj_w  = (const float*)d_in[3];
    const float* proj_b  = (const float*)d_in[4];
    const float* conv1_w = (const float*)d_in[5];
    const float* conv1_b = (const float*)d_in[6];
    const float* gn1_g   = (const float*)d_in[7];
    const float* gn1_b   = (const float*)d_in[8];
    const float* conv2_w = (const float*)d_in[9];
    const float* conv2_b = (const float*)d_in[10];
    const float* gn2_g   = (const float*)d_in[11];
    const float* gn2_b   = (const float*)d_in[12];
    float* out = (float*)d_out;

    float *p1, *p2, *st1, *st2;
    void* pehRaw;
    cudaGetSymbolAddress((void**)&p1, g_P1);
    cudaGetSymbolAddress((void**)&p2, g_P2);
    cudaGetSymbolAddress(&pehRaw, g_PEh);
    cudaGetSymbolAddress((void**)&st1, g_gnstat1);
    cudaGetSymbolAddress((void**)&st2, g_gnstat2);

    char *xsh, *pesh, *pesl, *p1h, *p2h, *p2l, *osh;
    char *wqh, *w1h, *w1l, *w2h, *w2l, *wph, *wpl, *qsh, *qsl;
    cudaGetSymbolAddress((void**)&xsh, g_xs_hi);
    cudaGetSymbolAddress((void**)&pesh, g_pes_hi); cudaGetSymbolAddress((void**)&pesl, g_pes_lo);
    cudaGetSymbolAddress((void**)&p1h, g_p1s_hi);
    cudaGetSymbolAddress((void**)&p2h, g_p2s_hi);  cudaGetSymbolAddress((void**)&p2l, g_p2s_lo);
    cudaGetSymbolAddress((void**)&osh, g_os_hi);
    cudaGetSymbolAddress((void**)&wqh, g_wqkv_hi);
    cudaGetSymbolAddress((void**)&w1h, g_wc1_hi);  cudaGetSymbolAddress((void**)&w1l, g_wc1_lo);
    cudaGetSymbolAddress((void**)&w2h, g_wc2_hi);  cudaGetSymbolAddress((void**)&w2l, g_wc2_lo);
    cudaGetSymbolAddress((void**)&wph, g_wpj_hi);  cudaGetSymbolAddress((void**)&wpl, g_wpj_lo);
    cudaGetSymbolAddress((void**)&qsh, g_qkvs_hi); cudaGetSymbolAddress((void**)&qsl, g_qkvs_lo);

    static bool attrSet = false;
    if (!attrSet) {
        cudaFuncSetAttribute(gemm_mma<3, false, true, false, true>,   cudaFuncAttributeMaxDynamicSharedMemorySize, GEMM_SMEM3);
        cudaFuncSetAttribute(gemm_mma<2, true, false, false, false>,  cudaFuncAttributeMaxDynamicSharedMemorySize, GEMM_SMEM2);
        cudaFuncSetAttribute(gemm_mma<1, false, false, true, false>,  cudaFuncAttributeMaxDynamicSharedMemorySize, GEMM_SMEM1);
        cudaFuncSetAttribute(gemm_mma<2, false, true, false, false>,  cudaFuncAttributeMaxDynamicSharedMemorySize, GEMM_SMEM2);
        cudaFuncSetAttribute(attn_mma, cudaFuncAttributeMaxDynamicSharedMemorySize, ATT_SMEM);
        attrSet = true;
    }

    const int M = BB * NN;       // 8192
    const int NKT = CC / 64;     // 8

    // 0) zero GN stats + split conversions
    gn_zero_kernel<<<1, 128>>>();
    split(pe, pesh, pesl, CC, M, true);             // A of conv (3-term)
    split(x, xsh, nullptr, CC, M, false);           // A of QKV (1-term)
    split(qkv_w, wqh, nullptr, CC, 3 * CC, false);  // B of QKV (1-term)
    split(conv1_w, w1h, w1l, CC, CC, true);         // B of conv (3-term)
    split(conv2_w, w2h, w2l, CC, CC, true);
    split(proj_w, wph, wpl, CC, CC, true);          // B of proj (2-term)

    // 1) conv1 / conv2 -> P1, P2 (fp32) + GN stats (fp16 3-term)
    gemm_mma<3, false, true, false, true><<<dim3(CC / 128, M / 128, 1), 256, GEMM_SMEM3>>>(
        pesh, pesl, w1h, w1l, conv1_b, p1, nullptr, nullptr, st1, NKT, 0, 0, 0, CC);
    gemm_mma<3, false, true, false, true><<<dim3(CC / 128, M / 128, 1), 256, GEMM_SMEM3>>>(
        pesh, pesl, w2h, w2l, conv2_b, p2, nullptr, nullptr, st2, NKT, 0, 0, 0, CC);

    // 2) GN apply -> writes P1 (hi) / P2 (hi+lo) split tiles
    gn_apply_kernel<<<dim3(2048, 2), 256>>>(
        gn1_g, gn1_b, gn2_g, gn2_b, p1h, p2h, p2l);

    // 3) PE gate: 0.125 * sigmoid(P1 @ P2^T) -> fp16 gate  (fp16 2-term)
    gemm_mma<2, true, false, false, false><<<dim3(NN / 128, NN / 128, BB), 256, GEMM_SMEM2>>>(
        p1h, nullptr, p2h, p2l, nullptr, pehRaw, nullptr, nullptr, nullptr, NKT,
        (NN / 128) * NKT, (NN / 128) * NKT, (long long)NN * NN, NN);

    // 4) QKV projection -> split tiles (fp16 1-term; epilogue writes hi+lo)
    gemm_mma<1, false, false, true, false><<<dim3(3 * CC / 128, M / 128, 1), 256, GEMM_SMEM1>>>(
        xsh, nullptr, wqh, nullptr, nullptr, nullptr, qsh, qsl, nullptr, NKT, 0, 0, 0, 3 * CC);

    // 5) attention: QK 1-term, PV 2-term, prefetched fp16 gate -> O hi tiles
    attn_mma<<<dim3(NN / 128, HH, BB), 256, ATT_SMEM>>>();

    // 6) output projection (fp16 2-term)
    gemm_mma<2, false, true, false, false><<<dim3(CC / 128, M / 128, 1), 256, GEMM_SMEM2>>>(
        osh, nullptr, wph, wpl, proj_b, out, nullptr, nullptr, nullptr, NKT, 0, 0, 0, CC);
}

// round 14
// speedup vs baseline: 1.3195x; 1.0639x over previous
#include <cuda_runtime.h>
#include <cuda_fp16.h>
#include <cstdint>
#include <math.h>

// Problem constants
#define BB 4
#define NN 2048
#define CC 512
#define HH 8
#define DH 64
#define GROUPS 8

// ===========================================================================
// Scratch (__device__ globals; alloc-free rule)
// ===========================================================================
__device__ float g_P1[BB * NN * CC];
__device__ float g_P2[BB * NN * CC];
__device__ __half g_PEh[(size_t)BB * NN * NN];  // 0.125 * sigmoid(...), fp16
__device__ float g_gnstat1[BB * GROUPS * 2];    // (sum, sumsq) per (b,g)
__device__ float g_gnstat2[BB * GROUPS * 2];

// fp16 split operands, tiled SW128 layout (tile = 128 rows x 64 f16 = 16KB)
#define TILE_BYTES 16384
__device__ char g_xs_hi[8192 * 1024];
__device__ char g_pes_hi[8192 * 1024], g_pes_lo[8192 * 1024];
__device__ char g_p1s_hi[8192 * 1024];
__device__ char g_p2s_hi[8192 * 1024];
__device__ char g_os_hi[8192 * 1024];
__device__ char g_wqkv_hi[1536 * 1024];
__device__ char g_wc1_hi[512 * 1024],  g_wc1_lo[512 * 1024];
__device__ char g_wc2_hi[512 * 1024],  g_wc2_lo[512 * 1024];
__device__ char g_wpj_hi[512 * 1024],  g_wpj_lo[512 * 1024];
// QKV in split-tile form: 64 row-tiles x 24 col-tiles x 16KB
__device__ char g_qkvs_hi[64 * 24 * TILE_BYTES];
__device__ char g_qkvs_lo[64 * 24 * TILE_BYTES];   // only V-lo tiles used

// ===========================================================================
// Helpers
// ===========================================================================
__device__ __forceinline__ uint32_t smem_to_u32(const void* p) {
    uint32_t a;
    asm("{ .reg .u64 t; cvta.to.shared.u64 t, %1; cvt.u32.u64 %0, t; }"
        : "=r"(a) : "l"(p));
    return a;
}

__device__ __forceinline__ void cpa16(uint32_t s, const void* g) {
    asm volatile("cp.async.cg.shared.global [%0], [%1], 16;" :: "r"(s), "l"(g));
}

__device__ __forceinline__ void ldm_x4(uint32_t* r, uint32_t addr) {
    asm volatile("ldmatrix.sync.aligned.m8n8.x4.shared.b16 {%0,%1,%2,%3}, [%4];"
        : "=r"(r[0]), "=r"(r[1]), "=r"(r[2]), "=r"(r[3]) : "r"(addr));
}

__device__ __forceinline__ void ldm_x4_t(uint32_t* r, uint32_t addr) {
    asm volatile("ldmatrix.sync.aligned.m8n8.x4.trans.shared.b16 {%0,%1,%2,%3}, [%4];"
        : "=r"(r[0]), "=r"(r[1]), "=r"(r[2]), "=r"(r[3]) : "r"(addr));
}

__device__ __forceinline__ void mma_f16(float* d, const uint32_t* a,
                                        const uint32_t* b) {
    asm volatile(
        "mma.sync.aligned.m16n8k16.row.col.f32.f16.f16.f32 "
        "{%0,%1,%2,%3}, {%4,%5,%6,%7}, {%8,%9}, {%0,%1,%2,%3};"
        : "+f"(d[0]), "+f"(d[1]), "+f"(d[2]), "+f"(d[3])
        : "r"(a[0]), "r"(a[1]), "r"(a[2]), "r"(a[3]), "r"(b[0]), "r"(b[1]));
}

// pack (lo, hi) floats -> f16x2 reg (lo in low 16 bits)
__device__ __forceinline__ uint32_t packh(float lo, float hi) {
    uint32_t d;
    asm("cvt.rn.f16x2.f32 %0, %1, %2;" : "=r"(d) : "f"(hi), "f"(lo));
    return d;
}

// ===========================================================================
// Split fp32 -> (f16 hi, f16 lo) into tiled SW128-swizzled layout.
// ===========================================================================
template <bool WLO>
__global__ void __launch_bounds__(256) split_f16_kernel(
    const float* __restrict__ X, char* __restrict__ Hi, char* __restrict__ Lo,
    int K, int total8)
{
    int idx = blockIdx.x * 256 + threadIdx.x;
    if (idx >= total8) return;
    int perRow = K >> 3;
    int r = idx / perRow;
    int c = (idx % perRow) << 3;

    float4 v0 = *(const float4*)(X + (size_t)r * K + c);
    float4 v1 = *(const float4*)(X + (size_t)r * K + c + 4);
    float vin[8] = {v0.x, v0.y, v0.z, v0.w, v1.x, v1.y, v1.z, v1.w};

    uint32_t hw[4], lw[4];
#pragma unroll
    for (int i = 0; i < 4; i++) {
        __half h0 = __float2half(vin[2 * i]);
        __half h1 = __float2half(vin[2 * i + 1]);
        __half2 hp = {h0, h1};
        hw[i] = *reinterpret_cast<uint32_t*>(&hp);
        if (WLO) {
            float l0 = vin[2 * i] - __half2float(h0);
            float l1 = vin[2 * i + 1] - __half2float(h1);
            lw[i] = packh(l0, l1);
        }
    }

    int rt = r >> 7, rr = r & 127;
    int kt = c >> 6, cc = c & 63;
    int tile = rt * (K >> 6) + kt;
    uint32_t inTile = rr * 128 + cc * 2;
    uint32_t sw = inTile ^ ((inTile >> 3) & 0x70);
    size_t off = (size_t)tile * TILE_BYTES + sw;
    *(uint4*)(Hi + off) = make_uint4(hw[0], hw[1], hw[2], hw[3]);
    if (WLO) *(uint4*)(Lo + off) = make_uint4(lw[0], lw[1], lw[2], lw[3]);
}

// ===========================================================================
// Zero GN stat accumulators
// ===========================================================================
__global__ void gn_zero_kernel()
{
    if (threadIdx.x < BB * GROUPS * 2) {
        g_gnstat1[threadIdx.x] = 0.f;
        g_gnstat2[threadIdx.x] = 0.f;
    }
}

// ===========================================================================
// fp16 split GEMM-NT via mma.sync.
// TERMS=1: ah*bh. TERMS=2: + ah*bl. TERMS=3: + al*bh.
// SIG: writes fp16 gate (0.125*sigmoid) into C interpreted as __half*.
// GNSTAT: epilogue accumulates (sum, sumsq) per (b, group) via atomics.
// ===========================================================================
template <int TERMS, bool SIG, bool BIAS, bool SPLIT, bool GNSTAT>
__global__ void __launch_bounds__(256) gemm_mma(
    const char* __restrict__ Ahi, const char* __restrict__ Alo,
    const char* __restrict__ Bhi, const char* __restrict__ Blo,
    const float* __restrict__ bias, void* __restrict__ C,
    char* __restrict__ Chi, char* __restrict__ Clo,
    float* __restrict__ stats,
    int numKt, int aBatchTiles, int bBatchTiles, long long cBatchStride, int ldc)
{
    constexpr int NTILES = TERMS + 1;
    constexpr uint32_t STB = NTILES * TILE_BYTES;

    extern __shared__ __align__(128) char smem[];
    uint32_t smem_base = smem_to_u32(smem);
    const int tid = threadIdx.x;
    const int wid = tid >> 5;
    const int lane = tid & 31;
    const int wm = wid & 1;
    const int wn = wid >> 1;

    const long long aTileBase = (long long)blockIdx.z * aBatchTiles + (long long)blockIdx.y * numKt;
    const long long bTileBase = (long long)blockIdx.z * bBatchTiles + (long long)blockIdx.x * numKt;

    auto issue_loads = [&](int kt, int stage) {
        const char* srcs[4];
        srcs[0] = Ahi + (aTileBase + kt) * TILE_BYTES;
        srcs[1] = Bhi + (bTileBase + kt) * TILE_BYTES;
        if (TERMS >= 2) srcs[2] = Blo + (bTileBase + kt) * TILE_BYTES;
        if (TERMS == 3) srcs[3] = Alo + (aTileBase + kt) * TILE_BYTES;
        uint32_t sb = smem_base + stage * STB;
#pragma unroll
        for (int t = 0; t < NTILES; t++)
#pragma unroll
            for (int i = 0; i < 4; i++) {
                uint32_t o = t * TILE_BYTES + i * 4096 + tid * 16;
                cpa16(sb + o, srcs[t] + i * 4096 + tid * 16);
            }
        asm volatile("cp.async.commit_group;" ::: "memory");
    };

    const int aRowBase = wm * 64 + (lane & 15);
    const uint32_t aKadd = (lane >> 4) * 16;
    const int bRowBase = wn * 32 + ((lane >> 4) << 3) + (lane & 7);
    const uint32_t bKadd = ((lane >> 3) & 1) * 16;

    float acc[4][4][4];
#pragma unroll
    for (int mt = 0; mt < 4; mt++)
#pragma unroll
        for (int nt = 0; nt < 4; nt++)
#pragma unroll
            for (int f = 0; f < 4; f++) acc[mt][nt][f] = 0.f;

    issue_loads(0, 0);

    for (int c = 0; c < numKt; c++) {
        const int buf = c & 1;
        if (c + 1 < numKt) {
            issue_loads(c + 1, buf ^ 1);
            asm volatile("cp.async.wait_group 1;" ::: "memory");
        } else {
            asm volatile("cp.async.wait_group 0;" ::: "memory");
        }
        __syncthreads();

        const uint32_t sb = smem_base + buf * STB;
        const uint32_t aHiB = sb;
        const uint32_t bHiB = sb + TILE_BYTES;
        const uint32_t bLoB = sb + 2 * TILE_BYTES;
        const uint32_t aLoB = sb + 3 * TILE_BYTES;

#pragma unroll
        for (int ks = 0; ks < 4; ks++) {
            uint32_t ah[4][4], al[4][4];
#pragma unroll
            for (int mt = 0; mt < 4; mt++) {
                int row = aRowBase + mt * 16;
                uint32_t koff = (ks * 32 + aKadd) ^ ((row & 7) << 4);
                uint32_t off = (uint32_t)row * 128 + koff;
                ldm_x4(ah[mt], aHiB + off);
                if (TERMS == 3) ldm_x4(al[mt], aLoB + off);
            }
            uint32_t bh[2][4], bl[2][4];
#pragma unroll
            for (int np = 0; np < 2; np++) {
                int row = bRowBase + np * 16;
                uint32_t koff = (ks * 32 + bKadd) ^ ((row & 7) << 4);
                uint32_t off = (uint32_t)row * 128 + koff;
                ldm_x4(bh[np], bHiB + off);
                if (TERMS >= 2) ldm_x4(bl[np], bLoB + off);
            }
#pragma unroll
            for (int mt = 0; mt < 4; mt++)
#pragma unroll
                for (int nt = 0; nt < 4; nt++) {
                    const uint32_t* bhp = &bh[nt >> 1][(nt & 1) * 2];
                    mma_f16(acc[mt][nt], ah[mt], bhp);
                    if (TERMS >= 2) {
                        const uint32_t* blp = &bl[nt >> 1][(nt & 1) * 2];
                        mma_f16(acc[mt][nt], ah[mt], blp);
                    }
                    if (TERMS == 3) mma_f16(acc[mt][nt], al[mt], bhp);
                }
        }
        __syncthreads();
    }

    // Epilogue
    const int g = lane >> 2, tg = lane & 3;
    float ls = 0.f, lsq = 0.f;
    if (SPLIT) {
        const int tilesPerRow = ldc >> 6;
#pragma unroll
        for (int mt = 0; mt < 4; mt++) {
            const int row0 = blockIdx.y * 128 + wm * 64 + mt * 16 + g;
#pragma unroll
            for (int nt = 0; nt < 4; nt++) {
                const int col = blockIdx.x * 128 + wn * 32 + nt * 8 + tg * 2;
                const int tile = (row0 >> 7) * tilesPerRow + (col >> 6);
#pragma unroll
                for (int half = 0; half < 2; half++) {
                    const int rowIn = (row0 & 127) + half * 8;
                    float v0 = acc[mt][nt][half * 2 + 0];
                    float v1 = acc[mt][nt][half * 2 + 1];
                    __half h0 = __float2half(v0);
                    __half h1 = __float2half(v1);
                    float l0 = v0 - __half2float(h0);
                    float l1 = v1 - __half2float(h1);
                    __half2 hp = {h0, h1};
                    uint32_t inoff = rowIn * 128 + (col & 63) * 2;
                    uint32_t sw = inoff ^ ((inoff >> 3) & 0x70);
                    *(uint32_t*)(Chi + (size_t)tile * TILE_BYTES + sw) =
                        *reinterpret_cast<uint32_t*>(&hp);
                    *(uint32_t*)(Clo + (size_t)tile * TILE_BYTES + sw) = packh(l0, l1);
                }
            }
        }
    } else if (SIG) {
        __half* Gbase = (__half*)C + (long long)blockIdx.z * cBatchStride;
#pragma unroll
        for (int mt = 0; mt < 4; mt++) {
            const int row0 = blockIdx.y * 128 + wm * 64 + mt * 16 + g;
#pragma unroll
            for (int nt = 0; nt < 4; nt++) {
                const int col = blockIdx.x * 128 + wn * 32 + nt * 8 + tg * 2;
#pragma unroll
                for (int half = 0; half < 2; half++) {
                    float v0 = 0.125f / (1.f + __expf(-acc[mt][nt][half * 2 + 0]));
                    float v1 = 0.125f / (1.f + __expf(-acc[mt][nt][half * 2 + 1]));
                    *(uint32_t*)(Gbase + (long long)(row0 + half * 8) * ldc + col) =
                        packh(v0, v1);
                }
            }
        }
    } else {
        float* Cbase = (float*)C + (long long)blockIdx.z * cBatchStride;
#pragma unroll
        for (int mt = 0; mt < 4; mt++) {
            const int row0 = blockIdx.y * 128 + wm * 64 + mt * 16 + g;
#pragma unroll
            for (int nt = 0; nt < 4; nt++) {
                const int col = blockIdx.x * 128 + wn * 32 + nt * 8 + tg * 2;
                float b0 = 0.f, b1 = 0.f;
                if (BIAS) { b0 = bias[col]; b1 = bias[col + 1]; }
#pragma unroll
                for (int half = 0; half < 2; half++) {
                    float v0 = acc[mt][nt][half * 2 + 0] + b0;
                    float v1 = acc[mt][nt][half * 2 + 1] + b1;
                    if (GNSTAT) {
                        ls += v0 + v1;
                        lsq += v0 * v0 + v1 * v1;
                    }
                    *(float2*)(Cbase + (long long)(row0 + half * 8) * ldc + col) =
                        make_float2(v0, v1);
                }
            }
        }
        if (GNSTAT) {
#pragma unroll
            for (int off = 16; off > 0; off >>= 1) {
                ls  += __shfl_xor_sync(0xffffffffu, ls, off);
                lsq += __shfl_xor_sync(0xffffffffu, lsq, off);
            }
            if (lane == 0) {
                const int b = blockIdx.y >> 4;
                const int grp = blockIdx.x * 2 + (wn >> 1);
                atomicAdd(&stats[(b * GROUPS + grp) * 2 + 0], ls);
                atomicAdd(&stats[(b * GROUPS + grp) * 2 + 1], lsq);
            }
        }
    }
}

// ===========================================================================
// GN apply: normalize P (fp32) using precomputed stats and write f16 hi
// SW128 split tiles (both P1, P2 hi-only: gate GEMM is 1-term).
// ===========================================================================
__global__ void __launch_bounds__(256) gn_apply_kernel(
    const float* __restrict__ g1, const float* __restrict__ b1,
    const float* __restrict__ g2, const float* __restrict__ b2,
    char* __restrict__ p1Hi, char* __restrict__ p2Hi)
{
    const int which = blockIdx.y;
    const float* P = which == 0 ? g_P1 : g_P2;
    const float* st = which == 0 ? g_gnstat1 : g_gnstat2;
    const float* gamma = which == 0 ? g1 : g2;
    const float* beta  = which == 0 ? b1 : b2;
    char* Hi = which == 0 ? p1Hi : p2Hi;

    const int idx = blockIdx.x * 256 + threadIdx.x;
    const int r = idx >> 6;
    const int c = (idx & 63) << 3;
    const int b = r >> 11;
    const int grp = c >> 6;
    const float CNT = (float)((CC / GROUPS) * NN);

    const float s = st[(b * GROUPS + grp) * 2 + 0];
    const float sq = st[(b * GROUPS + grp) * 2 + 1];
    const float mean = s / CNT;
    const float var = sq / CNT - mean * mean;
    const float rstd = rsqrtf(var + 1e-5f);

    float4 v0 = *(const float4*)(P + (size_t)r * CC + c);
    float4 v1 = *(const float4*)(P + (size_t)r * CC + c + 4);
    float vin[8] = {v0.x, v0.y, v0.z, v0.w, v1.x, v1.y, v1.z, v1.w};
    float4 gm0 = *(const float4*)(gamma + c);
    float4 gm1 = *(const float4*)(gamma + c + 4);
    float4 bt0 = *(const float4*)(beta + c);
    float4 bt1 = *(const float4*)(beta + c + 4);
    float gm[8] = {gm0.x, gm0.y, gm0.z, gm0.w, gm1.x, gm1.y, gm1.z, gm1.w};
    float bt[8] = {bt0.x, bt0.y, bt0.z, bt0.w, bt1.x, bt1.y, bt1.z, bt1.w};

    uint32_t hw[4];
#pragma unroll
    for (int i = 0; i < 4; i++) {
        float a0 = (vin[2 * i] - mean) * rstd * gm[2 * i] + bt[2 * i];
        float a1 = (vin[2 * i + 1] - mean) * rstd * gm[2 * i + 1] + bt[2 * i + 1];
        hw[i] = packh(a0, a1);
    }

    const int tile = (r >> 7) * 8 + grp;
    uint32_t inTile = (uint32_t)(r & 127) * 128 + (c & 63) * 2;
    uint32_t sw = inTile ^ ((inTile >> 3) & 0x70);
    size_t off = (size_t)tile * TILE_BYTES + sw;
    *(uint4*)(Hi + off) = make_uint4(hw[0], hw[1], hw[2], hw[3]);
}

// ===========================================================================
// Tensor-core flash attention with fp16 PE gate, register-prefetched.
// S = Qh*Kh (1-term), O += Ph*(Vh+Vl) (2-term). Grid (N/128, H, B); 8 warps.
// ===========================================================================
#define ATT_STAGE 24576
#define ATT_SMEM (16384 + 2 * ATT_STAGE)   // Q hi + 2 KV stages = 64KB

__global__ void __launch_bounds__(256) attn_mma()
{
    extern __shared__ __align__(128) char smem[];
    const uint32_t sb = smem_to_u32(smem);
    const uint32_t qh_base = sb;
    const uint32_t stage0 = sb + 16384;

    const int tid = threadIdx.x, wid = tid >> 5, lane = tid & 31;
    const int q0 = blockIdx.x * 128, h = blockIdx.y, b = blockIdx.z;
    const int g = lane >> 2, tg = lane & 3;

    const int rtQ = (b * NN + q0) >> 7;
    {
        const char* qsh = g_qkvs_hi + (size_t)(rtQ * 24 + h) * TILE_BYTES;
#pragma unroll
        for (int i = 0; i < 4; i++)
            cpa16(qh_base + i * 4096 + tid * 16, qsh + i * 4096 + tid * 16);
        asm volatile("cp.async.commit_group;" ::: "memory");
    }

    auto issue_kv = [&](int t, int stg) {
        const int kRow = t * 64;
        const int rt = (b * NN + kRow) >> 7;
        const int halfOff = (kRow & 64) ? 8192 : 0;
        const char* kh = g_qkvs_hi + (size_t)(rt * 24 + 8 + h) * TILE_BYTES + halfOff;
        const char* vh = g_qkvs_hi + (size_t)(rt * 24 + 16 + h) * TILE_BYTES + halfOff;
        const char* vl = g_qkvs_lo + (size_t)(rt * 24 + 16 + h) * TILE_BYTES + halfOff;
        uint32_t s = stage0 + stg * ATT_STAGE;
#pragma unroll
        for (int i = 0; i < 2; i++) {
            uint32_t o = i * 4096 + tid * 16;
            cpa16(s + o,         kh + o);
            cpa16(s + 8192 + o,  vh + o);
            cpa16(s + 16384 + o, vl + o);
        }
        asm volatile("cp.async.commit_group;" ::: "memory");
    };

    issue_kv(0, 0);
    asm volatile("cp.async.wait_group 1;" ::: "memory");  // Q arrived
    __syncthreads();

    // Q fragments (hi only, resident)
    uint32_t qfh[4][4];
    {
        const int row = wid * 16 + (lane & 15);
        const uint32_t roff = (uint32_t)row * 128;
#pragma unroll
        for (int ks = 0; ks < 4; ks++) {
            uint32_t colb = (lane >> 4) * 16 + ks * 32;
            uint32_t a = roff + (colb ^ ((row & 7) << 4));
            ldm_x4(qfh[ks], qh_base + a);
        }
    }

    float Oa[8][4];
#pragma unroll
    for (int nt = 0; nt < 8; nt++)
#pragma unroll
        for (int f = 0; f < 4; f++) Oa[nt][f] = 0.f;
    float mrow[2] = {-1e30f, -1e30f}, lrow[2] = {0.f, 0.f};

    const size_t peBase = (size_t)b * NN * NN;
    const int qRow0 = q0 + wid * 16 + g;
    const int bRow0 = ((lane >> 4) << 3) + (lane & 7);
    const uint32_t bKadd = ((lane >> 3) & 1) * 16;

    for (int t = 0; t < NN / 64; t++) {
        const int buf = t & 1;
        const int k0 = t * 64;

        // Prefetch fp16 PE gate words before the QK MMAs (latency overlap).
        uint32_t peReg[16];
#pragma unroll
        for (int nt = 0; nt < 8; nt++)
#pragma unroll
            for (int r = 0; r < 2; r++)
                peReg[nt * 2 + r] = *(const uint32_t*)&g_PEh[
                    peBase + (size_t)(qRow0 + r * 8) * NN + k0 + nt * 8 + tg * 2];

        if (t + 1 < NN / 64) {
            issue_kv(t + 1, buf ^ 1);
            asm volatile("cp.async.wait_group 1;" ::: "memory");
        } else {
            asm volatile("cp.async.wait_group 0;" ::: "memory");
        }
        __syncthreads();

        const uint32_t kb = stage0 + buf * ATT_STAGE;
        const uint32_t kh_b = kb;
        const uint32_t vh_b = kb + 8192, vl_b = kb + 16384;

        // S = Q K^T (fp16 1-term)
        float S[8][4];
#pragma unroll
        for (int nt = 0; nt < 8; nt++)
#pragma unroll
            for (int f = 0; f < 4; f++) S[nt][f] = 0.f;

#pragma unroll
        for (int ks = 0; ks < 4; ks++) {
#pragma unroll
            for (int np = 0; np < 4; np++) {
                const int row = bRow0 + np * 16;
                const uint32_t a = (uint32_t)row * 128 +
                                   ((ks * 32 + bKadd) ^ ((row & 7) << 4));
                uint32_t KH[4];
                ldm_x4(KH, kh_b + a);
#pragma unroll
                for (int hn = 0; hn < 2; hn++)
                    mma_f16(S[np * 2 + hn], qfh[ks], &KH[hn * 2]);
            }
        }

        // gate with prefetched fp16 PE (0.125 pre-folded)
#pragma unroll
        for (int nt = 0; nt < 8; nt++) {
#pragma unroll
            for (int r = 0; r < 2; r++) {
                const float2 pe = __half22float2(
                    *reinterpret_cast<const __half2*>(&peReg[nt * 2 + r]));
                S[nt][r * 2 + 0] *= pe.x;
                S[nt][r * 2 + 1] *= pe.y;
            }
        }

        // online softmax
        float corr[2];
#pragma unroll
        for (int r = 0; r < 2; r++) {
            float vm = -1e30f;
#pragma unroll
            for (int nt = 0; nt < 8; nt++)
                vm = fmaxf(vm, fmaxf(S[nt][r * 2], S[nt][r * 2 + 1]));
            vm = fmaxf(vm, __shfl_xor_sync(0xffffffffu, vm, 1));
            vm = fmaxf(vm, __shfl_xor_sync(0xffffffffu, vm, 2));
            const float mn = fmaxf(mrow[r], vm);
            corr[r] = __expf(mrow[r] - mn);
            mrow[r] = mn;
            float rsum = 0.f;
#pragma unroll
            for (int nt = 0; nt < 8; nt++) {
                float p0 = __expf(S[nt][r * 2] - mn);
                float p1 = __expf(S[nt][r * 2 + 1] - mn);
                S[nt][r * 2] = p0;
                S[nt][r * 2 + 1] = p1;
                rsum += p0 + p1;
            }
            rsum += __shfl_xor_sync(0xffffffffu, rsum, 1);
            rsum += __shfl_xor_sync(0xffffffffu, rsum, 2);
            lrow[r] = lrow[r] * corr[r] + rsum;
        }
#pragma unroll
        for (int nt = 0; nt < 8; nt++) {
            Oa[nt][0] *= corr[0]; Oa[nt][1] *= corr[0];
            Oa[nt][2] *= corr[1]; Oa[nt][3] *= corr[1];
        }

        // O += P V (fp16 2-term); P hi fragments from S accumulators
#pragma unroll
        for (int ks = 0; ks < 4; ks++) {
            uint32_t ah[4];
#pragma unroll
            for (int q = 0; q < 2; q++) {
                const float* sv = S[2 * ks + q];
                ah[q * 2 + 0] = packh(sv[0], sv[1]);
                ah[q * 2 + 1] = packh(sv[2], sv[3]);
            }
#pragma unroll
            for (int dp = 0; dp < 4; dp++) {
                const int row = ks * 16 + (lane & 15);
                const uint32_t a = (uint32_t)row * 128 +
                    ((dp * 32 + (lane >> 4) * 16) ^ ((row & 7) << 4));
                uint32_t VH[4], VL[4];
                ldm_x4_t(VH, vh_b + a);
                ldm_x4_t(VL, vl_b + a);
#pragma unroll
                for (int hn = 0; hn < 2; hn++) {
                    const int nt = dp * 2 + hn;
                    mma_f16(Oa[nt], ah, &VH[hn * 2]);
                    mma_f16(Oa[nt], ah, &VL[hn * 2]);
                }
            }
        }
        __syncthreads();
    }

    // Epilogue: normalize and write hi tiles for proj GEMM (O is A operand)
    const float inv[2] = {1.f / lrow[0], 1.f / lrow[1]};
    char* osh = g_os_hi + (size_t)(rtQ * 8 + h) * TILE_BYTES;
#pragma unroll
    for (int nt = 0; nt < 8; nt++) {
#pragma unroll
        for (int r = 0; r < 2; r++) {
            const float v0 = Oa[nt][r * 2 + 0] * inv[r];
            const float v1 = Oa[nt][r * 2 + 1] * inv[r];
            const int rowIn = wid * 16 + g + r * 8;
            const uint32_t inoff = (uint32_t)rowIn * 128 + nt * 16 + tg * 4;
            const uint32_t sw = inoff ^ ((inoff >> 3) & 0x70);
            *(uint32_t*)(osh + sw) = packh(v0, v1);
        }
    }
}

// ===========================================================================

static void split(const void* X, void* Hi, void* Lo, int K, int rows, bool wlo)
{
    int total8 = rows * K / 8;
    if (wlo)
        split_f16_kernel<true><<<(total8 + 255) / 256, 256>>>(
            (const float*)X, (char*)Hi, (char*)Lo, K, total8);
    else
        split_f16_kernel<false><<<(total8 + 255) / 256, 256>>>(
            (const float*)X, (char*)Hi, nullptr, K, total8);
}

#define GEMM_SMEM1 (2 * 2 * TILE_BYTES)   // 64KB
#define GEMM_SMEM2 (2 * 3 * TILE_BYTES)   // 96KB
#define GEMM_SMEM3 (2 * 4 * TILE_BYTES)   // 128KB

extern "C" void kernel_launch(void* const* d_in, const int* in_sizes, int n_in,
                              void* d_out, int out_size)
{
    const float* x       = (const float*)d_in[0];
    const float* pe      = (const float*)d_in[1];
    const float* qkv_w   = (const float*)d_in[2];
    const float* proj_w  = (const float*)d_in[3];
    const float* proj_b  = (const float*)d_in[4];
    const float* conv1_w = (const float*)d_in[5];
    const float* conv1_b = (const float*)d_in[6];
    const float* gn1_g   = (const float*)d_in[7];
    const float* gn1_b   = (const float*)d_in[8];
    const float* conv2_w = (const float*)d_in[9];
    const float* conv2_b = (const float*)d_in[10];
    const float* gn2_g   = (const float*)d_in[11];
    const float* gn2_b   = (const float*)d_in[12];
    float* out = (float*)d_out;

    float *p1, *p2, *st1, *st2;
    void* pehRaw;
    cudaGetSymbolAddress((void**)&p1, g_P1);
    cudaGetSymbolAddress((void**)&p2, g_P2);
    cudaGetSymbolAddress(&pehRaw, g_PEh);
    cudaGetSymbolAddress((void**)&st1, g_gnstat1);
    cudaGetSymbolAddress((void**)&st2, g_gnstat2);

    char *xsh, *pesh, *pesl, *p1h, *p2h, *osh;
    char *wqh, *w1h, *w1l, *w2h, *w2l, *wph, *wpl, *qsh, *qsl;
    cudaGetSymbolAddress((void**)&xsh, g_xs_hi);
    cudaGetSymbolAddress((void**)&pesh, g_pes_hi); cudaGetSymbolAddress((void**)&pesl, g_pes_lo);
    cudaGetSymbolAddress((void**)&p1h, g_p1s_hi);
    cudaGetSymbolAddress((void**)&p2h, g_p2s_hi);
    cudaGetSymbolAddress((void**)&osh, g_os_hi);
    cudaGetSymbolAddress((void**)&wqh, g_wqkv_hi);
    cudaGetSymbolAddress((void**)&w1h, g_wc1_hi);  cudaGetSymbolAddress((void**)&w1l, g_wc1_lo);
    cudaGetSymbolAddress((void**)&w2h, g_wc2_hi);  cudaGetSymbolAddress((void**)&w2l, g_wc2_lo);
    cudaGetSymbolAddress((void**)&wph, g_wpj_hi);  cudaGetSymbolAddress((void**)&wpl, g_wpj_lo);
    cudaGetSymbolAddress((void**)&qsh, g_qkvs_hi); cudaGetSymbolAddress((void**)&qsl, g_qkvs_lo);

    static bool attrSet = false;
    if (!attrSet) {
        cudaFuncSetAttribute(gemm_mma<3, false, true, false, true>,   cudaFuncAttributeMaxDynamicSharedMemorySize, GEMM_SMEM3);
        cudaFuncSetAttribute(gemm_mma<1, true, false, false, false>,  cudaFuncAttributeMaxDynamicSharedMemorySize, GEMM_SMEM1);
        cudaFuncSetAttribute(gemm_mma<1, false, false, true, false>,  cudaFuncAttributeMaxDynamicSharedMemorySize, GEMM_SMEM1);
        cudaFuncSetAttribute(gemm_mma<2, false, true, false, false>,  cudaFuncAttributeMaxDynamicSharedMemorySize, GEMM_SMEM2);
        cudaFuncSetAttribute(attn_mma, cudaFuncAttributeMaxDynamicSharedMemorySize, ATT_SMEM);
        attrSet = true;
    }

    const int M = BB * NN;       // 8192
    const int NKT = CC / 64;     // 8

    // 0) zero GN stats + split conversions
    gn_zero_kernel<<<1, 128>>>();
    split(pe, pesh, pesl, CC, M, true);             // A of conv (3-term)
    split(x, xsh, nullptr, CC, M, false);           // A of QKV (1-term)
    split(qkv_w, wqh, nullptr, CC, 3 * CC, false);  // B of QKV (1-term)
    split(conv1_w, w1h, w1l, CC, CC, true);         // B of conv (3-term)
    split(conv2_w, w2h, w2l, CC, CC, true);
    split(proj_w, wph, wpl, CC, CC, true);          // B of proj (2-term)

    // 1) conv1 / conv2 -> P1, P2 (fp32) + GN stats (fp16 3-term)
    gemm_mma<3, false, true, false, true><<<dim3(CC / 128, M / 128, 1), 256, GEMM_SMEM3>>>(
        pesh, pesl, w1h, w1l, conv1_b, p1, nullptr, nullptr, st1, NKT, 0, 0, 0, CC);
    gemm_mma<3, false, true, false, true><<<dim3(CC / 128, M / 128, 1), 256, GEMM_SMEM3>>>(
        pesh, pesl, w2h, w2l, conv2_b, p2, nullptr, nullptr, st2, NKT, 0, 0, 0, CC);

    // 2) GN apply -> writes P1 / P2 hi tiles
    gn_apply_kernel<<<dim3(2048, 2), 256>>>(
        gn1_g, gn1_b, gn2_g, gn2_b, p1h, p2h);

    // 3) PE gate: 0.125 * sigmoid(P1 @ P2^T) -> fp16 gate  (fp16 1-term)
    gemm_mma<1, true, false, false, false><<<dim3(NN / 128, NN / 128, BB), 256, GEMM_SMEM1>>>(
        p1h, nullptr, p2h, nullptr, nullptr, pehRaw, nullptr, nullptr, nullptr, NKT,
        (NN / 128) * NKT, (NN / 128) * NKT, (long long)NN * NN, NN);

    // 4) QKV projection -> split tiles (fp16 1-term; epilogue writes hi+lo)
    gemm_mma<1, false, false, true, false><<<dim3(3 * CC / 128, M / 128, 1), 256, GEMM_SMEM1>>>(
        xsh, nullptr, wqh, nullptr, nullptr, nullptr, qsh, qsl, nullptr, NKT, 0, 0, 0, 3 * CC);

    // 5) attention: QK 1-term, PV 2-term, prefetched fp16 gate -> O hi tiles
    attn_mma<<<dim3(NN / 128, HH, BB), 256, ATT_SMEM>>>();

    // 6) output projection (fp16 2-term)
    gemm_mma<2, false, true, false, false><<<dim3(CC / 128, M / 128, 1), 256, GEMM_SMEM2>>>(
        osh, nullptr, wph, wpl, proj_b, out, nullptr, nullptr, nullptr, NKT, 0, 0, 0, CC);
}

// round 15
// speedup vs baseline: 1.3566x; 1.0281x over previous
#include <cuda_runtime.h>
#include <cuda_fp16.h>
#include <cstdint>
#include <math.h>

// Problem constants
#define BB 4
#define NN 2048
#define CC 512
#define HH 8
#define DH 64
#define GROUPS 8

// ===========================================================================
// Scratch (__device__ globals; alloc-free rule)
// ===========================================================================
__device__ float g_P1[BB * NN * CC];
__device__ float g_P2[BB * NN * CC];
__device__ __half g_PEh[(size_t)BB * NN * NN];  // 0.125 * sigmoid(...), fp16
__device__ float g_gnstat1[BB * GROUPS * 2];    // (sum, sumsq) per (b,g)
__device__ float g_gnstat2[BB * GROUPS * 2];

// fp16 split operands, tiled SW128 layout (tile = 128 rows x 64 f16 = 16KB)
#define TILE_BYTES 16384
__device__ char g_xs_hi[8192 * 1024];
__device__ char g_pes_hi[8192 * 1024], g_pes_lo[8192 * 1024];
__device__ char g_p1s_hi[8192 * 1024];
__device__ char g_p2s_hi[8192 * 1024];
__device__ char g_os_hi[8192 * 1024];
__device__ char g_wqkv_hi[1536 * 1024];
__device__ char g_wc1_hi[512 * 1024],  g_wc1_lo[512 * 1024];
__device__ char g_wc2_hi[512 * 1024],  g_wc2_lo[512 * 1024];
__device__ char g_wpj_hi[512 * 1024],  g_wpj_lo[512 * 1024];
// QKV in split-tile form: 64 row-tiles x 24 col-tiles x 16KB
__device__ char g_qkvs_hi[64 * 24 * TILE_BYTES];
__device__ char g_qkvs_lo[64 * 24 * TILE_BYTES];   // only V-lo tiles used

// ===========================================================================
// Helpers
// ===========================================================================
__device__ __forceinline__ uint32_t smem_to_u32(const void* p) {
    uint32_t a;
    asm("{ .reg .u64 t; cvta.to.shared.u64 t, %1; cvt.u32.u64 %0, t; }"
        : "=r"(a) : "l"(p));
    return a;
}

__device__ __forceinline__ void cpa16(uint32_t s, const void* g) {
    asm volatile("cp.async.cg.shared.global [%0], [%1], 16;" :: "r"(s), "l"(g));
}

__device__ __forceinline__ void ldm_x4(uint32_t* r, uint32_t addr) {
    asm volatile("ldmatrix.sync.aligned.m8n8.x4.shared.b16 {%0,%1,%2,%3}, [%4];"
        : "=r"(r[0]), "=r"(r[1]), "=r"(r[2]), "=r"(r[3]) : "r"(addr));
}

__device__ __forceinline__ void ldm_x4_t(uint32_t* r, uint32_t addr) {
    asm volatile("ldmatrix.sync.aligned.m8n8.x4.trans.shared.b16 {%0,%1,%2,%3}, [%4];"
        : "=r"(r[0]), "=r"(r[1]), "=r"(r[2]), "=r"(r[3]) : "r"(addr));
}

__device__ __forceinline__ void mma_f16(float* d, const uint32_t* a,
                                        const uint32_t* b) {
    asm volatile(
        "mma.sync.aligned.m16n8k16.row.col.f32.f16.f16.f32 "
        "{%0,%1,%2,%3}, {%4,%5,%6,%7}, {%8,%9}, {%0,%1,%2,%3};"
        : "+f"(d[0]), "+f"(d[1]), "+f"(d[2]), "+f"(d[3])
        : "r"(a[0]), "r"(a[1]), "r"(a[2]), "r"(a[3]), "r"(b[0]), "r"(b[1]));
}

// pack (lo, hi) floats -> f16x2 reg (lo in low 16 bits)
__device__ __forceinline__ uint32_t packh(float lo, float hi) {
    uint32_t d;
    asm("cvt.rn.f16x2.f32 %0, %1, %2;" : "=r"(d) : "f"(hi), "f"(lo));
    return d;
}

// ===========================================================================
// Split fp32 -> (f16 hi, f16 lo) into tiled SW128-swizzled layout.
// ===========================================================================
template <bool WLO>
__global__ void __launch_bounds__(256) split_f16_kernel(
    const float* __restrict__ X, char* __restrict__ Hi, char* __restrict__ Lo,
    int K, int total8)
{
    int idx = blockIdx.x * 256 + threadIdx.x;
    if (idx >= total8) return;
    int perRow = K >> 3;
    int r = idx / perRow;
    int c = (idx % perRow) << 3;

    float4 v0 = *(const float4*)(X + (size_t)r * K + c);
    float4 v1 = *(const float4*)(X + (size_t)r * K + c + 4);
    float vin[8] = {v0.x, v0.y, v0.z, v0.w, v1.x, v1.y, v1.z, v1.w};

    uint32_t hw[4], lw[4];
#pragma unroll
    for (int i = 0; i < 4; i++) {
        __half h0 = __float2half(vin[2 * i]);
        __half h1 = __float2half(vin[2 * i + 1]);
        __half2 hp = {h0, h1};
        hw[i] = *reinterpret_cast<uint32_t*>(&hp);
        if (WLO) {
            float l0 = vin[2 * i] - __half2float(h0);
            float l1 = vin[2 * i + 1] - __half2float(h1);
            lw[i] = packh(l0, l1);
        }
    }

    int rt = r >> 7, rr = r & 127;
    int kt = c >> 6, cc = c & 63;
    int tile = rt * (K >> 6) + kt;
    uint32_t inTile = rr * 128 + cc * 2;
    uint32_t sw = inTile ^ ((inTile >> 3) & 0x70);
    size_t off = (size_t)tile * TILE_BYTES + sw;
    *(uint4*)(Hi + off) = make_uint4(hw[0], hw[1], hw[2], hw[3]);
    if (WLO) *(uint4*)(Lo + off) = make_uint4(lw[0], lw[1], lw[2], lw[3]);
}

// ===========================================================================
// Zero GN stat accumulators
// ===========================================================================
__global__ void gn_zero_kernel()
{
    if (threadIdx.x < BB * GROUPS * 2) {
        g_gnstat1[threadIdx.x] = 0.f;
        g_gnstat2[threadIdx.x] = 0.f;
    }
}

// ===========================================================================
// fp16 split GEMM-NT via mma.sync.
// TERMS=1: ah*bh. TERMS=2: + ah*bl. TERMS=3: + al*bh.
// SIG: writes fp16 gate (0.125*sigmoid) into C interpreted as __half*.
// GNSTAT: epilogue accumulates (sum, sumsq) per (b, group) via atomics.
// ===========================================================================
template <int TERMS, bool SIG, bool BIAS, bool SPLIT, bool GNSTAT>
__global__ void __launch_bounds__(256) gemm_mma(
    const char* __restrict__ Ahi, const char* __restrict__ Alo,
    const char* __restrict__ Bhi, const char* __restrict__ Blo,
    const float* __restrict__ bias, void* __restrict__ C,
    char* __restrict__ Chi, char* __restrict__ Clo,
    float* __restrict__ stats,
    int numKt, int aBatchTiles, int bBatchTiles, long long cBatchStride, int ldc)
{
    constexpr int NTILES = TERMS + 1;
    constexpr uint32_t STB = NTILES * TILE_BYTES;

    extern __shared__ __align__(128) char smem[];
    uint32_t smem_base = smem_to_u32(smem);
    const int tid = threadIdx.x;
    const int wid = tid >> 5;
    const int lane = tid & 31;
    const int wm = wid & 1;
    const int wn = wid >> 1;

    const long long aTileBase = (long long)blockIdx.z * aBatchTiles + (long long)blockIdx.y * numKt;
    const long long bTileBase = (long long)blockIdx.z * bBatchTiles + (long long)blockIdx.x * numKt;

    auto issue_loads = [&](int kt, int stage) {
        const char* srcs[4];
        srcs[0] = Ahi + (aTileBase + kt) * TILE_BYTES;
        srcs[1] = Bhi + (bTileBase + kt) * TILE_BYTES;
        if (TERMS >= 2) srcs[2] = Blo + (bTileBase + kt) * TILE_BYTES;
        if (TERMS == 3) srcs[3] = Alo + (aTileBase + kt) * TILE_BYTES;
        uint32_t sb = smem_base + stage * STB;
#pragma unroll
        for (int t = 0; t < NTILES; t++)
#pragma unroll
            for (int i = 0; i < 4; i++) {
                uint32_t o = t * TILE_BYTES + i * 4096 + tid * 16;
                cpa16(sb + o, srcs[t] + i * 4096 + tid * 16);
            }
        asm volatile("cp.async.commit_group;" ::: "memory");
    };

    const int aRowBase = wm * 64 + (lane & 15);
    const uint32_t aKadd = (lane >> 4) * 16;
    const int bRowBase = wn * 32 + ((lane >> 4) << 3) + (lane & 7);
    const uint32_t bKadd = ((lane >> 3) & 1) * 16;

    float acc[4][4][4];
#pragma unroll
    for (int mt = 0; mt < 4; mt++)
#pragma unroll
        for (int nt = 0; nt < 4; nt++)
#pragma unroll
            for (int f = 0; f < 4; f++) acc[mt][nt][f] = 0.f;

    issue_loads(0, 0);

    for (int c = 0; c < numKt; c++) {
        const int buf = c & 1;
        if (c + 1 < numKt) {
            issue_loads(c + 1, buf ^ 1);
            asm volatile("cp.async.wait_group 1;" ::: "memory");
        } else {
            asm volatile("cp.async.wait_group 0;" ::: "memory");
        }
        __syncthreads();

        const uint32_t sb = smem_base + buf * STB;
        const uint32_t aHiB = sb;
        const uint32_t bHiB = sb + TILE_BYTES;
        const uint32_t bLoB = sb + 2 * TILE_BYTES;
        const uint32_t aLoB = sb + 3 * TILE_BYTES;

#pragma unroll
        for (int ks = 0; ks < 4; ks++) {
            uint32_t ah[4][4], al[4][4];
#pragma unroll
            for (int mt = 0; mt < 4; mt++) {
                int row = aRowBase + mt * 16;
                uint32_t koff = (ks * 32 + aKadd) ^ ((row & 7) << 4);
                uint32_t off = (uint32_t)row * 128 + koff;
                ldm_x4(ah[mt], aHiB + off);
                if (TERMS == 3) ldm_x4(al[mt], aLoB + off);
            }
            uint32_t bh[2][4], bl[2][4];
#pragma unroll
            for (int np = 0; np < 2; np++) {
                int row = bRowBase + np * 16;
                uint32_t koff = (ks * 32 + bKadd) ^ ((row & 7) << 4);
                uint32_t off = (uint32_t)row * 128 + koff;
                ldm_x4(bh[np], bHiB + off);
                if (TERMS >= 2) ldm_x4(bl[np], bLoB + off);
            }
#pragma unroll
            for (int mt = 0; mt < 4; mt++)
#pragma unroll
                for (int nt = 0; nt < 4; nt++) {
                    const uint32_t* bhp = &bh[nt >> 1][(nt & 1) * 2];
                    mma_f16(acc[mt][nt], ah[mt], bhp);
                    if (TERMS >= 2) {
                        const uint32_t* blp = &bl[nt >> 1][(nt & 1) * 2];
                        mma_f16(acc[mt][nt], ah[mt], blp);
                    }
                    if (TERMS == 3) mma_f16(acc[mt][nt], al[mt], bhp);
                }
        }
        __syncthreads();
    }

    // Epilogue
    const int g = lane >> 2, tg = lane & 3;
    float ls = 0.f, lsq = 0.f;
    if (SPLIT) {
        const int tilesPerRow = ldc >> 6;
#pragma unroll
        for (int mt = 0; mt < 4; mt++) {
            const int row0 = blockIdx.y * 128 + wm * 64 + mt * 16 + g;
#pragma unroll
            for (int nt = 0; nt < 4; nt++) {
                const int col = blockIdx.x * 128 + wn * 32 + nt * 8 + tg * 2;
                const int tile = (row0 >> 7) * tilesPerRow + (col >> 6);
#pragma unroll
                for (int half = 0; half < 2; half++) {
                    const int rowIn = (row0 & 127) + half * 8;
                    float v0 = acc[mt][nt][half * 2 + 0];
                    float v1 = acc[mt][nt][half * 2 + 1];
                    __half h0 = __float2half(v0);
                    __half h1 = __float2half(v1);
                    float l0 = v0 - __half2float(h0);
                    float l1 = v1 - __half2float(h1);
                    __half2 hp = {h0, h1};
                    uint32_t inoff = rowIn * 128 + (col & 63) * 2;
                    uint32_t sw = inoff ^ ((inoff >> 3) & 0x70);
                    *(uint32_t*)(Chi + (size_t)tile * TILE_BYTES + sw) =
                        *reinterpret_cast<uint32_t*>(&hp);
                    *(uint32_t*)(Clo + (size_t)tile * TILE_BYTES + sw) = packh(l0, l1);
                }
            }
        }
    } else if (SIG) {
        __half* Gbase = (__half*)C + (long long)blockIdx.z * cBatchStride;
#pragma unroll
        for (int mt = 0; mt < 4; mt++) {
            const int row0 = blockIdx.y * 128 + wm * 64 + mt * 16 + g;
#pragma unroll
            for (int nt = 0; nt < 4; nt++) {
                const int col = blockIdx.x * 128 + wn * 32 + nt * 8 + tg * 2;
#pragma unroll
                for (int half = 0; half < 2; half++) {
                    float v0 = 0.125f / (1.f + __expf(-acc[mt][nt][half * 2 + 0]));
                    float v1 = 0.125f / (1.f + __expf(-acc[mt][nt][half * 2 + 1]));
                    *(uint32_t*)(Gbase + (long long)(row0 + half * 8) * ldc + col) =
                        packh(v0, v1);
                }
            }
        }
    } else {
        float* Cbase = (float*)C + (long long)blockIdx.z * cBatchStride;
#pragma unroll
        for (int mt = 0; mt < 4; mt++) {
            const int row0 = blockIdx.y * 128 + wm * 64 + mt * 16 + g;
#pragma unroll
            for (int nt = 0; nt < 4; nt++) {
                const int col = blockIdx.x * 128 + wn * 32 + nt * 8 + tg * 2;
                float b0 = 0.f, b1 = 0.f;
                if (BIAS) { b0 = bias[col]; b1 = bias[col + 1]; }
#pragma unroll
                for (int half = 0; half < 2; half++) {
                    float v0 = acc[mt][nt][half * 2 + 0] + b0;
                    float v1 = acc[mt][nt][half * 2 + 1] + b1;
                    if (GNSTAT) {
                        ls += v0 + v1;
                        lsq += v0 * v0 + v1 * v1;
                    }
                    *(float2*)(Cbase + (long long)(row0 + half * 8) * ldc + col) =
                        make_float2(v0, v1);
                }
            }
        }
        if (GNSTAT) {
#pragma unroll
            for (int off = 16; off > 0; off >>= 1) {
                ls  += __shfl_xor_sync(0xffffffffu, ls, off);
                lsq += __shfl_xor_sync(0xffffffffu, lsq, off);
            }
            if (lane == 0) {
                const int b = blockIdx.y >> 4;
                const int grp = blockIdx.x * 2 + (wn >> 1);
                atomicAdd(&stats[(b * GROUPS + grp) * 2 + 0], ls);
                atomicAdd(&stats[(b * GROUPS + grp) * 2 + 1], lsq);
            }
        }
    }
}

// ===========================================================================
// GN apply: normalize P (fp32) using precomputed stats and write f16 hi
// SW128 split tiles (both P1, P2 hi-only: gate GEMM is 1-term).
// ===========================================================================
__global__ void __launch_bounds__(256) gn_apply_kernel(
    const float* __restrict__ g1, const float* __restrict__ b1,
    const float* __restrict__ g2, const float* __restrict__ b2,
    char* __restrict__ p1Hi, char* __restrict__ p2Hi)
{
    const int which = blockIdx.y;
    const float* P = which == 0 ? g_P1 : g_P2;
    const float* st = which == 0 ? g_gnstat1 : g_gnstat2;
    const float* gamma = which == 0 ? g1 : g2;
    const float* beta  = which == 0 ? b1 : b2;
    char* Hi = which == 0 ? p1Hi : p2Hi;

    const int idx = blockIdx.x * 256 + threadIdx.x;
    const int r = idx >> 6;
    const int c = (idx & 63) << 3;
    const int b = r >> 11;
    const int grp = c >> 6;
    const float CNT = (float)((CC / GROUPS) * NN);

    const float s = st[(b * GROUPS + grp) * 2 + 0];
    const float sq = st[(b * GROUPS + grp) * 2 + 1];
    const float mean = s / CNT;
    const float var = sq / CNT - mean * mean;
    const float rstd = rsqrtf(var + 1e-5f);

    float4 v0 = *(const float4*)(P + (size_t)r * CC + c);
    float4 v1 = *(const float4*)(P + (size_t)r * CC + c + 4);
    float vin[8] = {v0.x, v0.y, v0.z, v0.w, v1.x, v1.y, v1.z, v1.w};
    float4 gm0 = *(const float4*)(gamma + c);
    float4 gm1 = *(const float4*)(gamma + c + 4);
    float4 bt0 = *(const float4*)(beta + c);
    float4 bt1 = *(const float4*)(beta + c + 4);
    float gm[8] = {gm0.x, gm0.y, gm0.z, gm0.w, gm1.x, gm1.y, gm1.z, gm1.w};
    float bt[8] = {bt0.x, bt0.y, bt0.z, bt0.w, bt1.x, bt1.y, bt1.z, bt1.w};

    uint32_t hw[4];
#pragma unroll
    for (int i = 0; i < 4; i++) {
        float a0 = (vin[2 * i] - mean) * rstd * gm[2 * i] + bt[2 * i];
        float a1 = (vin[2 * i + 1] - mean) * rstd * gm[2 * i + 1] + bt[2 * i + 1];
        hw[i] = packh(a0, a1);
    }

    const int tile = (r >> 7) * 8 + grp;
    uint32_t inTile = (uint32_t)(r & 127) * 128 + (c & 63) * 2;
    uint32_t sw = inTile ^ ((inTile >> 3) & 0x70);
    size_t off = (size_t)tile * TILE_BYTES + sw;
    *(uint4*)(Hi + off) = make_uint4(hw[0], hw[1], hw[2], hw[3]);
}

// ===========================================================================
// Tensor-core flash attention with fp16 PE gate, register-prefetched.
// S = Qh*Kh (1-term), O += Ph*(Vh+Vl) (2-term). Grid (N/128, H, B); 8 warps.
// ===========================================================================
#define ATT_STAGE 24576
#define ATT_SMEM (16384 + 2 * ATT_STAGE)   // Q hi + 2 KV stages = 64KB

__global__ void __launch_bounds__(256) attn_mma()
{
    extern __shared__ __align__(128) char smem[];
    const uint32_t sb = smem_to_u32(smem);
    const uint32_t qh_base = sb;
    const uint32_t stage0 = sb + 16384;

    const int tid = threadIdx.x, wid = tid >> 5, lane = tid & 31;
    const int q0 = blockIdx.x * 128, h = blockIdx.y, b = blockIdx.z;
    const int g = lane >> 2, tg = lane & 3;

    const int rtQ = (b * NN + q0) >> 7;
    {
        const char* qsh = g_qkvs_hi + (size_t)(rtQ * 24 + h) * TILE_BYTES;
#pragma unroll
        for (int i = 0; i < 4; i++)
            cpa16(qh_base + i * 4096 + tid * 16, qsh + i * 4096 + tid * 16);
        asm volatile("cp.async.commit_group;" ::: "memory");
    }

    auto issue_kv = [&](int t, int stg) {
        const int kRow = t * 64;
        const int rt = (b * NN + kRow) >> 7;
        const int halfOff = (kRow & 64) ? 8192 : 0;
        const char* kh = g_qkvs_hi + (size_t)(rt * 24 + 8 + h) * TILE_BYTES + halfOff;
        const char* vh = g_qkvs_hi + (size_t)(rt * 24 + 16 + h) * TILE_BYTES + halfOff;
        const char* vl = g_qkvs_lo + (size_t)(rt * 24 + 16 + h) * TILE_BYTES + halfOff;
        uint32_t s = stage0 + stg * ATT_STAGE;
#pragma unroll
        for (int i = 0; i < 2; i++) {
            uint32_t o = i * 4096 + tid * 16;
            cpa16(s + o,         kh + o);
            cpa16(s + 8192 + o,  vh + o);
            cpa16(s + 16384 + o, vl + o);
        }
        asm volatile("cp.async.commit_group;" ::: "memory");
    };

    issue_kv(0, 0);
    asm volatile("cp.async.wait_group 1;" ::: "memory");  // Q arrived
    __syncthreads();

    // Q fragments (hi only, resident)
    uint32_t qfh[4][4];
    {
        const int row = wid * 16 + (lane & 15);
        const uint32_t roff = (uint32_t)row * 128;
#pragma unroll
        for (int ks = 0; ks < 4; ks++) {
            uint32_t colb = (lane >> 4) * 16 + ks * 32;
            uint32_t a = roff + (colb ^ ((row & 7) << 4));
            ldm_x4(qfh[ks], qh_base + a);
        }
    }

    float Oa[8][4];
#pragma unroll
    for (int nt = 0; nt < 8; nt++)
#pragma unroll
        for (int f = 0; f < 4; f++) Oa[nt][f] = 0.f;
    float mrow[2] = {-1e30f, -1e30f}, lrow[2] = {0.f, 0.f};

    const size_t peBase = (size_t)b * NN * NN;
    const int qRow0 = q0 + wid * 16 + g;
    const int bRow0 = ((lane >> 4) << 3) + (lane & 7);
    const uint32_t bKadd = ((lane >> 3) & 1) * 16;

    for (int t = 0; t < NN / 64; t++) {
        const int buf = t & 1;
        const int k0 = t * 64;

        // Prefetch fp16 PE gate words before the QK MMAs (latency overlap).
        uint32_t peReg[16];
#pragma unroll
        for (int nt = 0; nt < 8; nt++)
#pragma unroll
            for (int r = 0; r < 2; r++)
                peReg[nt * 2 + r] = *(const uint32_t*)&g_PEh[
                    peBase + (size_t)(qRow0 + r * 8) * NN + k0 + nt * 8 + tg * 2];

        if (t + 1 < NN / 64) {
            issue_kv(t + 1, buf ^ 1);
            asm volatile("cp.async.wait_group 1;" ::: "memory");
        } else {
            asm volatile("cp.async.wait_group 0;" ::: "memory");
        }
        __syncthreads();

        const uint32_t kb = stage0 + buf * ATT_STAGE;
        const uint32_t kh_b = kb;
        const uint32_t vh_b = kb + 8192, vl_b = kb + 16384;

        // S = Q K^T (fp16 1-term)
        float S[8][4];
#pragma unroll
        for (int nt = 0; nt < 8; nt++)
#pragma unroll
            for (int f = 0; f < 4; f++) S[nt][f] = 0.f;

#pragma unroll
        for (int ks = 0; ks < 4; ks++) {
#pragma unroll
            for (int np = 0; np < 4; np++) {
                const int row = bRow0 + np * 16;
                const uint32_t a = (uint32_t)row * 128 +
                                   ((ks * 32 + bKadd) ^ ((row & 7) << 4));
                uint32_t KH[4];
                ldm_x4(KH, kh_b + a);
#pragma unroll
                for (int hn = 0; hn < 2; hn++)
                    mma_f16(S[np * 2 + hn], qfh[ks], &KH[hn * 2]);
            }
        }

        // gate with prefetched fp16 PE (0.125 pre-folded)
#pragma unroll
        for (int nt = 0; nt < 8; nt++) {
#pragma unroll
            for (int r = 0; r < 2; r++) {
                const float2 pe = __half22float2(
                    *reinterpret_cast<const __half2*>(&peReg[nt * 2 + r]));
                S[nt][r * 2 + 0] *= pe.x;
                S[nt][r * 2 + 1] *= pe.y;
            }
        }

        // online softmax
        float corr[2];
#pragma unroll
        for (int r = 0; r < 2; r++) {
            float vm = -1e30f;
#pragma unroll
            for (int nt = 0; nt < 8; nt++)
                vm = fmaxf(vm, fmaxf(S[nt][r * 2], S[nt][r * 2 + 1]));
            vm = fmaxf(vm, __shfl_xor_sync(0xffffffffu, vm, 1));
            vm = fmaxf(vm, __shfl_xor_sync(0xffffffffu, vm, 2));
            const float mn = fmaxf(mrow[r], vm);
            corr[r] = __expf(mrow[r] - mn);
            mrow[r] = mn;
            float rsum = 0.f;
#pragma unroll
            for (int nt = 0; nt < 8; nt++) {
                float p0 = __expf(S[nt][r * 2] - mn);
                float p1 = __expf(S[nt][r * 2 + 1] - mn);
                S[nt][r * 2] = p0;
                S[nt][r * 2 + 1] = p1;
                rsum += p0 + p1;
            }
            rsum += __shfl_xor_sync(0xffffffffu, rsum, 1);
            rsum += __shfl_xor_sync(0xffffffffu, rsum, 2);
            lrow[r] = lrow[r] * corr[r] + rsum;
        }
#pragma unroll
        for (int nt = 0; nt < 8; nt++) {
            Oa[nt][0] *= corr[0]; Oa[nt][1] *= corr[0];
            Oa[nt][2] *= corr[1]; Oa[nt][3] *= corr[1];
        }

        // O += P V (fp16 2-term); P hi fragments from S accumulators
#pragma unroll
        for (int ks = 0; ks < 4; ks++) {
            uint32_t ah[4];
#pragma unroll
            for (int q = 0; q < 2; q++) {
                const float* sv = S[2 * ks + q];
                ah[q * 2 + 0] = packh(sv[0], sv[1]);
                ah[q * 2 + 1] = packh(sv[2], sv[3]);
            }
#pragma unroll
            for (int dp = 0; dp < 4; dp++) {
                const int row = ks * 16 + (lane & 15);
                const uint32_t a = (uint32_t)row * 128 +
                    ((dp * 32 + (lane >> 4) * 16) ^ ((row & 7) << 4));
                uint32_t VH[4], VL[4];
                ldm_x4_t(VH, vh_b + a);
                ldm_x4_t(VL, vl_b + a);
#pragma unroll
                for (int hn = 0; hn < 2; hn++) {
                    const int nt = dp * 2 + hn;
                    mma_f16(Oa[nt], ah, &VH[hn * 2]);
                    mma_f16(Oa[nt], ah, &VL[hn * 2]);
                }
            }
        }
        __syncthreads();
    }

    // Epilogue: normalize and write hi tiles for proj GEMM (O is A operand)
    const float inv[2] = {1.f / lrow[0], 1.f / lrow[1]};
    char* osh = g_os_hi + (size_t)(rtQ * 8 + h) * TILE_BYTES;
#pragma unroll
    for (int nt = 0; nt < 8; nt++) {
#pragma unroll
        for (int r = 0; r < 2; r++) {
            const float v0 = Oa[nt][r * 2 + 0] * inv[r];
            const float v1 = Oa[nt][r * 2 + 1] * inv[r];
            const int rowIn = wid * 16 + g + r * 8;
            const uint32_t inoff = (uint32_t)rowIn * 128 + nt * 16 + tg * 4;
            const uint32_t sw = inoff ^ ((inoff >> 3) & 0x70);
            *(uint32_t*)(osh + sw) = packh(v0, v1);
        }
    }
}

// ===========================================================================

static void split_on(cudaStream_t st, const void* X, void* Hi, void* Lo,
                     int K, int rows, bool wlo)
{
    int total8 = rows * K / 8;
    if (wlo)
        split_f16_kernel<true><<<(total8 + 255) / 256, 256, 0, st>>>(
            (const float*)X, (char*)Hi, (char*)Lo, K, total8);
    else
        split_f16_kernel<false><<<(total8 + 255) / 256, 256, 0, st>>>(
            (const float*)X, (char*)Hi, nullptr, K, total8);
}

#define GEMM_SMEM1 (2 * 2 * TILE_BYTES)   // 64KB
#define GEMM_SMEM2 (2 * 3 * TILE_BYTES)   // 96KB
#define GEMM_SMEM3 (2 * 4 * TILE_BYTES)   // 128KB

extern "C" void kernel_launch(void* const* d_in, const int* in_sizes, int n_in,
                              void* d_out, int out_size)
{
    const float* x       = (const float*)d_in[0];
    const float* pe      = (const float*)d_in[1];
    const float* qkv_w   = (const float*)d_in[2];
    const float* proj_w  = (const float*)d_in[3];
    const float* proj_b  = (const float*)d_in[4];
    const float* conv1_w = (const float*)d_in[5];
    const float* conv1_b = (const float*)d_in[6];
    const float* gn1_g   = (const float*)d_in[7];
    const float* gn1_b   = (const float*)d_in[8];
    const float* conv2_w = (const float*)d_in[9];
    const float* conv2_b = (const float*)d_in[10];
    const float* gn2_g   = (const float*)d_in[11];
    const float* gn2_b   = (const float*)d_in[12];
    float* out = (float*)d_out;

    float *p1, *p2, *st1, *st2;
    void* pehRaw;
    cudaGetSymbolAddress((void**)&p1, g_P1);
    cudaGetSymbolAddress((void**)&p2, g_P2);
    cudaGetSymbolAddress(&pehRaw, g_PEh);
    cudaGetSymbolAddress((void**)&st1, g_gnstat1);
    cudaGetSymbolAddress((void**)&st2, g_gnstat2);

    char *xsh, *pesh, *pesl, *p1h, *p2h, *osh;
    char *wqh, *w1h, *w1l, *w2h, *w2l, *wph, *wpl, *qsh, *qsl;
    cudaGetSymbolAddress((void**)&xsh, g_xs_hi);
    cudaGetSymbolAddress((void**)&pesh, g_pes_hi); cudaGetSymbolAddress((void**)&pesl, g_pes_lo);
    cudaGetSymbolAddress((void**)&p1h, g_p1s_hi);
    cudaGetSymbolAddress((void**)&p2h, g_p2s_hi);
    cudaGetSymbolAddress((void**)&osh, g_os_hi);
    cudaGetSymbolAddress((void**)&wqh, g_wqkv_hi);
    cudaGetSymbolAddress((void**)&w1h, g_wc1_hi);  cudaGetSymbolAddress((void**)&w1l, g_wc1_lo);
    cudaGetSymbolAddress((void**)&w2h, g_wc2_hi);  cudaGetSymbolAddress((void**)&w2l, g_wc2_lo);
    cudaGetSymbolAddress((void**)&wph, g_wpj_hi);  cudaGetSymbolAddress((void**)&wpl, g_wpj_lo);
    cudaGetSymbolAddress((void**)&qsh, g_qkvs_hi); cudaGetSymbolAddress((void**)&qsl, g_qkvs_lo);

    static bool initDone = false;
    static cudaStream_t s2;
    static cudaEvent_t eFork, eJoin;
    if (!initDone) {
        cudaFuncSetAttribute(gemm_mma<3, false, true, false, true>,   cudaFuncAttributeMaxDynamicSharedMemorySize, GEMM_SMEM3);
        cudaFuncSetAttribute(gemm_mma<1, true, false, false, false>,  cudaFuncAttributeMaxDynamicSharedMemorySize, GEMM_SMEM1);
        cudaFuncSetAttribute(gemm_mma<1, false, false, true, false>,  cudaFuncAttributeMaxDynamicSharedMemorySize, GEMM_SMEM1);
        cudaFuncSetAttribute(gemm_mma<2, false, true, false, false>,  cudaFuncAttributeMaxDynamicSharedMemorySize, GEMM_SMEM2);
        cudaFuncSetAttribute(attn_mma, cudaFuncAttributeMaxDynamicSharedMemorySize, ATT_SMEM);
        cudaStreamCreateWithFlags(&s2, cudaStreamNonBlocking);
        cudaEventCreateWithFlags(&eFork, cudaEventDisableTiming);
        cudaEventCreateWithFlags(&eJoin, cudaEventDisableTiming);
        initDone = true;
    }

    const int M = BB * NN;       // 8192
    const int NKT = CC / 64;     // 8

    // ---- Fork: QKV branch on s2 (depends only on inputs) ----
    cudaEventRecord(eFork, 0);
    cudaStreamWaitEvent(s2, eFork, 0);
    split_on(s2, x, xsh, nullptr, CC, M, false);           // A of QKV
    split_on(s2, qkv_w, wqh, nullptr, CC, 3 * CC, false);  // B of QKV
    gemm_mma<1, false, false, true, false><<<dim3(3 * CC / 128, M / 128, 1), 256, GEMM_SMEM1, s2>>>(
        xsh, nullptr, wqh, nullptr, nullptr, nullptr, qsh, qsl, nullptr, NKT, 0, 0, 0, 3 * CC);
    cudaEventRecord(eJoin, s2);

    // ---- Main spine: conv -> GN -> gate ----
    gn_zero_kernel<<<1, 128>>>();
    split_on(0, pe, pesh, pesl, CC, M, true);        // A of conv (3-term)
    split_on(0, conv1_w, w1h, w1l, CC, CC, true);
    split_on(0, conv2_w, w2h, w2l, CC, CC, true);
    split_on(0, proj_w, wph, wpl, CC, CC, true);     // B of proj (2-term)

    gemm_mma<3, false, true, false, true><<<dim3(CC / 128, M / 128, 1), 256, GEMM_SMEM3>>>(
        pesh, pesl, w1h, w1l, conv1_b, p1, nullptr, nullptr, st1, NKT, 0, 0, 0, CC);
    gemm_mma<3, false, true, false, true><<<dim3(CC / 128, M / 128, 1), 256, GEMM_SMEM3>>>(
        pesh, pesl, w2h, w2l, conv2_b, p2, nullptr, nullptr, st2, NKT, 0, 0, 0, CC);

    gn_apply_kernel<<<dim3(2048, 2), 256>>>(
        gn1_g, gn1_b, gn2_g, gn2_b, p1h, p2h);

    gemm_mma<1, true, false, false, false><<<dim3(NN / 128, NN / 128, BB), 256, GEMM_SMEM1>>>(
        p1h, nullptr, p2h, nullptr, nullptr, pehRaw, nullptr, nullptr, nullptr, NKT,
        (NN / 128) * NKT, (NN / 128) * NKT, (long long)NN * NN, NN);

    // ---- Join: attention needs both QKV tiles and the gate ----
    cudaStreamWaitEvent(0, eJoin, 0);
    attn_mma<<<dim3(NN / 128, HH, BB), 256, ATT_SMEM>>>();

    // ---- Output projection ----
    gemm_mma<2, false, true, false, false><<<dim3(CC / 128, M / 128, 1), 256, GEMM_SMEM2>>>(
        osh, nullptr, wph, wpl, proj_b, out, nullptr, nullptr, nullptr, NKT, 0, 0, 0, CC);
}

// round 16
// speedup vs baseline: 1.3674x; 1.0079x over previous
#include <cuda_runtime.h>
#include <cuda_fp16.h>
#include <cstdint>
#include <math.h>

// Problem constants
#define BB 4
#define NN 2048
#define CC 512
#define HH 8
#define DH 64
#define GROUPS 8

// ===========================================================================
// Scratch (__device__ globals; alloc-free rule)
// ===========================================================================
__device__ float g_P1[BB * NN * CC];
__device__ float g_P2[BB * NN * CC];
__device__ __half g_PEh[(size_t)BB * NN * NN];  // 0.125 * sigmoid(...), fp16
__device__ float g_gnstat1[BB * GROUPS * 2];    // (sum, sumsq) per (b,g)
__device__ float g_gnstat2[BB * GROUPS * 2];

// fp16 split operands, tiled SW128 layout (tile = 128 rows x 64 f16 = 16KB)
#define TILE_BYTES 16384
__device__ char g_xs_hi[8192 * 1024];
__device__ char g_pes_hi[8192 * 1024], g_pes_lo[8192 * 1024];
__device__ char g_p1s_hi[8192 * 1024];
__device__ char g_p2s_hi[8192 * 1024];
__device__ char g_os_hi[8192 * 1024];
__device__ char g_wqkv_hi[1536 * 1024];
__device__ char g_wc1_hi[512 * 1024],  g_wc1_lo[512 * 1024];
__device__ char g_wc2_hi[512 * 1024],  g_wc2_lo[512 * 1024];
__device__ char g_wpj_hi[512 * 1024],  g_wpj_lo[512 * 1024];
// QKV in split-tile form: 64 row-tiles x 24 col-tiles x 16KB (hi only)
__device__ char g_qkvs_hi[64 * 24 * TILE_BYTES];

// ===========================================================================
// Helpers
// ===========================================================================
__device__ __forceinline__ uint32_t smem_to_u32(const void* p) {
    uint32_t a;
    asm("{ .reg .u64 t; cvta.to.shared.u64 t, %1; cvt.u32.u64 %0, t; }"
        : "=r"(a) : "l"(p));
    return a;
}

__device__ __forceinline__ void cpa16(uint32_t s, const void* g) {
    asm volatile("cp.async.cg.shared.global [%0], [%1], 16;" :: "r"(s), "l"(g));
}

__device__ __forceinline__ void ldm_x4(uint32_t* r, uint32_t addr) {
    asm volatile("ldmatrix.sync.aligned.m8n8.x4.shared.b16 {%0,%1,%2,%3}, [%4];"
        : "=r"(r[0]), "=r"(r[1]), "=r"(r[2]), "=r"(r[3]) : "r"(addr));
}

__device__ __forceinline__ void ldm_x4_t(uint32_t* r, uint32_t addr) {
    asm volatile("ldmatrix.sync.aligned.m8n8.x4.trans.shared.b16 {%0,%1,%2,%3}, [%4];"
        : "=r"(r[0]), "=r"(r[1]), "=r"(r[2]), "=r"(r[3]) : "r"(addr));
}

__device__ __forceinline__ void mma_f16(float* d, const uint32_t* a,
                                        const uint32_t* b) {
    asm volatile(
        "mma.sync.aligned.m16n8k16.row.col.f32.f16.f16.f32 "
        "{%0,%1,%2,%3}, {%4,%5,%6,%7}, {%8,%9}, {%0,%1,%2,%3};"
        : "+f"(d[0]), "+f"(d[1]), "+f"(d[2]), "+f"(d[3])
        : "r"(a[0]), "r"(a[1]), "r"(a[2]), "r"(a[3]), "r"(b[0]), "r"(b[1]));
}

// pack (lo, hi) floats -> f16x2 reg (lo in low 16 bits)
__device__ __forceinline__ uint32_t packh(float lo, float hi) {
    uint32_t d;
    asm("cvt.rn.f16x2.f32 %0, %1, %2;" : "=r"(d) : "f"(hi), "f"(lo));
    return d;
}

// ===========================================================================
// Split fp32 -> (f16 hi, f16 lo) into tiled SW128-swizzled layout.
// ===========================================================================
template <bool WLO>
__global__ void __launch_bounds__(256) split_f16_kernel(
    const float* __restrict__ X, char* __restrict__ Hi, char* __restrict__ Lo,
    int K, int total8)
{
    int idx = blockIdx.x * 256 + threadIdx.x;
    if (idx >= total8) return;
    int perRow = K >> 3;
    int r = idx / perRow;
    int c = (idx % perRow) << 3;

    float4 v0 = *(const float4*)(X + (size_t)r * K + c);
    float4 v1 = *(const float4*)(X + (size_t)r * K + c + 4);
    float vin[8] = {v0.x, v0.y, v0.z, v0.w, v1.x, v1.y, v1.z, v1.w};

    uint32_t hw[4], lw[4];
#pragma unroll
    for (int i = 0; i < 4; i++) {
        __half h0 = __float2half(vin[2 * i]);
        __half h1 = __float2half(vin[2 * i + 1]);
        __half2 hp = {h0, h1};
        hw[i] = *reinterpret_cast<uint32_t*>(&hp);
        if (WLO) {
            float l0 = vin[2 * i] - __half2float(h0);
            float l1 = vin[2 * i + 1] - __half2float(h1);
            lw[i] = packh(l0, l1);
        }
    }

    int rt = r >> 7, rr = r & 127;
    int kt = c >> 6, cc = c & 63;
    int tile = rt * (K >> 6) + kt;
    uint32_t inTile = rr * 128 + cc * 2;
    uint32_t sw = inTile ^ ((inTile >> 3) & 0x70);
    size_t off = (size_t)tile * TILE_BYTES + sw;
    *(uint4*)(Hi + off) = make_uint4(hw[0], hw[1], hw[2], hw[3]);
    if (WLO) *(uint4*)(Lo + off) = make_uint4(lw[0], lw[1], lw[2], lw[3]);
}

// ===========================================================================
// Zero GN stat accumulators
// ===========================================================================
__global__ void gn_zero_kernel()
{
    if (threadIdx.x < BB * GROUPS * 2) {
        g_gnstat1[threadIdx.x] = 0.f;
        g_gnstat2[threadIdx.x] = 0.f;
    }
}

// ===========================================================================
// fp16 split GEMM-NT via mma.sync.
// TERMS=1: ah*bh. TERMS=2: + ah*bl. TERMS=3: + al*bh.
// SIG: writes fp16 gate (0.125*sigmoid) into C interpreted as __half*.
// SPLIT: writes f16 hi tiles (and lo tiles iff Clo != nullptr).
// GNSTAT: epilogue accumulates (sum, sumsq) per (b, group) via atomics.
// ===========================================================================
template <int TERMS, bool SIG, bool BIAS, bool SPLIT, bool GNSTAT>
__global__ void __launch_bounds__(256) gemm_mma(
    const char* __restrict__ Ahi, const char* __restrict__ Alo,
    const char* __restrict__ Bhi, const char* __restrict__ Blo,
    const float* __restrict__ bias, void* __restrict__ C,
    char* __restrict__ Chi, char* __restrict__ Clo,
    float* __restrict__ stats,
    int numKt, int aBatchTiles, int bBatchTiles, long long cBatchStride, int ldc)
{
    constexpr int NTILES = TERMS + 1;
    constexpr uint32_t STB = NTILES * TILE_BYTES;

    extern __shared__ __align__(128) char smem[];
    uint32_t smem_base = smem_to_u32(smem);
    const int tid = threadIdx.x;
    const int wid = tid >> 5;
    const int lane = tid & 31;
    const int wm = wid & 1;
    const int wn = wid >> 1;

    const long long aTileBase = (long long)blockIdx.z * aBatchTiles + (long long)blockIdx.y * numKt;
    const long long bTileBase = (long long)blockIdx.z * bBatchTiles + (long long)blockIdx.x * numKt;

    auto issue_loads = [&](int kt, int stage) {
        const char* srcs[4];
        srcs[0] = Ahi + (aTileBase + kt) * TILE_BYTES;
        srcs[1] = Bhi + (bTileBase + kt) * TILE_BYTES;
        if (TERMS >= 2) srcs[2] = Blo + (bTileBase + kt) * TILE_BYTES;
        if (TERMS == 3) srcs[3] = Alo + (aTileBase + kt) * TILE_BYTES;
        uint32_t sb = smem_base + stage * STB;
#pragma unroll
        for (int t = 0; t < NTILES; t++)
#pragma unroll
            for (int i = 0; i < 4; i++) {
                uint32_t o = t * TILE_BYTES + i * 4096 + tid * 16;
                cpa16(sb + o, srcs[t] + i * 4096 + tid * 16);
            }
        asm volatile("cp.async.commit_group;" ::: "memory");
    };

    const int aRowBase = wm * 64 + (lane & 15);
    const uint32_t aKadd = (lane >> 4) * 16;
    const int bRowBase = wn * 32 + ((lane >> 4) << 3) + (lane & 7);
    const uint32_t bKadd = ((lane >> 3) & 1) * 16;

    float acc[4][4][4];
#pragma unroll
    for (int mt = 0; mt < 4; mt++)
#pragma unroll
        for (int nt = 0; nt < 4; nt++)
#pragma unroll
            for (int f = 0; f < 4; f++) acc[mt][nt][f] = 0.f;

    issue_loads(0, 0);

    for (int c = 0; c < numKt; c++) {
        const int buf = c & 1;
        if (c + 1 < numKt) {
            issue_loads(c + 1, buf ^ 1);
            asm volatile("cp.async.wait_group 1;" ::: "memory");
        } else {
            asm volatile("cp.async.wait_group 0;" ::: "memory");
        }
        __syncthreads();

        const uint32_t sb = smem_base + buf * STB;
        const uint32_t aHiB = sb;
        const uint32_t bHiB = sb + TILE_BYTES;
        const uint32_t bLoB = sb + 2 * TILE_BYTES;
        const uint32_t aLoB = sb + 3 * TILE_BYTES;

#pragma unroll
        for (int ks = 0; ks < 4; ks++) {
            uint32_t ah[4][4], al[4][4];
#pragma unroll
            for (int mt = 0; mt < 4; mt++) {
                int row = aRowBase + mt * 16;
                uint32_t koff = (ks * 32 + aKadd) ^ ((row & 7) << 4);
                uint32_t off = (uint32_t)row * 128 + koff;
                ldm_x4(ah[mt], aHiB + off);
                if (TERMS == 3) ldm_x4(al[mt], aLoB + off);
            }
            uint32_t bh[2][4], bl[2][4];
#pragma unroll
            for (int np = 0; np < 2; np++) {
                int row = bRowBase + np * 16;
                uint32_t koff = (ks * 32 + bKadd) ^ ((row & 7) << 4);
                uint32_t off = (uint32_t)row * 128 + koff;
                ldm_x4(bh[np], bHiB + off);
                if (TERMS >= 2) ldm_x4(bl[np], bLoB + off);
            }
#pragma unroll
            for (int mt = 0; mt < 4; mt++)
#pragma unroll
                for (int nt = 0; nt < 4; nt++) {
                    const uint32_t* bhp = &bh[nt >> 1][(nt & 1) * 2];
                    mma_f16(acc[mt][nt], ah[mt], bhp);
                    if (TERMS >= 2) {
                        const uint32_t* blp = &bl[nt >> 1][(nt & 1) * 2];
                        mma_f16(acc[mt][nt], ah[mt], blp);
                    }
                    if (TERMS == 3) mma_f16(acc[mt][nt], al[mt], bhp);
                }
        }
        __syncthreads();
    }

    // Epilogue
    const int g = lane >> 2, tg = lane & 3;
    float ls = 0.f, lsq = 0.f;
    if (SPLIT) {
        const int tilesPerRow = ldc >> 6;
        const bool wlo = (Clo != nullptr);
#pragma unroll
        for (int mt = 0; mt < 4; mt++) {
            const int row0 = blockIdx.y * 128 + wm * 64 + mt * 16 + g;
#pragma unroll
            for (int nt = 0; nt < 4; nt++) {
                const int col = blockIdx.x * 128 + wn * 32 + nt * 8 + tg * 2;
                const int tile = (row0 >> 7) * tilesPerRow + (col >> 6);
#pragma unroll
                for (int half = 0; half < 2; half++) {
                    const int rowIn = (row0 & 127) + half * 8;
                    float v0 = acc[mt][nt][half * 2 + 0];
                    float v1 = acc[mt][nt][half * 2 + 1];
                    __half h0 = __float2half(v0);
                    __half h1 = __float2half(v1);
                    __half2 hp = {h0, h1};
                    uint32_t inoff = rowIn * 128 + (col & 63) * 2;
                    uint32_t sw = inoff ^ ((inoff >> 3) & 0x70);
                    *(uint32_t*)(Chi + (size_t)tile * TILE_BYTES + sw) =
                        *reinterpret_cast<uint32_t*>(&hp);
                    if (wlo) {
                        float l0 = v0 - __half2float(h0);
                        float l1 = v1 - __half2float(h1);
                        *(uint32_t*)(Clo + (size_t)tile * TILE_BYTES + sw) = packh(l0, l1);
                    }
                }
            }
        }
    } else if (SIG) {
        __half* Gbase = (__half*)C + (long long)blockIdx.z * cBatchStride;
#pragma unroll
        for (int mt = 0; mt < 4; mt++) {
            const int row0 = blockIdx.y * 128 + wm * 64 + mt * 16 + g;
#pragma unroll
            for (int nt = 0; nt < 4; nt++) {
                const int col = blockIdx.x * 128 + wn * 32 + nt * 8 + tg * 2;
#pragma unroll
                for (int half = 0; half < 2; half++) {
                    float v0 = 0.125f / (1.f + __expf(-acc[mt][nt][half * 2 + 0]));
                    float v1 = 0.125f / (1.f + __expf(-acc[mt][nt][half * 2 + 1]));
                    *(uint32_t*)(Gbase + (long long)(row0 + half * 8) * ldc + col) =
                        packh(v0, v1);
                }
            }
        }
    } else {
        float* Cbase = (float*)C + (long long)blockIdx.z * cBatchStride;
#pragma unroll
        for (int mt = 0; mt < 4; mt++) {
            const int row0 = blockIdx.y * 128 + wm * 64 + mt * 16 + g;
#pragma unroll
            for (int nt = 0; nt < 4; nt++) {
                const int col = blockIdx.x * 128 + wn * 32 + nt * 8 + tg * 2;
                float b0 = 0.f, b1 = 0.f;
                if (BIAS) { b0 = bias[col]; b1 = bias[col + 1]; }
#pragma unroll
                for (int half = 0; half < 2; half++) {
                    float v0 = acc[mt][nt][half * 2 + 0] + b0;
                    float v1 = acc[mt][nt][half * 2 + 1] + b1;
                    if (GNSTAT) {
                        ls += v0 + v1;
                        lsq += v0 * v0 + v1 * v1;
                    }
                    *(float2*)(Cbase + (long long)(row0 + half * 8) * ldc + col) =
                        make_float2(v0, v1);
                }
            }
        }
        if (GNSTAT) {
#pragma unroll
            for (int off = 16; off > 0; off >>= 1) {
                ls  += __shfl_xor_sync(0xffffffffu, ls, off);
                lsq += __shfl_xor_sync(0xffffffffu, lsq, off);
            }
            if (lane == 0) {
                const int b = blockIdx.y >> 4;
                const int grp = blockIdx.x * 2 + (wn >> 1);
                atomicAdd(&stats[(b * GROUPS + grp) * 2 + 0], ls);
                atomicAdd(&stats[(b * GROUPS + grp) * 2 + 1], lsq);
            }
        }
    }
}

// ===========================================================================
// GN apply: normalize P (fp32) using precomputed stats and write f16 hi
// SW128 split tiles (both P1, P2 hi-only: gate GEMM is 1-term).
// ===========================================================================
__global__ void __launch_bounds__(256) gn_apply_kernel(
    const float* __restrict__ g1, const float* __restrict__ b1,
    const float* __restrict__ g2, const float* __restrict__ b2,
    char* __restrict__ p1Hi, char* __restrict__ p2Hi)
{
    const int which = blockIdx.y;
    const float* P = which == 0 ? g_P1 : g_P2;
    const float* st = which == 0 ? g_gnstat1 : g_gnstat2;
    const float* gamma = which == 0 ? g1 : g2;
    const float* beta  = which == 0 ? b1 : b2;
    char* Hi = which == 0 ? p1Hi : p2Hi;

    const int idx = blockIdx.x * 256 + threadIdx.x;
    const int r = idx >> 6;
    const int c = (idx & 63) << 3;
    const int b = r >> 11;
    const int grp = c >> 6;
    const float CNT = (float)((CC / GROUPS) * NN);

    const float s = st[(b * GROUPS + grp) * 2 + 0];
    const float sq = st[(b * GROUPS + grp) * 2 + 1];
    const float mean = s / CNT;
    const float var = sq / CNT - mean * mean;
    const float rstd = rsqrtf(var + 1e-5f);

    float4 v0 = *(const float4*)(P + (size_t)r * CC + c);
    float4 v1 = *(const float4*)(P + (size_t)r * CC + c + 4);
    float vin[8] = {v0.x, v0.y, v0.z, v0.w, v1.x, v1.y, v1.z, v1.w};
    float4 gm0 = *(const float4*)(gamma + c);
    float4 gm1 = *(const float4*)(gamma + c + 4);
    float4 bt0 = *(const float4*)(beta + c);
    float4 bt1 = *(const float4*)(beta + c + 4);
    float gm[8] = {gm0.x, gm0.y, gm0.z, gm0.w, gm1.x, gm1.y, gm1.z, gm1.w};
    float bt[8] = {bt0.x, bt0.y, bt0.z, bt0.w, bt1.x, bt1.y, bt1.z, bt1.w};

    uint32_t hw[4];
#pragma unroll
    for (int i = 0; i < 4; i++) {
        float a0 = (vin[2 * i] - mean) * rstd * gm[2 * i] + bt[2 * i];
        float a1 = (vin[2 * i + 1] - mean) * rstd * gm[2 * i + 1] + bt[2 * i + 1];
        hw[i] = packh(a0, a1);
    }

    const int tile = (r >> 7) * 8 + grp;
    uint32_t inTile = (uint32_t)(r & 127) * 128 + (c & 63) * 2;
    uint32_t sw = inTile ^ ((inTile >> 3) & 0x70);
    size_t off = (size_t)tile * TILE_BYTES + sw;
    *(uint4*)(Hi + off) = make_uint4(hw[0], hw[1], hw[2], hw[3]);
}

// ===========================================================================
// Tensor-core flash attention with fp16 PE gate, register-prefetched.
// S = Qh*Kh (1-term), O += Ph*Vh (1-term). Grid (N/128, H, B); 8 warps.
// KV stage: Kh 8KB + Vh 8KB = 16KB.
// ===========================================================================
#define ATT_STAGE 16384
#define ATT_SMEM (16384 + 2 * ATT_STAGE)   // Q hi + 2 KV stages = 48KB

__global__ void __launch_bounds__(256) attn_mma()
{
    extern __shared__ __align__(128) char smem[];
    const uint32_t sb = smem_to_u32(smem);
    const uint32_t qh_base = sb;
    const uint32_t stage0 = sb + 16384;

    const int tid = threadIdx.x, wid = tid >> 5, lane = tid & 31;
    const int q0 = blockIdx.x * 128, h = blockIdx.y, b = blockIdx.z;
    const int g = lane >> 2, tg = lane & 3;

    const int rtQ = (b * NN + q0) >> 7;
    {
        const char* qsh = g_qkvs_hi + (size_t)(rtQ * 24 + h) * TILE_BYTES;
#pragma unroll
        for (int i = 0; i < 4; i++)
            cpa16(qh_base + i * 4096 + tid * 16, qsh + i * 4096 + tid * 16);
        asm volatile("cp.async.commit_group;" ::: "memory");
    }

    auto issue_kv = [&](int t, int stg) {
        const int kRow = t * 64;
        const int rt = (b * NN + kRow) >> 7;
        const int halfOff = (kRow & 64) ? 8192 : 0;
        const char* kh = g_qkvs_hi + (size_t)(rt * 24 + 8 + h) * TILE_BYTES + halfOff;
        const char* vh = g_qkvs_hi + (size_t)(rt * 24 + 16 + h) * TILE_BYTES + halfOff;
        uint32_t s = stage0 + stg * ATT_STAGE;
#pragma unroll
        for (int i = 0; i < 2; i++) {
            uint32_t o = i * 4096 + tid * 16;
            cpa16(s + o,        kh + o);
            cpa16(s + 8192 + o, vh + o);
        }
        asm volatile("cp.async.commit_group;" ::: "memory");
    };

    issue_kv(0, 0);
    asm volatile("cp.async.wait_group 1;" ::: "memory");  // Q arrived
    __syncthreads();

    // Q fragments (hi only, resident)
    uint32_t qfh[4][4];
    {
        const int row = wid * 16 + (lane & 15);
        const uint32_t roff = (uint32_t)row * 128;
#pragma unroll
        for (int ks = 0; ks < 4; ks++) {
            uint32_t colb = (lane >> 4) * 16 + ks * 32;
            uint32_t a = roff + (colb ^ ((row & 7) << 4));
            ldm_x4(qfh[ks], qh_base + a);
        }
    }

    float Oa[8][4];
#pragma unroll
    for (int nt = 0; nt < 8; nt++)
#pragma unroll
        for (int f = 0; f < 4; f++) Oa[nt][f] = 0.f;
    float mrow[2] = {-1e30f, -1e30f}, lrow[2] = {0.f, 0.f};

    const size_t peBase = (size_t)b * NN * NN;
    const int qRow0 = q0 + wid * 16 + g;
    const int bRow0 = ((lane >> 4) << 3) + (lane & 7);
    const uint32_t bKadd = ((lane >> 3) & 1) * 16;

    for (int t = 0; t < NN / 64; t++) {
        const int buf = t & 1;
        const int k0 = t * 64;

        // Prefetch fp16 PE gate words before the QK MMAs (latency overlap).
        uint32_t peReg[16];
#pragma unroll
        for (int nt = 0; nt < 8; nt++)
#pragma unroll
            for (int r = 0; r < 2; r++)
                peReg[nt * 2 + r] = *(const uint32_t*)&g_PEh[
                    peBase + (size_t)(qRow0 + r * 8) * NN + k0 + nt * 8 + tg * 2];

        if (t + 1 < NN / 64) {
            issue_kv(t + 1, buf ^ 1);
            asm volatile("cp.async.wait_group 1;" ::: "memory");
        } else {
            asm volatile("cp.async.wait_group 0;" ::: "memory");
        }
        __syncthreads();

        const uint32_t kb = stage0 + buf * ATT_STAGE;
        const uint32_t kh_b = kb;
        const uint32_t vh_b = kb + 8192;

        // S = Q K^T (fp16 1-term)
        float S[8][4];
#pragma unroll
        for (int nt = 0; nt < 8; nt++)
#pragma unroll
            for (int f = 0; f < 4; f++) S[nt][f] = 0.f;

#pragma unroll
        for (int ks = 0; ks < 4; ks++) {
#pragma unroll
            for (int np = 0; np < 4; np++) {
                const int row = bRow0 + np * 16;
                const uint32_t a = (uint32_t)row * 128 +
                                   ((ks * 32 + bKadd) ^ ((row & 7) << 4));
                uint32_t KH[4];
                ldm_x4(KH, kh_b + a);
#pragma unroll
                for (int hn = 0; hn < 2; hn++)
                    mma_f16(S[np * 2 + hn], qfh[ks], &KH[hn * 2]);
            }
        }

        // gate with prefetched fp16 PE (0.125 pre-folded)
#pragma unroll
        for (int nt = 0; nt < 8; nt++) {
#pragma unroll
            for (int r = 0; r < 2; r++) {
                const float2 pe = __half22float2(
                    *reinterpret_cast<const __half2*>(&peReg[nt * 2 + r]));
                S[nt][r * 2 + 0] *= pe.x;
                S[nt][r * 2 + 1] *= pe.y;
            }
        }

        // online softmax
        float corr[2];
#pragma unroll
        for (int r = 0; r < 2; r++) {
            float vm = -1e30f;
#pragma unroll
            for (int nt = 0; nt < 8; nt++)
                vm = fmaxf(vm, fmaxf(S[nt][r * 2], S[nt][r * 2 + 1]));
            vm = fmaxf(vm, __shfl_xor_sync(0xffffffffu, vm, 1));
            vm = fmaxf(vm, __shfl_xor_sync(0xffffffffu, vm, 2));
            const float mn = fmaxf(mrow[r], vm);
            corr[r] = __expf(mrow[r] - mn);
            mrow[r] = mn;
            float rsum = 0.f;
#pragma unroll
            for (int nt = 0; nt < 8; nt++) {
                float p0 = __expf(S[nt][r * 2] - mn);
                float p1 = __expf(S[nt][r * 2 + 1] - mn);
                S[nt][r * 2] = p0;
                S[nt][r * 2 + 1] = p1;
                rsum += p0 + p1;
            }
            rsum += __shfl_xor_sync(0xffffffffu, rsum, 1);
            rsum += __shfl_xor_sync(0xffffffffu, rsum, 2);
            lrow[r] = lrow[r] * corr[r] + rsum;
        }
#pragma unroll
        for (int nt = 0; nt < 8; nt++) {
            Oa[nt][0] *= corr[0]; Oa[nt][1] *= corr[0];
            Oa[nt][2] *= corr[1]; Oa[nt][3] *= corr[1];
        }

        // O += P V (fp16 1-term); P hi fragments from S accumulators
#pragma unroll
        for (int ks = 0; ks < 4; ks++) {
            uint32_t ah[4];
#pragma unroll
            for (int q = 0; q < 2; q++) {
                const float* sv = S[2 * ks + q];
                ah[q * 2 + 0] = packh(sv[0], sv[1]);
                ah[q * 2 + 1] = packh(sv[2], sv[3]);
            }
#pragma unroll
            for (int dp = 0; dp < 4; dp++) {
                const int row = ks * 16 + (lane & 15);
                const uint32_t a = (uint32_t)row * 128 +
                    ((dp * 32 + (lane >> 4) * 16) ^ ((row & 7) << 4));
                uint32_t VH[4];
                ldm_x4_t(VH, vh_b + a);
#pragma unroll
                for (int hn = 0; hn < 2; hn++)
                    mma_f16(Oa[dp * 2 + hn], ah, &VH[hn * 2]);
            }
        }
        __syncthreads();
    }

    // Epilogue: normalize and write hi tiles for proj GEMM (O is A operand)
    const float inv[2] = {1.f / lrow[0], 1.f / lrow[1]};
    char* osh = g_os_hi + (size_t)(rtQ * 8 + h) * TILE_BYTES;
#pragma unroll
    for (int nt = 0; nt < 8; nt++) {
#pragma unroll
        for (int r = 0; r < 2; r++) {
            const float v0 = Oa[nt][r * 2 + 0] * inv[r];
            const float v1 = Oa[nt][r * 2 + 1] * inv[r];
            const int rowIn = wid * 16 + g + r * 8;
            const uint32_t inoff = (uint32_t)rowIn * 128 + nt * 16 + tg * 4;
            const uint32_t sw = inoff ^ ((inoff >> 3) & 0x70);
            *(uint32_t*)(osh + sw) = packh(v0, v1);
        }
    }
}

// ===========================================================================

static void split_on(cudaStream_t st, const void* X, void* Hi, void* Lo,
                     int K, int rows, bool wlo)
{
    int total8 = rows * K / 8;
    if (wlo)
        split_f16_kernel<true><<<(total8 + 255) / 256, 256, 0, st>>>(
            (const float*)X, (char*)Hi, (char*)Lo, K, total8);
    else
        split_f16_kernel<false><<<(total8 + 255) / 256, 256, 0, st>>>(
            (const float*)X, (char*)Hi, nullptr, K, total8);
}

#define GEMM_SMEM1 (2 * 2 * TILE_BYTES)   // 64KB
#define GEMM_SMEM2 (2 * 3 * TILE_BYTES)   // 96KB
#define GEMM_SMEM3 (2 * 4 * TILE_BYTES)   // 128KB

extern "C" void kernel_launch(void* const* d_in, const int* in_sizes, int n_in,
                              void* d_out, int out_size)
{
    const float* x       = (const float*)d_in[0];
    const float* pe      = (const float*)d_in[1];
    const float* qkv_w   = (const float*)d_in[2];
    const float* proj_w  = (const float*)d_in[3];
    const float* proj_b  = (const float*)d_in[4];
    const float* conv1_w = (const float*)d_in[5];
    const float* conv1_b = (const float*)d_in[6];
    const float* gn1_g   = (const float*)d_in[7];
    const float* gn1_b   = (const float*)d_in[8];
    const float* conv2_w = (const float*)d_in[9];
    const float* conv2_b = (const float*)d_in[10];
    const float* gn2_g   = (const float*)d_in[11];
    const float* gn2_b   = (const float*)d_in[12];
    float* out = (float*)d_out;

    float *p1, *p2, *st1, *st2;
    void* pehRaw;
    cudaGetSymbolAddress((void**)&p1, g_P1);
    cudaGetSymbolAddress((void**)&p2, g_P2);
    cudaGetSymbolAddress(&pehRaw, g_PEh);
    cudaGetSymbolAddress((void**)&st1, g_gnstat1);
    cudaGetSymbolAddress((void**)&st2, g_gnstat2);

    char *xsh, *pesh, *pesl, *p1h, *p2h, *osh;
    char *wqh, *w1h, *w1l, *w2h, *w2l, *wph, *wpl, *qsh;
    cudaGetSymbolAddress((void**)&xsh, g_xs_hi);
    cudaGetSymbolAddress((void**)&pesh, g_pes_hi); cudaGetSymbolAddress((void**)&pesl, g_pes_lo);
    cudaGetSymbolAddress((void**)&p1h, g_p1s_hi);
    cudaGetSymbolAddress((void**)&p2h, g_p2s_hi);
    cudaGetSymbolAddress((void**)&osh, g_os_hi);
    cudaGetSymbolAddress((void**)&wqh, g_wqkv_hi);
    cudaGetSymbolAddress((void**)&w1h, g_wc1_hi);  cudaGetSymbolAddress((void**)&w1l, g_wc1_lo);
    cudaGetSymbolAddress((void**)&w2h, g_wc2_hi);  cudaGetSymbolAddress((void**)&w2l, g_wc2_lo);
    cudaGetSymbolAddress((void**)&wph, g_wpj_hi);  cudaGetSymbolAddress((void**)&wpl, g_wpj_lo);
    cudaGetSymbolAddress((void**)&qsh, g_qkvs_hi);

    static bool initDone = false;
    static cudaStream_t s2;
    static cudaEvent_t eFork, eJoin;
    if (!initDone) {
        cudaFuncSetAttribute(gemm_mma<3, false, true, false, true>,   cudaFuncAttributeMaxDynamicSharedMemorySize, GEMM_SMEM3);
        cudaFuncSetAttribute(gemm_mma<1, true, false, false, false>,  cudaFuncAttributeMaxDynamicSharedMemorySize, GEMM_SMEM1);
        cudaFuncSetAttribute(gemm_mma<1, false, false, true, false>,  cudaFuncAttributeMaxDynamicSharedMemorySize, GEMM_SMEM1);
        cudaFuncSetAttribute(gemm_mma<2, false, true, false, false>,  cudaFuncAttributeMaxDynamicSharedMemorySize, GEMM_SMEM2);
        cudaFuncSetAttribute(attn_mma, cudaFuncAttributeMaxDynamicSharedMemorySize, ATT_SMEM);
        cudaStreamCreateWithFlags(&s2, cudaStreamNonBlocking);
        cudaEventCreateWithFlags(&eFork, cudaEventDisableTiming);
        cudaEventCreateWithFlags(&eJoin, cudaEventDisableTiming);
        initDone = true;
    }

    const int M = BB * NN;       // 8192
    const int NKT = CC / 64;     // 8

    // ---- Fork: QKV branch + proj_w split on s2 (depend only on inputs) ----
    cudaEventRecord(eFork, 0);
    cudaStreamWaitEvent(s2, eFork, 0);
    split_on(s2, x, xsh, nullptr, CC, M, false);           // A of QKV
    split_on(s2, qkv_w, wqh, nullptr, CC, 3 * CC, false);  // B of QKV
    split_on(s2, proj_w, wph, wpl, CC, CC, true);          // B of proj (2-term)
    gemm_mma<1, false, false, true, false><<<dim3(3 * CC / 128, M / 128, 1), 256, GEMM_SMEM1, s2>>>(
        xsh, nullptr, wqh, nullptr, nullptr, nullptr, qsh, nullptr, nullptr, NKT, 0, 0, 0, 3 * CC);
    cudaEventRecord(eJoin, s2);

    // ---- Main spine: conv -> GN -> gate ----
    gn_zero_kernel<<<1, 128>>>();
    split_on(0, pe, pesh, pesl, CC, M, true);        // A of conv (3-term)
    split_on(0, conv1_w, w1h, w1l, CC, CC, true);
    split_on(0, conv2_w, w2h, w2l, CC, CC, true);

    gemm_mma<3, false, true, false, true><<<dim3(CC / 128, M / 128, 1), 256, GEMM_SMEM3>>>(
        pesh, pesl, w1h, w1l, conv1_b, p1, nullptr, nullptr, st1, NKT, 0, 0, 0, CC);
    gemm_mma<3, false, true, false, true><<<dim3(CC / 128, M / 128, 1), 256, GEMM_SMEM3>>>(
        pesh, pesl, w2h, w2l, conv2_b, p2, nullptr, nullptr, st2, NKT, 0, 0, 0, CC);

    gn_apply_kernel<<<dim3(2048, 2), 256>>>(
        gn1_g, gn1_b, gn2_g, gn2_b, p1h, p2h);

    gemm_mma<1, true, false, false, false><<<dim3(NN / 128, NN / 128, BB), 256, GEMM_SMEM1>>>(
        p1h, nullptr, p2h, nullptr, nullptr, pehRaw, nullptr, nullptr, nullptr, NKT,
        (NN / 128) * NKT, (NN / 128) * NKT, (long long)NN * NN, NN);

    // ---- Join: attention needs QKV tiles, gate ----
    cudaStreamWaitEvent(0, eJoin, 0);
    attn_mma<<<dim3(NN / 128, HH, BB), 256, ATT_SMEM>>>();

    // ---- Output projection (fp16 2-term) ----
    gemm_mma<2, false, true, false, false><<<dim3(CC / 128, M / 128, 1), 256, GEMM_SMEM2>>>(
        osh, nullptr, wph, wpl, proj_b, out, nullptr, nullptr, nullptr, NKT, 0, 0, 0, CC);
}

// round 17
// speedup vs baseline: 1.4767x; 1.0800x over previous
#include <cuda_runtime.h>
#include <cuda_fp16.h>
#include <cstdint>
#include <math.h>

// Problem constants
#define BB 4
#define NN 2048
#define CC 512
#define HH 8
#define DH 64
#define GROUPS 8

// ===========================================================================
// Scratch (__device__ globals; alloc-free rule)
// ===========================================================================
__device__ float g_P1[BB * NN * CC];
__device__ float g_P2[BB * NN * CC];
__device__ __half g_PEh[(size_t)BB * NN * NN];  // 0.125 * sigmoid(...), fp16
__device__ float g_gnstat1[BB * GROUPS * 2];    // (sum, sumsq) per (b,g)
__device__ float g_gnstat2[BB * GROUPS * 2];

// fp16 split operands, tiled SW128 layout (tile = 128 rows x 64 f16 = 16KB)
#define TILE_BYTES 16384
__device__ char g_xs_hi[8192 * 1024];
__device__ char g_pes_hi[8192 * 1024];
__device__ char g_p1s_hi[8192 * 1024];
__device__ char g_p2s_hi[8192 * 1024];
__device__ char g_os_hi[8192 * 1024];
__device__ char g_wqkv_hi[1536 * 1024];
__device__ char g_wc1_hi[512 * 1024],  g_wc1_lo[512 * 1024];
__device__ char g_wc2_hi[512 * 1024],  g_wc2_lo[512 * 1024];
__device__ char g_wpj_hi[512 * 1024];
// QKV in split-tile form: 64 row-tiles x 24 col-tiles x 16KB (hi only)
__device__ char g_qkvs_hi[64 * 24 * TILE_BYTES];

// ===========================================================================
// Helpers
// ===========================================================================
__device__ __forceinline__ uint32_t smem_to_u32(const void* p) {
    uint32_t a;
    asm("{ .reg .u64 t; cvta.to.shared.u64 t, %1; cvt.u32.u64 %0, t; }"
        : "=r"(a) : "l"(p));
    return a;
}

__device__ __forceinline__ void cpa16(uint32_t s, const void* g) {
    asm volatile("cp.async.cg.shared.global [%0], [%1], 16;" :: "r"(s), "l"(g));
}

__device__ __forceinline__ void ldm_x4(uint32_t* r, uint32_t addr) {
    asm volatile("ldmatrix.sync.aligned.m8n8.x4.shared.b16 {%0,%1,%2,%3}, [%4];"
        : "=r"(r[0]), "=r"(r[1]), "=r"(r[2]), "=r"(r[3]) : "r"(addr));
}

__device__ __forceinline__ void ldm_x4_t(uint32_t* r, uint32_t addr) {
    asm volatile("ldmatrix.sync.aligned.m8n8.x4.trans.shared.b16 {%0,%1,%2,%3}, [%4];"
        : "=r"(r[0]), "=r"(r[1]), "=r"(r[2]), "=r"(r[3]) : "r"(addr));
}

__device__ __forceinline__ void mma_f16(float* d, const uint32_t* a,
                                        const uint32_t* b) {
    asm volatile(
        "mma.sync.aligned.m16n8k16.row.col.f32.f16.f16.f32 "
        "{%0,%1,%2,%3}, {%4,%5,%6,%7}, {%8,%9}, {%0,%1,%2,%3};"
        : "+f"(d[0]), "+f"(d[1]), "+f"(d[2]), "+f"(d[3])
        : "r"(a[0]), "r"(a[1]), "r"(a[2]), "r"(a[3]), "r"(b[0]), "r"(b[1]));
}

// pack (lo, hi) floats -> f16x2 reg (lo in low 16 bits)
__device__ __forceinline__ uint32_t packh(float lo, float hi) {
    uint32_t d;
    asm("cvt.rn.f16x2.f32 %0, %1, %2;" : "=r"(d) : "f"(hi), "f"(lo));
    return d;
}

// ===========================================================================
// Split fp32 -> (f16 hi, f16 lo) into tiled SW128-swizzled layout.
// ===========================================================================
template <bool WLO>
__global__ void __launch_bounds__(256) split_f16_kernel(
    const float* __restrict__ X, char* __restrict__ Hi, char* __restrict__ Lo,
    int K, int total8)
{
    int idx = blockIdx.x * 256 + threadIdx.x;
    if (idx >= total8) return;
    int perRow = K >> 3;
    int r = idx / perRow;
    int c = (idx % perRow) << 3;

    float4 v0 = *(const float4*)(X + (size_t)r * K + c);
    float4 v1 = *(const float4*)(X + (size_t)r * K + c + 4);
    float vin[8] = {v0.x, v0.y, v0.z, v0.w, v1.x, v1.y, v1.z, v1.w};

    uint32_t hw[4], lw[4];
#pragma unroll
    for (int i = 0; i < 4; i++) {
        __half h0 = __float2half(vin[2 * i]);
        __half h1 = __float2half(vin[2 * i + 1]);
        __half2 hp = {h0, h1};
        hw[i] = *reinterpret_cast<uint32_t*>(&hp);
        if (WLO) {
            float l0 = vin[2 * i] - __half2float(h0);
            float l1 = vin[2 * i + 1] - __half2float(h1);
            lw[i] = packh(l0, l1);
        }
    }

    int rt = r >> 7, rr = r & 127;
    int kt = c >> 6, cc = c & 63;
    int tile = rt * (K >> 6) + kt;
    uint32_t inTile = rr * 128 + cc * 2;
    uint32_t sw = inTile ^ ((inTile >> 3) & 0x70);
    size_t off = (size_t)tile * TILE_BYTES + sw;
    *(uint4*)(Hi + off) = make_uint4(hw[0], hw[1], hw[2], hw[3]);
    if (WLO) *(uint4*)(Lo + off) = make_uint4(lw[0], lw[1], lw[2], lw[3]);
}

// ===========================================================================
// Zero GN stat accumulators
// ===========================================================================
__global__ void gn_zero_kernel()
{
    if (threadIdx.x < BB * GROUPS * 2) {
        g_gnstat1[threadIdx.x] = 0.f;
        g_gnstat2[threadIdx.x] = 0.f;
    }
}

// ===========================================================================
// fp16 split GEMM-NT via mma.sync.
// TERMS=1: ah*bh. TERMS=2: + ah*bl. TERMS=3: + al*bh.
// SIG: writes fp16 gate (0.125*sigmoid) into C interpreted as __half*.
// SPLIT: writes f16 hi tiles (and lo tiles iff Clo != nullptr).
// GNSTAT: epilogue accumulates (sum, sumsq) per (b, group) via atomics.
// ===========================================================================
template <int TERMS, bool SIG, bool BIAS, bool SPLIT, bool GNSTAT>
__global__ void __launch_bounds__(256) gemm_mma(
    const char* __restrict__ Ahi, const char* __restrict__ Alo,
    const char* __restrict__ Bhi, const char* __restrict__ Blo,
    const float* __restrict__ bias, void* __restrict__ C,
    char* __restrict__ Chi, char* __restrict__ Clo,
    float* __restrict__ stats,
    int numKt, int aBatchTiles, int bBatchTiles, long long cBatchStride, int ldc)
{
    constexpr int NTILES = TERMS + 1;
    constexpr uint32_t STB = NTILES * TILE_BYTES;

    extern __shared__ __align__(128) char smem[];
    uint32_t smem_base = smem_to_u32(smem);
    const int tid = threadIdx.x;
    const int wid = tid >> 5;
    const int lane = tid & 31;
    const int wm = wid & 1;
    const int wn = wid >> 1;

    const long long aTileBase = (long long)blockIdx.z * aBatchTiles + (long long)blockIdx.y * numKt;
    const long long bTileBase = (long long)blockIdx.z * bBatchTiles + (long long)blockIdx.x * numKt;

    auto issue_loads = [&](int kt, int stage) {
        const char* srcs[4];
        srcs[0] = Ahi + (aTileBase + kt) * TILE_BYTES;
        srcs[1] = Bhi + (bTileBase + kt) * TILE_BYTES;
        if (TERMS >= 2) srcs[2] = Blo + (bTileBase + kt) * TILE_BYTES;
        if (TERMS == 3) srcs[3] = Alo + (aTileBase + kt) * TILE_BYTES;
        uint32_t sb = smem_base + stage * STB;
#pragma unroll
        for (int t = 0; t < NTILES; t++)
#pragma unroll
            for (int i = 0; i < 4; i++) {
                uint32_t o = t * TILE_BYTES + i * 4096 + tid * 16;
                cpa16(sb + o, srcs[t] + i * 4096 + tid * 16);
            }
        asm volatile("cp.async.commit_group;" ::: "memory");
    };

    const int aRowBase = wm * 64 + (lane & 15);
    const uint32_t aKadd = (lane >> 4) * 16;
    const int bRowBase = wn * 32 + ((lane >> 4) << 3) + (lane & 7);
    const uint32_t bKadd = ((lane >> 3) & 1) * 16;

    float acc[4][4][4];
#pragma unroll
    for (int mt = 0; mt < 4; mt++)
#pragma unroll
        for (int nt = 0; nt < 4; nt++)
#pragma unroll
            for (int f = 0; f < 4; f++) acc[mt][nt][f] = 0.f;

    issue_loads(0, 0);

    for (int c = 0; c < numKt; c++) {
        const int buf = c & 1;
        if (c + 1 < numKt) {
            issue_loads(c + 1, buf ^ 1);
            asm volatile("cp.async.wait_group 1;" ::: "memory");
        } else {
            asm volatile("cp.async.wait_group 0;" ::: "memory");
        }
        __syncthreads();

        const uint32_t sb = smem_base + buf * STB;
        const uint32_t aHiB = sb;
        const uint32_t bHiB = sb + TILE_BYTES;
        const uint32_t bLoB = sb + 2 * TILE_BYTES;
        const uint32_t aLoB = sb + 3 * TILE_BYTES;

#pragma unroll
        for (int ks = 0; ks < 4; ks++) {
            uint32_t ah[4][4], al[4][4];
#pragma unroll
            for (int mt = 0; mt < 4; mt++) {
                int row = aRowBase + mt * 16;
                uint32_t koff = (ks * 32 + aKadd) ^ ((row & 7) << 4);
                uint32_t off = (uint32_t)row * 128 + koff;
                ldm_x4(ah[mt], aHiB + off);
                if (TERMS == 3) ldm_x4(al[mt], aLoB + off);
            }
            uint32_t bh[2][4], bl[2][4];
#pragma unroll
            for (int np = 0; np < 2; np++) {
                int row = bRowBase + np * 16;
                uint32_t koff = (ks * 32 + bKadd) ^ ((row & 7) << 4);
                uint32_t off = (uint32_t)row * 128 + koff;
                ldm_x4(bh[np], bHiB + off);
                if (TERMS >= 2) ldm_x4(bl[np], bLoB + off);
            }
#pragma unroll
            for (int mt = 0; mt < 4; mt++)
#pragma unroll
                for (int nt = 0; nt < 4; nt++) {
                    const uint32_t* bhp = &bh[nt >> 1][(nt & 1) * 2];
                    mma_f16(acc[mt][nt], ah[mt], bhp);
                    if (TERMS >= 2) {
                        const uint32_t* blp = &bl[nt >> 1][(nt & 1) * 2];
                        mma_f16(acc[mt][nt], ah[mt], blp);
                    }
                    if (TERMS == 3) mma_f16(acc[mt][nt], al[mt], bhp);
                }
        }
        __syncthreads();
    }

    // Epilogue
    const int g = lane >> 2, tg = lane & 3;
    float ls = 0.f, lsq = 0.f;
    if (SPLIT) {
        const int tilesPerRow = ldc >> 6;
        const bool wlo = (Clo != nullptr);
#pragma unroll
        for (int mt = 0; mt < 4; mt++) {
            const int row0 = blockIdx.y * 128 + wm * 64 + mt * 16 + g;
#pragma unroll
            for (int nt = 0; nt < 4; nt++) {
                const int col = blockIdx.x * 128 + wn * 32 + nt * 8 + tg * 2;
                const int tile = (row0 >> 7) * tilesPerRow + (col >> 6);
#pragma unroll
                for (int half = 0; half < 2; half++) {
                    const int rowIn = (row0 & 127) + half * 8;
                    float v0 = acc[mt][nt][half * 2 + 0];
                    float v1 = acc[mt][nt][half * 2 + 1];
                    __half h0 = __float2half(v0);
                    __half h1 = __float2half(v1);
                    __half2 hp = {h0, h1};
                    uint32_t inoff = rowIn * 128 + (col & 63) * 2;
                    uint32_t sw = inoff ^ ((inoff >> 3) & 0x70);
                    *(uint32_t*)(Chi + (size_t)tile * TILE_BYTES + sw) =
                        *reinterpret_cast<uint32_t*>(&hp);
                    if (wlo) {
                        float l0 = v0 - __half2float(h0);
                        float l1 = v1 - __half2float(h1);
                        *(uint32_t*)(Clo + (size_t)tile * TILE_BYTES + sw) = packh(l0, l1);
                    }
                }
            }
        }
    } else if (SIG) {
        __half* Gbase = (__half*)C + (long long)blockIdx.z * cBatchStride;
#pragma unroll
        for (int mt = 0; mt < 4; mt++) {
            const int row0 = blockIdx.y * 128 + wm * 64 + mt * 16 + g;
#pragma unroll
            for (int nt = 0; nt < 4; nt++) {
                const int col = blockIdx.x * 128 + wn * 32 + nt * 8 + tg * 2;
#pragma unroll
                for (int half = 0; half < 2; half++) {
                    float v0 = 0.125f / (1.f + __expf(-acc[mt][nt][half * 2 + 0]));
                    float v1 = 0.125f / (1.f + __expf(-acc[mt][nt][half * 2 + 1]));
                    *(uint32_t*)(Gbase + (long long)(row0 + half * 8) * ldc + col) =
                        packh(v0, v1);
                }
            }
        }
    } else {
        float* Cbase = (float*)C + (long long)blockIdx.z * cBatchStride;
#pragma unroll
        for (int mt = 0; mt < 4; mt++) {
            const int row0 = blockIdx.y * 128 + wm * 64 + mt * 16 + g;
#pragma unroll
            for (int nt = 0; nt < 4; nt++) {
                const int col = blockIdx.x * 128 + wn * 32 + nt * 8 + tg * 2;
                float b0 = 0.f, b1 = 0.f;
                if (BIAS) { b0 = bias[col]; b1 = bias[col + 1]; }
#pragma unroll
                for (int half = 0; half < 2; half++) {
                    float v0 = acc[mt][nt][half * 2 + 0] + b0;
                    float v1 = acc[mt][nt][half * 2 + 1] + b1;
                    if (GNSTAT) {
                        ls += v0 + v1;
                        lsq += v0 * v0 + v1 * v1;
                    }
                    *(float2*)(Cbase + (long long)(row0 + half * 8) * ldc + col) =
                        make_float2(v0, v1);
                }
            }
        }
        if (GNSTAT) {
#pragma unroll
            for (int off = 16; off > 0; off >>= 1) {
                ls  += __shfl_xor_sync(0xffffffffu, ls, off);
                lsq += __shfl_xor_sync(0xffffffffu, lsq, off);
            }
            if (lane == 0) {
                const int b = blockIdx.y >> 4;
                const int grp = blockIdx.x * 2 + (wn >> 1);
                atomicAdd(&stats[(b * GROUPS + grp) * 2 + 0], ls);
                atomicAdd(&stats[(b * GROUPS + grp) * 2 + 1], lsq);
            }
        }
    }
}

// ===========================================================================
// GN apply: normalize P (fp32) using precomputed stats and write f16 hi
// SW128 split tiles (both P1, P2 hi-only: gate GEMM is 1-term).
// ===========================================================================
__global__ void __launch_bounds__(256) gn_apply_kernel(
    const float* __restrict__ g1, const float* __restrict__ b1,
    const float* __restrict__ g2, const float* __restrict__ b2,
    char* __restrict__ p1Hi, char* __restrict__ p2Hi)
{
    const int which = blockIdx.y;
    const float* P = which == 0 ? g_P1 : g_P2;
    const float* st = which == 0 ? g_gnstat1 : g_gnstat2;
    const float* gamma = which == 0 ? g1 : g2;
    const float* beta  = which == 0 ? b1 : b2;
    char* Hi = which == 0 ? p1Hi : p2Hi;

    const int idx = blockIdx.x * 256 + threadIdx.x;
    const int r = idx >> 6;
    const int c = (idx & 63) << 3;
    const int b = r >> 11;
    const int grp = c >> 6;
    const float CNT = (float)((CC / GROUPS) * NN);

    const float s = st[(b * GROUPS + grp) * 2 + 0];
    const float sq = st[(b * GROUPS + grp) * 2 + 1];
    const float mean = s / CNT;
    const float var = sq / CNT - mean * mean;
    const float rstd = rsqrtf(var + 1e-5f);

    float4 v0 = *(const float4*)(P + (size_t)r * CC + c);
    float4 v1 = *(const float4*)(P + (size_t)r * CC + c + 4);
    float vin[8] = {v0.x, v0.y, v0.z, v0.w, v1.x, v1.y, v1.z, v1.w};
    float4 gm0 = *(const float4*)(gamma + c);
    float4 gm1 = *(const float4*)(gamma + c + 4);
    float4 bt0 = *(const float4*)(beta + c);
    float4 bt1 = *(const float4*)(beta + c + 4);
    float gm[8] = {gm0.x, gm0.y, gm0.z, gm0.w, gm1.x, gm1.y, gm1.z, gm1.w};
    float bt[8] = {bt0.x, bt0.y, bt0.z, bt0.w, bt1.x, bt1.y, bt1.z, bt1.w};

    uint32_t hw[4];
#pragma unroll
    for (int i = 0; i < 4; i++) {
        float a0 = (vin[2 * i] - mean) * rstd * gm[2 * i] + bt[2 * i];
        float a1 = (vin[2 * i + 1] - mean) * rstd * gm[2 * i + 1] + bt[2 * i + 1];
        hw[i] = packh(a0, a1);
    }

    const int tile = (r >> 7) * 8 + grp;
    uint32_t inTile = (uint32_t)(r & 127) * 128 + (c & 63) * 2;
    uint32_t sw = inTile ^ ((inTile >> 3) & 0x70);
    size_t off = (size_t)tile * TILE_BYTES + sw;
    *(uint4*)(Hi + off) = make_uint4(hw[0], hw[1], hw[2], hw[3]);
}

// ===========================================================================
// Tensor-core flash attention with fp16 PE gate, register-prefetched.
// S = Qh*Kh (1-term), O += Ph*Vh (1-term). Grid (N/128, H, B); 8 warps.
// KV stage: Kh 8KB + Vh 8KB = 16KB.
// ===========================================================================
#define ATT_STAGE 16384
#define ATT_SMEM (16384 + 2 * ATT_STAGE)   // Q hi + 2 KV stages = 48KB

__global__ void __launch_bounds__(256) attn_mma()
{
    extern __shared__ __align__(128) char smem[];
    const uint32_t sb = smem_to_u32(smem);
    const uint32_t qh_base = sb;
    const uint32_t stage0 = sb + 16384;

    const int tid = threadIdx.x, wid = tid >> 5, lane = tid & 31;
    const int q0 = blockIdx.x * 128, h = blockIdx.y, b = blockIdx.z;
    const int g = lane >> 2, tg = lane & 3;

    const int rtQ = (b * NN + q0) >> 7;
    {
        const char* qsh = g_qkvs_hi + (size_t)(rtQ * 24 + h) * TILE_BYTES;
#pragma unroll
        for (int i = 0; i < 4; i++)
            cpa16(qh_base + i * 4096 + tid * 16, qsh + i * 4096 + tid * 16);
        asm volatile("cp.async.commit_group;" ::: "memory");
    }

    auto issue_kv = [&](int t, int stg) {
        const int kRow = t * 64;
        const int rt = (b * NN + kRow) >> 7;
        const int halfOff = (kRow & 64) ? 8192 : 0;
        const char* kh = g_qkvs_hi + (size_t)(rt * 24 + 8 + h) * TILE_BYTES + halfOff;
        const char* vh = g_qkvs_hi + (size_t)(rt * 24 + 16 + h) * TILE_BYTES + halfOff;
        uint32_t s = stage0 + stg * ATT_STAGE;
#pragma unroll
        for (int i = 0; i < 2; i++) {
            uint32_t o = i * 4096 + tid * 16;
            cpa16(s + o,        kh + o);
            cpa16(s + 8192 + o, vh + o);
        }
        asm volatile("cp.async.commit_group;" ::: "memory");
    };

    issue_kv(0, 0);
    asm volatile("cp.async.wait_group 1;" ::: "memory");  // Q arrived
    __syncthreads();

    // Q fragments (hi only, resident)
    uint32_t qfh[4][4];
    {
        const int row = wid * 16 + (lane & 15);
        const uint32_t roff = (uint32_t)row * 128;
#pragma unroll
        for (int ks = 0; ks < 4; ks++) {
            uint32_t colb = (lane >> 4) * 16 + ks * 32;
            uint32_t a = roff + (colb ^ ((row & 7) << 4));
            ldm_x4(qfh[ks], qh_base + a);
        }
    }

    float Oa[8][4];
#pragma unroll
    for (int nt = 0; nt < 8; nt++)
#pragma unroll
        for (int f = 0; f < 4; f++) Oa[nt][f] = 0.f;
    float mrow[2] = {-1e30f, -1e30f}, lrow[2] = {0.f, 0.f};

    const size_t peBase = (size_t)b * NN * NN;
    const int qRow0 = q0 + wid * 16 + g;
    const int bRow0 = ((lane >> 4) << 3) + (lane & 7);
    const uint32_t bKadd = ((lane >> 3) & 1) * 16;

    for (int t = 0; t < NN / 64; t++) {
        const int buf = t & 1;
        const int k0 = t * 64;

        // Prefetch fp16 PE gate words before the QK MMAs (latency overlap).
        uint32_t peReg[16];
#pragma unroll
        for (int nt = 0; nt < 8; nt++)
#pragma unroll
            for (int r = 0; r < 2; r++)
                peReg[nt * 2 + r] = *(const uint32_t*)&g_PEh[
                    peBase + (size_t)(qRow0 + r * 8) * NN + k0 + nt * 8 + tg * 2];

        if (t + 1 < NN / 64) {
            issue_kv(t + 1, buf ^ 1);
            asm volatile("cp.async.wait_group 1;" ::: "memory");
        } else {
            asm volatile("cp.async.wait_group 0;" ::: "memory");
        }
        __syncthreads();

        const uint32_t kb = stage0 + buf * ATT_STAGE;
        const uint32_t kh_b = kb;
        const uint32_t vh_b = kb + 8192;

        // S = Q K^T (fp16 1-term)
        float S[8][4];
#pragma unroll
        for (int nt = 0; nt < 8; nt++)
#pragma unroll
            for (int f = 0; f < 4; f++) S[nt][f] = 0.f;

#pragma unroll
        for (int ks = 0; ks < 4; ks++) {
#pragma unroll
            for (int np = 0; np < 4; np++) {
                const int row = bRow0 + np * 16;
                const uint32_t a = (uint32_t)row * 128 +
                                   ((ks * 32 + bKadd) ^ ((row & 7) << 4));
                uint32_t KH[4];
                ldm_x4(KH, kh_b + a);
#pragma unroll
                for (int hn = 0; hn < 2; hn++)
                    mma_f16(S[np * 2 + hn], qfh[ks], &KH[hn * 2]);
            }
        }

        // gate with prefetched fp16 PE (0.125 pre-folded)
#pragma unroll
        for (int nt = 0; nt < 8; nt++) {
#pragma unroll
            for (int r = 0; r < 2; r++) {
                const float2 pe = __half22float2(
                    *reinterpret_cast<const __half2*>(&peReg[nt * 2 + r]));
                S[nt][r * 2 + 0] *= pe.x;
                S[nt][r * 2 + 1] *= pe.y;
            }
        }

        // online softmax
        float corr[2];
#pragma unroll
        for (int r = 0; r < 2; r++) {
            float vm = -1e30f;
#pragma unroll
            for (int nt = 0; nt < 8; nt++)
                vm = fmaxf(vm, fmaxf(S[nt][r * 2], S[nt][r * 2 + 1]));
            vm = fmaxf(vm, __shfl_xor_sync(0xffffffffu, vm, 1));
            vm = fmaxf(vm, __shfl_xor_sync(0xffffffffu, vm, 2));
            const float mn = fmaxf(mrow[r], vm);
            corr[r] = __expf(mrow[r] - mn);
            mrow[r] = mn;
            float rsum = 0.f;
#pragma unroll
            for (int nt = 0; nt < 8; nt++) {
                float p0 = __expf(S[nt][r * 2] - mn);
                float p1 = __expf(S[nt][r * 2 + 1] - mn);
                S[nt][r * 2] = p0;
                S[nt][r * 2 + 1] = p1;
                rsum += p0 + p1;
            }
            rsum += __shfl_xor_sync(0xffffffffu, rsum, 1);
            rsum += __shfl_xor_sync(0xffffffffu, rsum, 2);
            lrow[r] = lrow[r] * corr[r] + rsum;
        }
#pragma unroll
        for (int nt = 0; nt < 8; nt++) {
            Oa[nt][0] *= corr[0]; Oa[nt][1] *= corr[0];
            Oa[nt][2] *= corr[1]; Oa[nt][3] *= corr[1];
        }

        // O += P V (fp16 1-term); P hi fragments from S accumulators
#pragma unroll
        for (int ks = 0; ks < 4; ks++) {
            uint32_t ah[4];
#pragma unroll
            for (int q = 0; q < 2; q++) {
                const float* sv = S[2 * ks + q];
                ah[q * 2 + 0] = packh(sv[0], sv[1]);
                ah[q * 2 + 1] = packh(sv[2], sv[3]);
            }
#pragma unroll
            for (int dp = 0; dp < 4; dp++) {
                const int row = ks * 16 + (lane & 15);
                const uint32_t a = (uint32_t)row * 128 +
                    ((dp * 32 + (lane >> 4) * 16) ^ ((row & 7) << 4));
                uint32_t VH[4];
                ldm_x4_t(VH, vh_b + a);
#pragma unroll
                for (int hn = 0; hn < 2; hn++)
                    mma_f16(Oa[dp * 2 + hn], ah, &VH[hn * 2]);
            }
        }
        __syncthreads();
    }

    // Epilogue: normalize and write hi tiles for proj GEMM (O is A operand)
    const float inv[2] = {1.f / lrow[0], 1.f / lrow[1]};
    char* osh = g_os_hi + (size_t)(rtQ * 8 + h) * TILE_BYTES;
#pragma unroll
    for (int nt = 0; nt < 8; nt++) {
#pragma unroll
        for (int r = 0; r < 2; r++) {
            const float v0 = Oa[nt][r * 2 + 0] * inv[r];
            const float v1 = Oa[nt][r * 2 + 1] * inv[r];
            const int rowIn = wid * 16 + g + r * 8;
            const uint32_t inoff = (uint32_t)rowIn * 128 + nt * 16 + tg * 4;
            const uint32_t sw = inoff ^ ((inoff >> 3) & 0x70);
            *(uint32_t*)(osh + sw) = packh(v0, v1);
        }
    }
}

// ===========================================================================

static void split_on(cudaStream_t st, const void* X, void* Hi, void* Lo,
                     int K, int rows, bool wlo)
{
    int total8 = rows * K / 8;
    if (wlo)
        split_f16_kernel<true><<<(total8 + 255) / 256, 256, 0, st>>>(
            (const float*)X, (char*)Hi, (char*)Lo, K, total8);
    else
        split_f16_kernel<false><<<(total8 + 255) / 256, 256, 0, st>>>(
            (const float*)X, (char*)Hi, nullptr, K, total8);
}

#define GEMM_SMEM1 (2 * 2 * TILE_BYTES)   // 64KB
#define GEMM_SMEM2 (2 * 3 * TILE_BYTES)   // 96KB

extern "C" void kernel_launch(void* const* d_in, const int* in_sizes, int n_in,
                              void* d_out, int out_size)
{
    const float* x       = (const float*)d_in[0];
    const float* pe      = (const float*)d_in[1];
    const float* qkv_w   = (const float*)d_in[2];
    const float* proj_w  = (const float*)d_in[3];
    const float* proj_b  = (const float*)d_in[4];
    const float* conv1_w = (const float*)d_in[5];
    const float* conv1_b = (const float*)d_in[6];
    const float* gn1_g   = (const float*)d_in[7];
    const float* gn1_b   = (const float*)d_in[8];
    const float* conv2_w = (const float*)d_in[9];
    const float* conv2_b = (const float*)d_in[10];
    const float* gn2_g   = (const float*)d_in[11];
    const float* gn2_b   = (const float*)d_in[12];
    float* out = (float*)d_out;

    float *p1, *p2, *st1, *st2;
    void* pehRaw;
    cudaGetSymbolAddress((void**)&p1, g_P1);
    cudaGetSymbolAddress((void**)&p2, g_P2);
    cudaGetSymbolAddress(&pehRaw, g_PEh);
    cudaGetSymbolAddress((void**)&st1, g_gnstat1);
    cudaGetSymbolAddress((void**)&st2, g_gnstat2);

    char *xsh, *pesh, *p1h, *p2h, *osh;
    char *wqh, *w1h, *w1l, *w2h, *w2l, *wph, *qsh;
    cudaGetSymbolAddress((void**)&xsh, g_xs_hi);
    cudaGetSymbolAddress((void**)&pesh, g_pes_hi);
    cudaGetSymbolAddress((void**)&p1h, g_p1s_hi);
    cudaGetSymbolAddress((void**)&p2h, g_p2s_hi);
    cudaGetSymbolAddress((void**)&osh, g_os_hi);
    cudaGetSymbolAddress((void**)&wqh, g_wqkv_hi);
    cudaGetSymbolAddress((void**)&w1h, g_wc1_hi);  cudaGetSymbolAddress((void**)&w1l, g_wc1_lo);
    cudaGetSymbolAddress((void**)&w2h, g_wc2_hi);  cudaGetSymbolAddress((void**)&w2l, g_wc2_lo);
    cudaGetSymbolAddress((void**)&wph, g_wpj_hi);
    cudaGetSymbolAddress((void**)&qsh, g_qkvs_hi);

    static bool initDone = false;
    static cudaStream_t s2;
    static cudaEvent_t eFork, eJoin;
    if (!initDone) {
        cudaFuncSetAttribute(gemm_mma<2, false, true, false, true>,   cudaFuncAttributeMaxDynamicSharedMemorySize, GEMM_SMEM2);
        cudaFuncSetAttribute(gemm_mma<1, true, false, false, false>,  cudaFuncAttributeMaxDynamicSharedMemorySize, GEMM_SMEM1);
        cudaFuncSetAttribute(gemm_mma<1, false, false, true, false>,  cudaFuncAttributeMaxDynamicSharedMemorySize, GEMM_SMEM1);
        cudaFuncSetAttribute(gemm_mma<1, false, true, false, false>,  cudaFuncAttributeMaxDynamicSharedMemorySize, GEMM_SMEM1);
        cudaFuncSetAttribute(attn_mma, cudaFuncAttributeMaxDynamicSharedMemorySize, ATT_SMEM);
        cudaStreamCreateWithFlags(&s2, cudaStreamNonBlocking);
        cudaEventCreateWithFlags(&eFork, cudaEventDisableTiming);
        cudaEventCreateWithFlags(&eJoin, cudaEventDisableTiming);
        initDone = true;
    }

    const int M = BB * NN;       // 8192
    const int NKT = CC / 64;     // 8

    // ---- Fork: QKV branch + proj_w split on s2 (depend only on inputs) ----
    cudaEventRecord(eFork, 0);
    cudaStreamWaitEvent(s2, eFork, 0);
    split_on(s2, x, xsh, nullptr, CC, M, false);           // A of QKV
    split_on(s2, qkv_w, wqh, nullptr, CC, 3 * CC, false);  // B of QKV
    split_on(s2, proj_w, wph, nullptr, CC, CC, false);     // B of proj (1-term)
    gemm_mma<1, false, false, true, false><<<dim3(3 * CC / 128, M / 128, 1), 256, GEMM_SMEM1, s2>>>(
        xsh, nullptr, wqh, nullptr, nullptr, nullptr, qsh, nullptr, nullptr, NKT, 0, 0, 0, 3 * CC);
    cudaEventRecord(eJoin, s2);

    // ---- Main spine: conv -> GN -> gate ----
    gn_zero_kernel<<<1, 128>>>();
    split_on(0, pe, pesh, nullptr, CC, M, false);    // A of conv (2-term: hi only)
    split_on(0, conv1_w, w1h, w1l, CC, CC, true);    // B of conv (hi+lo)
    split_on(0, conv2_w, w2h, w2l, CC, CC, true);

    gemm_mma<2, false, true, false, true><<<dim3(CC / 128, M / 128, 1), 256, GEMM_SMEM2>>>(
        pesh, nullptr, w1h, w1l, conv1_b, p1, nullptr, nullptr, st1, NKT, 0, 0, 0, CC);
    gemm_mma<2, false, true, false, true><<<dim3(CC / 128, M / 128, 1), 256, GEMM_SMEM2>>>(
        pesh, nullptr, w2h, w2l, conv2_b, p2, nullptr, nullptr, st2, NKT, 0, 0, 0, CC);

    gn_apply_kernel<<<dim3(2048, 2), 256>>>(
        gn1_g, gn1_b, gn2_g, gn2_b, p1h, p2h);

    gemm_mma<1, true, false, false, false><<<dim3(NN / 128, NN / 128, BB), 256, GEMM_SMEM1>>>(
        p1h, nullptr, p2h, nullptr, nullptr, pehRaw, nullptr, nullptr, nullptr, NKT,
        (NN / 128) * NKT, (NN / 128) * NKT, (long long)NN * NN, NN);

    // ---- Join: attention needs QKV tiles, gate ----
    cudaStreamWaitEvent(0, eJoin, 0);
    attn_mma<<<dim3(NN / 128, HH, BB), 256, ATT_SMEM>>>();

    // ---- Output projection (fp16 1-term) ----
    gemm_mma<1, false, true, false, false><<<dim3(CC / 128, M / 128, 1), 256, GEMM_SMEM1>>>(
        osh, nullptr, wph, nullptr, proj_b, out, nullptr, nullptr, nullptr, NKT, 0, 0, 0, CC);
}